// round 13
// baseline (speedup 1.0000x reference)
#include <cuda_runtime.h>
#include <cuda_fp16.h>
#include <cstdint>
#include <cstddef>

// ---------------- problem constants ----------------
#define SP    25088          // 8*56*56
#define T_TOK 50176          // 2*SP
#define NTOK  98
#define SCALE_Q 0.125f
#define PAD_SP 33640         // 10*58*58
#define PDH    3364          // 58*58
#define W2SZ  (27*128*128)

// ---------------- scratch ----------------
__device__ __half g_xh  [(size_t)T_TOK*256];
__device__ __half g_qkvh[(size_t)T_TOK*768];
__device__ __half g_atnh[(size_t)T_TOK*256];
__device__ float  g_xw  [(size_t)T_TOK*256];
__device__ float  g_s   [(size_t)T_TOK*256];
__device__ __half g_Xa  [(size_t)2*PAD_SP*128];   // zero-init padding stays zero
__device__ __half g_Xb  [(size_t)2*PAD_SP*128];
__device__ __half g_w2h [(size_t)4*W2SZ];         // 4 conv weights [tap][co][ci]
__device__ __half g_wqkvh[768*256];
__device__ __half g_gqkvh[768*256];
__device__ __half g_wprjh[256*256];
__device__ __half g_gprjh[256*256];
__device__ __half g_bmat[(size_t)2*4*128*112];    // bias matrices [attn][head][r][m], fp16

// ---------------- PTX helpers (sm_80-baseline only) ----------------
__device__ __forceinline__ uint32_t smem_u32(const void* p) {
    uint32_t a;
    asm("{ .reg .u64 t; cvta.to.shared.u64 t, %1; cvt.u32.u64 %0, t; }" : "=r"(a) : "l"(p));
    return a;
}
__device__ __forceinline__ void cp16(uint32_t s, const void* g) {
    asm volatile("cp.async.cg.shared.global [%0], [%1], 16;" :: "r"(s), "l"(g));
}
#define CP_COMMIT() asm volatile("cp.async.commit_group;" ::: "memory")
#define CP_WAIT1()  asm volatile("cp.async.wait_group 1;"  ::: "memory")

__device__ __forceinline__ void ldsm4(uint32_t* r, uint32_t a) {
    asm volatile("ldmatrix.sync.aligned.m8n8.x4.shared.b16 {%0,%1,%2,%3}, [%4];"
        : "=r"(r[0]), "=r"(r[1]), "=r"(r[2]), "=r"(r[3]) : "r"(a));
}
__device__ __forceinline__ void ldsm4t(uint32_t* r, uint32_t a) {
    asm volatile("ldmatrix.sync.aligned.m8n8.x4.trans.shared.b16 {%0,%1,%2,%3}, [%4];"
        : "=r"(r[0]), "=r"(r[1]), "=r"(r[2]), "=r"(r[3]) : "r"(a));
}
#define MMA_F16(c, a, b0, b1) \
    asm volatile("mma.sync.aligned.m16n8k16.row.col.f32.f16.f16.f32 " \
        "{%0,%1,%2,%3}, {%4,%5,%6,%7}, {%8,%9}, {%0,%1,%2,%3};" \
        : "+f"((c)[0]), "+f"((c)[1]), "+f"((c)[2]), "+f"((c)[3]) \
        : "r"((a)[0]), "r"((a)[1]), "r"((a)[2]), "r"((a)[3]), "r"(b0), "r"(b1))

// ---------------- all weight/bias prep in ONE kernel ----------------
__global__ __launch_bounds__(256) void prep_kernel(
    const float* __restrict__ wqkv, const float* __restrict__ gqkv,
    const float* __restrict__ wprj, const float* __restrict__ gprj,
    const float* __restrict__ c1w, const float* __restrict__ c2w,
    const float* __restrict__ c3w, const float* __restrict__ c4w,
    const float* __restrict__ wbias, const float* __restrict__ gbias,
    __half* __restrict__ wqkvh, __half* __restrict__ gqkvh,
    __half* __restrict__ wprjh, __half* __restrict__ gprjh,
    __half* __restrict__ w2h, __half* __restrict__ bmat)
{
    int bx = blockIdx.x, tid = threadIdx.x;
    if (bx < 1536) {                       // qkv weights f2h: 2 x 768 blocks
        int j = (bx >= 768) ? (bx - 768) : bx;
        const float* s = (bx < 768) ? wqkv : gqkv;
        __half* d = (bx < 768) ? wqkvh : gqkvh;
        int i = j*256 + tid;
        d[i] = __float2half_rn(s[i]);
    } else if (bx < 2048) {                // proj weights f2h: 2 x 256 blocks
        const float* s = (bx < 1792) ? wprj : gprj;
        __half* d = (bx < 1792) ? wprjh : gprjh;
        int j = bx - 1536; if (j >= 256) j -= 256;
        int i = j*256 + tid;
        d[i] = __float2half_rn(s[i]);
    } else if (bx < 8960) {                // conv weight transform: 4 x 1728 blocks
        int seg = (bx - 2048) / 1728;
        const float* w = (seg == 0) ? c1w : (seg == 1) ? c2w : (seg == 2) ? c3w : c4w;
        __half* o = w2h + (size_t)seg * W2SZ;
        int i = ((bx - 2048) % 1728)*256 + tid;
        int ci = i & 127; int r = i >> 7; int co = r & 127; int tap = r >> 7;
        o[i] = __float2half_rn(w[(co*128 + ci)*27 + tap]);
    } else {                               // bias matrices: 2 x 224 blocks
        int seg = (bx - 8960) / 224;
        const float* bt = seg ? gbias : wbias;
        __half* bm = bmat + (size_t)seg * 4*128*112;
        int i = ((bx - 8960) % 224)*256 + tid;
        int m = i % 112; int r = (i/112) & 127; int head = i / (112*128);
        float v = 0.f;
        if (r < 98) {
            if (m >= 98) v = -30000.f;     // mask (fits fp16; exp -> 0)
            else {
                int pd_r = r/49; int rr = r - pd_r*49; int ph_r = rr/7, pw_r = rr - ph_r*7;
                int pd_m = m/49; int mm = m - pd_m*49; int ph_m = mm/7, pw_m = mm - ph_m*7;
                int rpi = ((pd_r - pd_m + 1)*13 + (ph_r - ph_m + 6))*13 + (pw_r - pw_m + 6);
                v = bt[rpi*4 + head];
            }
        }
        bm[i] = __float2half_rn(v);
    }
}

// ---------------- LN kernels (output half) ----------------
__global__ __launch_bounds__(256) void ln_in_kernel(
    const float* __restrict__ in, const float* __restrict__ w,
    const float* __restrict__ b, __half* __restrict__ out)
{
    __shared__ float s[28][257];
    int bx = blockIdx.x;
    int wt = bx & 1; int tmp = bx >> 1;
    int h = tmp % 56; tmp /= 56;
    int d = tmp & 7; int bb = tmp >> 3;
    int w0 = wt * 28;
    size_t sp = ((size_t)d*56 + h)*56 + w0;
    const float* ib = in + (size_t)bb*256*SP + sp;
    for (int i = threadIdx.x; i < 28*256; i += 256) {
        int c = i / 28, ww_ = i - c*28;
        s[ww_][c] = ib[(size_t)c*SP + ww_];
    }
    __syncthreads();
    int warp = threadIdx.x >> 5, lane = threadIdx.x & 31;
    for (int tk = warp; tk < 28; tk += 8) {
        float s1 = 0.f, s2 = 0.f;
        #pragma unroll
        for (int j = 0; j < 8; j++) { float v = s[tk][lane + (j<<5)]; s1 += v; s2 += v*v; }
        #pragma unroll
        for (int o = 16; o; o >>= 1) {
            s1 += __shfl_xor_sync(0xffffffffu, s1, o);
            s2 += __shfl_xor_sync(0xffffffffu, s2, o);
        }
        float m = s1 * (1.f/256.f);
        float var = s2 * (1.f/256.f) - m*m;
        float iv = rsqrtf(var + 1e-5f);
        size_t t = (size_t)bb*SP + sp + tk;
        __half* orow = out + t*256;
        #pragma unroll
        for (int j = 0; j < 8; j++) {
            int c = lane + (j<<5);
            orow[c] = __float2half_rn((s[tk][c] - m) * iv * w[c] + b[c]);
        }
    }
}

__global__ __launch_bounds__(256) void ln_row_kernel(
    const float* __restrict__ in, const float* __restrict__ w,
    const float* __restrict__ b, __half* __restrict__ out)
{
    int t = blockIdx.x*8 + (threadIdx.x >> 5);
    int lane = threadIdx.x & 31;
    const float* row = in + (size_t)t*256;
    float v[8]; float s1 = 0.f, s2 = 0.f;
    #pragma unroll
    for (int j = 0; j < 8; j++) { v[j] = row[lane + (j<<5)]; s1 += v[j]; s2 += v[j]*v[j]; }
    #pragma unroll
    for (int o = 16; o; o >>= 1) {
        s1 += __shfl_xor_sync(0xffffffffu, s1, o);
        s2 += __shfl_xor_sync(0xffffffffu, s2, o);
    }
    float m = s1 * (1.f/256.f);
    float var = s2 * (1.f/256.f) - m*m;
    float iv = rsqrtf(var + 1e-5f);
    __half* orow = out + (size_t)t*256;
    #pragma unroll
    for (int j = 0; j < 8; j++) {
        int c = lane + (j<<5);
        orow[c] = __float2half_rn((v[j] - m) * iv * w[c] + b[c]);
    }
}

// ---------------- shared warp-MMA stage: 128x128 tile, BK=64 ----------------
struct FragCtx {
    uint32_t aoff;
    uint32_t boff;
    uint32_t axor[4];
    uint32_t bxor[4];
};
__device__ __forceinline__ FragCtx make_frag_ctx(int lane, int wm, int wn) {
    FragCtx f;
    int l7 = lane & 7;
    f.aoff = (uint32_t)((wm*32 + ((lane>>3)&1)*8 + l7) * 128);
    f.boff = (uint32_t)((wn*64 + ((lane>>4)&1)*8 + l7) * 128);
    #pragma unroll
    for (int kk = 0; kk < 4; kk++) {
        f.axor[kk] = (uint32_t)(((2*kk + (lane>>4)) ^ l7) << 4);
        f.bxor[kk] = (uint32_t)(((2*kk + ((lane>>3)&1)) ^ l7) << 4);
    }
    return f;
}
__device__ __forceinline__ void mma_stage(uint32_t Ab, uint32_t Bb,
                                          const FragCtx& f, float c[2][8][4])
{
    #pragma unroll
    for (int kk = 0; kk < 4; kk++) {
        uint32_t a0[4], a1[4];
        ldsm4(a0, Ab + f.aoff + f.axor[kk]);
        ldsm4(a1, Ab + f.aoff + 2048u + f.axor[kk]);
        #pragma unroll
        for (int g = 0; g < 4; g++) {
            uint32_t bb[4];
            ldsm4(bb, Bb + f.boff + (uint32_t)g*2048u + f.bxor[kk]);
            MMA_F16(c[0][2*g],   a0, bb[0], bb[1]);
            MMA_F16(c[1][2*g],   a1, bb[0], bb[1]);
            MMA_F16(c[0][2*g+1], a0, bb[2], bb[3]);
            MMA_F16(c[1][2*g+1], a1, bb[2], bb[3]);
        }
    }
}

// ---------------- shared mainloop body for 128x128 @ K=256 GEMM ----------------
__device__ __forceinline__ void hgemm_mainloop(
    const __half* asrc, const __half* bsrc, uint32_t sb, uint32_t dst,
    int q0, int mrow, const FragCtx& f, float c[2][8][4])
{
    auto load_st = [&](int s) {
        uint32_t base = (uint32_t)(s % 3) * 32768u;
        #pragma unroll
        for (int q = q0; q < q0 + 4; q++) {
            uint32_t sw = (uint32_t)((q ^ (mrow & 7)) << 4);
            cp16(dst + base + sw, asrc + s*64 + q*8);
            cp16(dst + base + 16384u + sw, bsrc + s*64 + q*8);
        }
    };
    load_st(0); CP_COMMIT();
    load_st(1); CP_COMMIT();
    #pragma unroll
    for (int k = 0; k < 4; k++) {
        CP_WAIT1();
        __syncthreads();
        if (k + 2 < 4) load_st(k + 2);
        CP_COMMIT();
        uint32_t Ab = sb + (uint32_t)(k % 3)*32768u;
        mma_stage(Ab, Ab + 16384u, f, c);
    }
    __syncthreads();
}

// ---------------- fp16 GEMM (plain): OUTHALF 1 -> C half, 0 -> C float (+res) --------
template<int OUTHALF>
__global__ __launch_bounds__(256, 2) void hgemm_kernel(
    const __half* __restrict__ A, const __half* __restrict__ B,
    const float* __restrict__ bias, const float* __restrict__ res,
    void* __restrict__ Cout, int N)
{
    extern __shared__ __align__(16) char dsm[];
    __shared__ float sbias[128];
    const int tid = threadIdx.x, lane = tid & 31, wid = tid >> 5;
    const int wm = wid & 3, wn = wid >> 2;
    const int bx = blockIdx.x, by = blockIdx.y;

    if (tid < 128) sbias[tid] = bias ? bias[bx*128 + tid] : 0.f;

    const int mrow = tid >> 1;
    const int q0 = (tid & 1) * 4;
    const uint32_t sb = smem_u32(dsm);
    FragCtx f = make_frag_ctx(lane, wm, wn);
    float c[2][8][4];
    #pragma unroll
    for (int t = 0; t < 2; t++)
        #pragma unroll
        for (int j = 0; j < 8; j++)
            #pragma unroll
            for (int q = 0; q < 4; q++) c[t][j][q] = 0.f;

    hgemm_mainloop(A + ((size_t)(by*128 + mrow))*256,
                   B + ((size_t)(bx*128 + mrow))*256,
                   sb, sb + (uint32_t)mrow*128u, q0, mrow, f, c);

    float* Cb = (float*)dsm;   // 128 x 132
    const int r0 = lane >> 2, c0 = lane & 3;
    #pragma unroll
    for (int t = 0; t < 2; t++) {
        int row = wm*32 + t*16 + r0;
        #pragma unroll
        for (int t2 = 0; t2 < 8; t2++) {
            int col = wn*64 + t2*8 + (c0 << 1);
            Cb[row*132 + col]       = c[t][t2][0] + sbias[col];
            Cb[row*132 + col + 1]   = c[t][t2][1] + sbias[col+1];
            Cb[(row+8)*132 + col]   = c[t][t2][2] + sbias[col];
            Cb[(row+8)*132 + col+1] = c[t][t2][3] + sbias[col+1];
        }
    }
    __syncthreads();

    const int m = tid >> 1, ch = (tid & 1) << 6;
    size_t goff = ((size_t)(by*128 + m))*N + bx*128 + ch;
    if (OUTHALF) {
        __half* Ch = (__half*)Cout;
        #pragma unroll
        for (int j8 = 0; j8 < 8; j8++) {
            const float* p = &Cb[m*132 + ch + j8*8];
            __half2 h0 = __floats2half2_rn(p[0], p[1]);
            __half2 h1 = __floats2half2_rn(p[2], p[3]);
            __half2 h2 = __floats2half2_rn(p[4], p[5]);
            __half2 h3 = __floats2half2_rn(p[6], p[7]);
            uint4 u;
            u.x = *(uint32_t*)&h0; u.y = *(uint32_t*)&h1;
            u.z = *(uint32_t*)&h2; u.w = *(uint32_t*)&h3;
            *(uint4*)(Ch + goff + j8*8) = u;
        }
    } else {
        float* Cf = (float*)Cout;
        #pragma unroll
        for (int j4 = 0; j4 < 16; j4++) {
            float4 v = *(const float4*)&Cb[m*132 + ch + j4*4];
            if (res) {
                float4 r = *(const float4*)(res + goff + j4*4);
                v.x += r.x; v.y += r.y; v.z += r.z; v.w += r.w;
            }
            *(float4*)(Cf + goff + j4*4) = v;
        }
    }
}

// ---------------- fused grid-proj: y = A@B^T + bias + xw; s = input + y; Xa = half(s2)
__global__ __launch_bounds__(256, 2) void hgemm_fuse_kernel(
    const __half* __restrict__ A, const __half* __restrict__ B,
    const float* __restrict__ bias, const float* __restrict__ xw,
    const float* __restrict__ input, float* __restrict__ s,
    __half* __restrict__ Xa)
{
    extern __shared__ __align__(16) char dsm[];
    __shared__ float sbias[128];
    const int tid = threadIdx.x, lane = tid & 31, wid = tid >> 5;
    const int wm = wid & 3, wn = wid >> 2;
    const int bx = blockIdx.x, by = blockIdx.y;

    if (tid < 128) sbias[tid] = bias[bx*128 + tid];

    const int mrow = tid >> 1;
    const int q0 = (tid & 1) * 4;
    const uint32_t sb = smem_u32(dsm);
    FragCtx f = make_frag_ctx(lane, wm, wn);
    float c[2][8][4];
    #pragma unroll
    for (int t = 0; t < 2; t++)
        #pragma unroll
        for (int j = 0; j < 8; j++)
            #pragma unroll
            for (int q = 0; q < 4; q++) c[t][j][q] = 0.f;

    hgemm_mainloop(A + ((size_t)(by*128 + mrow))*256,
                   B + ((size_t)(bx*128 + mrow))*256,
                   sb, sb + (uint32_t)mrow*128u, q0, mrow, f, c);

    float* Cb = (float*)dsm;   // 128 x 132, rows = tokens, cols = local chan
    const int r0 = lane >> 2, c0 = lane & 3;
    #pragma unroll
    for (int t = 0; t < 2; t++) {
        int row = wm*32 + t*16 + r0;
        #pragma unroll
        for (int t2 = 0; t2 < 8; t2++) {
            int col = wn*64 + t2*8 + (c0 << 1);
            Cb[row*132 + col]       = c[t][t2][0] + sbias[col];
            Cb[row*132 + col + 1]   = c[t][t2][1] + sbias[col+1];
            Cb[(row+8)*132 + col]   = c[t][t2][2] + sbias[col];
            Cb[(row+8)*132 + col+1] = c[t][t2][3] + sbias[col+1];
        }
    }
    __syncthreads();

    // phase A (token-major): y = Cb + xw
    const int m = tid >> 1, ch = (tid & 1) << 6;
    {
        size_t goff = ((size_t)(by*128 + m))*256 + bx*128 + ch;
        #pragma unroll
        for (int j4 = 0; j4 < 16; j4++) {
            float4 r = *(const float4*)(xw + goff + j4*4);
            float* p = &Cb[m*132 + ch + j4*4];
            p[0] += r.x; p[1] += r.y; p[2] += r.z; p[3] += r.w;
        }
    }
    __syncthreads();

    // phase B (chan-major, coalesced NCDHW): s = input + y; Cb <- s
    {
        const int co = tid >> 1, mh = (tid & 1) << 6;
        const int tok0 = by*128;
        const int b = tok0 / SP, sp0 = tok0 % SP;
        size_t gbase = (size_t)b*256*SP + (size_t)(bx*128 + co)*SP + sp0 + mh;
        #pragma unroll
        for (int j4 = 0; j4 < 16; j4++) {
            float4 iv = *(const float4*)(input + gbase + j4*4);
            float* p0 = &Cb[(mh + j4*4 + 0)*132 + co];
            float* p1 = &Cb[(mh + j4*4 + 1)*132 + co];
            float* p2 = &Cb[(mh + j4*4 + 2)*132 + co];
            float* p3 = &Cb[(mh + j4*4 + 3)*132 + co];
            float v0 = iv.x + *p0, v1 = iv.y + *p1, v2 = iv.z + *p2, v3 = iv.w + *p3;
            *p0 = v0; *p1 = v1; *p2 = v2; *p3 = v3;
            float4 o = make_float4(v0, v1, v2, v3);
            *(float4*)(s + gbase + j4*4) = o;
        }
    }
    __syncthreads();

    // phase C (token-major): Xa = half(s2) for channels 128..255 (bx==1)
    if (bx == 1) {
        const int tok = by*128 + m;
        const int b = tok / SP;
        int sp = tok % SP;
        int d = sp / 3136; int r = sp - d*3136; int h = r / 56, w = r - h*56;
        size_t po = (size_t)(d+1)*PDH + (size_t)(h+1)*58 + (w+1);
        __half* xp = Xa + ((size_t)b*PAD_SP + po)*128 + ch;
        #pragma unroll
        for (int j8 = 0; j8 < 8; j8++) {
            const float* p = &Cb[m*132 + ch + j8*8];
            __half2 h0 = __floats2half2_rn(p[0], p[1]);
            __half2 h1 = __floats2half2_rn(p[2], p[3]);
            __half2 h2 = __floats2half2_rn(p[4], p[5]);
            __half2 h3 = __floats2half2_rn(p[6], p[7]);
            uint4 u;
            u.x = *(uint32_t*)&h0; u.y = *(uint32_t*)&h1;
            u.z = *(uint32_t*)&h2; u.w = *(uint32_t*)&h3;
            *(uint4*)(xp + j8*8) = u;
        }
    }
}

// ---------------- tensor-core attention (M pad 112, 7 compute warps, fp16 bias) ------
__global__ __launch_bounds__(256, 3) void attn_mma_kernel(
    const __half* __restrict__ qkv, const __half* __restrict__ bmat,
    __half* __restrict__ out, int grid_mode)
{
    __shared__ __align__(16) __half Qs[112*64];
    __shared__ __align__(16) __half Ks[112*64];
    __shared__ __align__(16) __half Vs[112*64];
    __shared__ int ts[NTOK];

    const int tid = threadIdx.x, lane = tid & 31, warp = tid >> 5;
    const int wi = blockIdx.x, head = blockIdx.y;
    const int b = wi >> 8, wd = (wi>>6)&3, wh = (wi>>3)&7, ww = wi & 7;
    const int hoff = head << 6;

    if (tid < NTOK) {
        int pd = tid / 49; int r7 = tid - pd*49; int ph = r7 / 7, pw = r7 - ph*7;
        int d, h, w;
        if (grid_mode) { d = pd*4 + wd; h = ph*8 + wh; w = pw*8 + ww; }
        else           { d = wd*2 + pd; h = wh*7 + ph; w = ww*7 + pw; }
        ts[tid] = ((b*8 + d)*56 + h)*56 + w;
    }
    __syncthreads();

    {
        const int row = tid >> 1;
        const int cb = (tid & 1) * 4;
        const __half2 sc2 = __floats2half2_rn(SCALE_Q, SCALE_Q);
        const uint4 z4 = make_uint4(0,0,0,0);
        if (row < 112) {
            size_t base = (row < 98) ? ((size_t)ts[row]*768 + hoff) : 0;
            #pragma unroll
            for (int cc = 0; cc < 4; cc++) {
                int c = cb + cc;
                int sw8 = (c ^ (row & 7)) * 8;
                uint4 vq = z4, vk = z4, vv = z4;
                if (row < 98) {
                    vq = *(const uint4*)(qkv + base + c*8);
                    vk = *(const uint4*)(qkv + base + 256 + c*8);
                    vv = *(const uint4*)(qkv + base + 512 + c*8);
                    __half2* hq = (__half2*)&vq;
                    hq[0] = __hmul2(hq[0], sc2); hq[1] = __hmul2(hq[1], sc2);
                    hq[2] = __hmul2(hq[2], sc2); hq[3] = __hmul2(hq[3], sc2);
                }
                *(uint4*)(Qs + row*64 + sw8) = vq;
                *(uint4*)(Ks + row*64 + sw8) = vk;
                *(uint4*)(Vs + row*64 + sw8) = vv;
            }
        }
    }
    __syncthreads();

    if (warp < 7) {
        const uint32_t qb = smem_u32(Qs), kb = smem_u32(Ks), vb = smem_u32(Vs);
        const int l7 = lane & 7;

        float c[14][4];
        #pragma unroll
        for (int t = 0; t < 14; t++)
            #pragma unroll
            for (int q = 0; q < 4; q++) c[t][q] = 0.f;

        const uint32_t a_base = qb + (uint32_t)((warp*16 + ((lane>>3)&1)*8 + l7) * 128);
        const uint32_t b_rowo = (uint32_t)((((lane>>4)&1)*8 + l7) * 128);
        #pragma unroll
        for (int kk = 0; kk < 4; kk++) {
            uint32_t a[4];
            ldsm4(a, a_base + (uint32_t)(((2*kk + (lane>>4)) ^ l7) << 4));
            uint32_t bx_ = (uint32_t)(((2*kk + ((lane>>3)&1)) ^ l7) << 4);
            #pragma unroll
            for (int g = 0; g < 7; g++) {
                uint32_t bb[4];
                ldsm4(bb, kb + (uint32_t)(g*2048) + b_rowo + bx_);
                MMA_F16(c[2*g],   a, bb[0], bb[1]);
                MMA_F16(c[2*g+1], a, bb[2], bb[3]);
            }
        }

        const int r_lo = warp*16 + (lane >> 2);
        const int r_hi = r_lo + 8;
        const int mcol = (lane & 3) * 2;
        const __half* bm_lo = bmat + ((size_t)head*128 + r_lo)*112 + mcol;
        const __half* bm_hi = bm_lo + 8*112;
        float mx_lo = -1e30f, mx_hi = -1e30f;
        #pragma unroll
        for (int t = 0; t < 14; t++) {
            float2 blo = __half22float2(*(const __half2*)(bm_lo + t*8));
            float2 bhi = __half22float2(*(const __half2*)(bm_hi + t*8));
            c[t][0] += blo.x;  c[t][1] += blo.y;
            c[t][2] += bhi.x;  c[t][3] += bhi.y;
            mx_lo = fmaxf(mx_lo, fmaxf(c[t][0], c[t][1]));
            mx_hi = fmaxf(mx_hi, fmaxf(c[t][2], c[t][3]));
        }
        #pragma unroll
        for (int o = 1; o <= 2; o <<= 1) {
            mx_lo = fmaxf(mx_lo, __shfl_xor_sync(0xffffffffu, mx_lo, o));
            mx_hi = fmaxf(mx_hi, __shfl_xor_sync(0xffffffffu, mx_hi, o));
        }
        float sum_lo = 0.f, sum_hi = 0.f;
        #pragma unroll
        for (int t = 0; t < 14; t++) {
            c[t][0] = __expf(c[t][0] - mx_lo); sum_lo += c[t][0];
            c[t][1] = __expf(c[t][1] - mx_lo); sum_lo += c[t][1];
            c[t][2] = __expf(c[t][2] - mx_hi); sum_hi += c[t][2];
            c[t][3] = __expf(c[t][3] - mx_hi); sum_hi += c[t][3];
        }
        #pragma unroll
        for (int o = 1; o <= 2; o <<= 1) {
            sum_lo += __shfl_xor_sync(0xffffffffu, sum_lo, o);
            sum_hi += __shfl_xor_sync(0xffffffffu, sum_hi, o);
        }
        const float inv_lo = 1.f / sum_lo, inv_hi = 1.f / sum_hi;

        uint32_t ap[7][4];
        #pragma unroll
        for (int j = 0; j < 7; j++) {
            __half2 h;
            h = __floats2half2_rn(c[2*j][0]*inv_lo,   c[2*j][1]*inv_lo);   ap[j][0] = *(uint32_t*)&h;
            h = __floats2half2_rn(c[2*j][2]*inv_hi,   c[2*j][3]*inv_hi);   ap[j][1] = *(uint32_t*)&h;
            h = __floats2half2_rn(c[2*j+1][0]*inv_lo, c[2*j+1][1]*inv_lo); ap[j][2] = *(uint32_t*)&h;
            h = __floats2half2_rn(c[2*j+1][2]*inv_hi, c[2*j+1][3]*inv_hi); ap[j][3] = *(uint32_t*)&h;
        }

        float c2[8][4];
        #pragma unroll
        for (int t = 0; t < 8; t++)
            #pragma unroll
            for (int q = 0; q < 4; q++) c2[t][q] = 0.f;

        #pragma unroll
        for (int j = 0; j < 7; j++) {
            int vrow = j*16 + l7 + 8*((lane>>3)&1);
            uint32_t vbase = vb + (uint32_t)(vrow * 128);
            #pragma unroll
            for (int g = 0; g < 4; g++) {
                uint32_t bb[4];
                ldsm4t(bb, vbase + (uint32_t)((((2*g) + (lane>>4)) ^ (vrow & 7)) << 4));
                MMA_F16(c2[2*g],   ap[j], bb[0], bb[1]);
                MMA_F16(c2[2*g+1], ap[j], bb[2], bb[3]);
            }
        }

        if (r_lo < 98) {
            __half* op = out + (size_t)ts[r_lo]*256 + hoff;
            #pragma unroll
            for (int t2 = 0; t2 < 8; t2++) {
                __half2 h = __floats2half2_rn(c2[t2][0], c2[t2][1]);
                *(__half2*)(op + t2*8 + mcol) = h;
            }
        }
        if (r_hi < 98) {
            __half* op = out + (size_t)ts[r_hi]*256 + hoff;
            #pragma unroll
            for (int t2 = 0; t2 < 8; t2++) {
                __half2 h = __floats2half2_rn(c2[t2][2], c2[t2][3]);
                *(__half2*)(op + t2*8 + mcol) = h;
            }
        }
    }
}

// ---------------- fp16 implicit-GEMM conv, M=128 tiles, 2-stage ring, 3 CTAs/SM -----
// grid 392; N=128 co; K = 27 taps x 128 ci as 54 stages of 64. 8 warps = 4(M) x 2(N).
// stage 32KB; 2-stage ring 64KB; smem alloc 68KB (epilogue Cbuf 128x132 = 67.6KB).
__global__ __launch_bounds__(256, 3) void conv_mma_kernel(
    const __half* __restrict__ Xin, const __half* __restrict__ w2,
    const float* __restrict__ bias, const float* __restrict__ res,
    float* __restrict__ outN, __half* __restrict__ outX, int leaky)
{
    extern __shared__ __align__(16) char dsm[];
    __shared__ float sbias[128];

    const int tid = threadIdx.x, lane = tid & 31, wid = tid >> 5;
    const int wm = wid & 3, wn = wid >> 2;
    const int bx = blockIdx.x;
    const int b = bx / 196;
    const int spb = (bx % 196) * 128;

    if (tid < 128) sbias[tid] = bias[tid];

    const int mrow = tid >> 1;
    const int q0 = (tid & 1) * 4;
    int sp_c = spb + mrow;
    int d_c = sp_c / 3136; int r_c = sp_c - d_c*3136; int h_c = r_c / 56, w_c = r_c - h_c*56;
    const int padrow = d_c*PDH + h_c*58 + w_c;
    const __half* XinB = Xin + (size_t)b * PAD_SP * 128;
    const uint32_t sb = smem_u32(dsm);
    const uint32_t dst = sb + (uint32_t)mrow*128u;
    FragCtx f = make_frag_ctx(lane, wm, wn);

    float c[2][8][4];
    #pragma unroll
    for (int t = 0; t < 2; t++)
        #pragma unroll
        for (int j = 0; j < 8; j++)
            #pragma unroll
            for (int q = 0; q < 4; q++) c[t][j][q] = 0.f;

    const int NST = 54;
    auto load_st = [&](int s) {
        int tap = s >> 1, kh64 = (s & 1) * 64;
        int kd = tap / 9; int rem = tap - kd*9; int kh = rem / 3, kw = rem - kh*3;
        int toff = kd*PDH + kh*58 + kw;
        uint32_t base = (uint32_t)(s & 1) * 32768u;   // 2-stage ring
        const __half* ga = XinB + (size_t)(padrow + toff)*128 + kh64;
        const __half* gb = w2 + ((size_t)tap*128 + mrow)*128 + kh64;
        #pragma unroll
        for (int q = q0; q < q0 + 4; q++) {
            uint32_t sw = (uint32_t)((q ^ (mrow & 7)) << 4);
            cp16(dst + base + sw, ga + q*8);
            cp16(dst + base + 16384u + sw, gb + q*8);
        }
    };
    load_st(0); CP_COMMIT();
    for (int k = 0; k < NST; k++) {
        if (k + 1 < NST) load_st(k + 1);
        CP_COMMIT();
        CP_WAIT1();
        __syncthreads();
        uint32_t Ab = sb + (uint32_t)(k & 1)*32768u;
        mma_stage(Ab, Ab + 16384u, f, c);
        __syncthreads();
    }

    float* Cb = (float*)dsm;   // 128 x 132 (67.6KB <= 68KB alloc)
    const int r0 = lane >> 2, c0 = lane & 3;
    #pragma unroll
    for (int t = 0; t < 2; t++) {
        int row = wm*32 + t*16 + r0;
        #pragma unroll
        for (int t2 = 0; t2 < 8; t2++) {
            int col = wn*64 + t2*8 + (c0 << 1);
            float b0s = sbias[col], b1s = sbias[col+1];
            float v0 = c[t][t2][0] + b0s;
            float v1 = c[t][t2][1] + b1s;
            float v2 = c[t][t2][2] + b0s;
            float v3 = c[t][t2][3] + b1s;
            if (leaky) {
                v0 = (v0 >= 0.f) ? v0 : 0.01f*v0;
                v1 = (v1 >= 0.f) ? v1 : 0.01f*v1;
                v2 = (v2 >= 0.f) ? v2 : 0.01f*v2;
                v3 = (v3 >= 0.f) ? v3 : 0.01f*v3;
            }
            Cb[row*132 + col]       = v0;
            Cb[row*132 + col + 1]   = v1;
            Cb[(row+8)*132 + col]   = v2;
            Cb[(row+8)*132 + col+1] = v3;
        }
    }
    __syncthreads();

    if (res) {
        int co = tid >> 1, mh = (tid & 1) << 6;
        const float* rp = res + (size_t)b*256*SP + (size_t)co*SP + spb + mh;
        #pragma unroll
        for (int j4 = 0; j4 < 16; j4++) {
            float4 r4 = *(const float4*)(rp + j4*4);
            Cb[(mh + j4*4 + 0)*132 + co] += r4.x;
            Cb[(mh + j4*4 + 1)*132 + co] += r4.y;
            Cb[(mh + j4*4 + 2)*132 + co] += r4.z;
            Cb[(mh + j4*4 + 3)*132 + co] += r4.w;
        }
        __syncthreads();
    }

    if (outX) {
        int m = tid >> 1, ch = (tid & 1) << 6;
        int sp = spb + m; int d = sp / 3136; int r = sp - d*3136; int h = r / 56, w = r - h*56;
        size_t po = (size_t)(d+1)*PDH + (size_t)(h+1)*58 + (w+1);
        __half* xp = outX + ((size_t)b*PAD_SP + po)*128 + ch;
        #pragma unroll
        for (int j8 = 0; j8 < 8; j8++) {
            const float* p = &Cb[m*132 + ch + j8*8];
            __half2 h0 = __floats2half2_rn(p[0], p[1]);
            __half2 h1 = __floats2half2_rn(p[2], p[3]);
            __half2 h2 = __floats2half2_rn(p[4], p[5]);
            __half2 h3 = __floats2half2_rn(p[6], p[7]);
            uint4 u;
            u.x = *(uint32_t*)&h0; u.y = *(uint32_t*)&h1;
            u.z = *(uint32_t*)&h2; u.w = *(uint32_t*)&h3;
            *(uint4*)(xp + j8*8) = u;
        }
    }
    if (outN) {
        int co = tid >> 1, mh = (tid & 1) << 6;
        float* op = outN + (size_t)b*256*SP + (size_t)co*SP + spb + mh;
        #pragma unroll
        for (int j4 = 0; j4 < 16; j4++) {
            float4 o;
            o.x = Cb[(mh + j4*4 + 0)*132 + co];
            o.y = Cb[(mh + j4*4 + 1)*132 + co];
            o.z = Cb[(mh + j4*4 + 2)*132 + co];
            o.w = Cb[(mh + j4*4 + 3)*132 + co];
            *(float4*)(op + j4*4) = o;
        }
    }
}

// ---------------- launcher ----------------
extern "C" void kernel_launch(void* const* d_in, const int* in_sizes, int n_in,
                              void* d_out, int out_size)
{
    (void)in_sizes; (void)n_in; (void)out_size;
    const float* input  = (const float*)d_in[0];
    const float* n1w    = (const float*)d_in[1];
    const float* n1b    = (const float*)d_in[2];
    const float* n2w    = (const float*)d_in[3];
    const float* n2b    = (const float*)d_in[4];
    const float* wqkv   = (const float*)d_in[5];
    const float* wprojw = (const float*)d_in[6];
    const float* wprojb = (const float*)d_in[7];
    const float* wbias  = (const float*)d_in[8];
    const float* gqkv   = (const float*)d_in[9];
    const float* gprojw = (const float*)d_in[10];
    const float* gprojb = (const float*)d_in[11];
    const float* gbias  = (const float*)d_in[12];
    const float* f1c1w  = (const float*)d_in[13];
    const float* f1c1b  = (const float*)d_in[14];
    const float* f1c2w  = (const float*)d_in[15];
    const float* f1c2b  = (const float*)d_in[16];
    const float* g1c1w  = (const float*)d_in[17];
    const float* g1c1b  = (const float*)d_in[18];
    const float* g1c2w  = (const float*)d_in[19];
    const float* g1c2b  = (const float*)d_in[20];
    float* out = (float*)d_out;

    __half *xh, *qkvh, *atnh, *Xa, *Xb, *w2h, *wqkvh, *gqkvh, *wprjh, *gprjh, *bmat;
    float *xw, *s;
    cudaGetSymbolAddress((void**)&xh,    g_xh);
    cudaGetSymbolAddress((void**)&qkvh,  g_qkvh);
    cudaGetSymbolAddress((void**)&atnh,  g_atnh);
    cudaGetSymbolAddress((void**)&xw,    g_xw);
    cudaGetSymbolAddress((void**)&s,     g_s);
    cudaGetSymbolAddress((void**)&Xa,    g_Xa);
    cudaGetSymbolAddress((void**)&Xb,    g_Xb);
    cudaGetSymbolAddress((void**)&w2h,   g_w2h);
    cudaGetSymbolAddress((void**)&wqkvh, g_wqkvh);
    cudaGetSymbolAddress((void**)&gqkvh, g_gqkvh);
    cudaGetSymbolAddress((void**)&wprjh, g_wprjh);
    cudaGetSymbolAddress((void**)&gprjh, g_gprjh);
    cudaGetSymbolAddress((void**)&bmat,  g_bmat);

    const int TSMEM = 3 * 32768;   // hgemm ring / Cbuf
    const int CSMEM = 69632;       // conv: 2x32KB ring; 68KB covers Cbuf 128*132*4
    cudaFuncSetAttribute(hgemm_kernel<1>,   cudaFuncAttributeMaxDynamicSharedMemorySize, TSMEM);
    cudaFuncSetAttribute(hgemm_kernel<0>,   cudaFuncAttributeMaxDynamicSharedMemorySize, TSMEM);
    cudaFuncSetAttribute(hgemm_fuse_kernel, cudaFuncAttributeMaxDynamicSharedMemorySize, TSMEM);
    cudaFuncSetAttribute(conv_mma_kernel,   cudaFuncAttributeMaxDynamicSharedMemorySize, CSMEM);

    // all prep in one launch
    prep_kernel<<<9408, 256>>>(wqkv, gqkv, wprojw, gprojw,
                               f1c1w, f1c2w, g1c1w, g1c2w, wbias, gbias,
                               wqkvh, gqkvh, wprjh, gprjh, w2h, bmat);

    // window attention block
    ln_in_kernel<<<1792, 256>>>(input, n1w, n1b, xh);
    hgemm_kernel<1><<<dim3(6, 392), 256, TSMEM>>>(xh, wqkvh, nullptr, nullptr, qkvh, 768);
    attn_mma_kernel<<<dim3(512, 4), 256>>>(qkvh, bmat, atnh, 0);
    hgemm_kernel<0><<<dim3(2, 392), 256, TSMEM>>>(atnh, wprjh, wprojb, nullptr, xw, 256);
    // grid attention block (proj fused with residuals -> s, Xa)
    ln_row_kernel<<<6272, 256>>>(xw, n2w, n2b, xh);
    hgemm_kernel<1><<<dim3(6, 392), 256, TSMEM>>>(xh, gqkvh, nullptr, nullptr, qkvh, 768);
    attn_mma_kernel<<<dim3(512, 4), 256>>>(qkvh, bmat + (size_t)4*128*112, atnh, 1);
    hgemm_fuse_kernel<<<dim3(2, 392), 256, TSMEM>>>(atnh, gprjh, gprojb, xw, input, s, Xa);

    // conv chain (392 blocks of 128-position tiles, 3 CTAs/SM, single wave)
    conv_mma_kernel<<<392, 256, CSMEM>>>(Xa, w2h,            f1c1b, nullptr, nullptr, Xb, 1);
    conv_mma_kernel<<<392, 256, CSMEM>>>(Xb, w2h + W2SZ,     f1c2b, s, out, Xa, 0);
    conv_mma_kernel<<<392, 256, CSMEM>>>(Xa, w2h + 2*W2SZ,   g1c1b, nullptr, nullptr, Xb, 1);
    conv_mma_kernel<<<392, 256, CSMEM>>>(Xb, w2h + 3*W2SZ,   g1c2b, s + (size_t)128*SP,
                                         out + (size_t)128*SP, nullptr, 0);
}

// round 14
// speedup vs baseline: 1.4646x; 1.4646x over previous
#include <cuda_runtime.h>
#include <cuda_fp16.h>
#include <cstdint>
#include <cstddef>

// ---------------- problem constants ----------------
#define SP    25088          // 8*56*56
#define T_TOK 50176          // 2*SP
#define NTOK  98
#define SCALE_Q 0.125f
#define PAD_SP 33640         // 10*58*58
#define PDH    3364          // 58*58
#define W2SZ  (27*128*128)

// ---------------- scratch ----------------
__device__ __half g_xh  [(size_t)T_TOK*256];
__device__ __half g_qkvh[(size_t)T_TOK*768];
__device__ __half g_atnh[(size_t)T_TOK*256];
__device__ float  g_xw  [(size_t)T_TOK*256];
__device__ float  g_s   [(size_t)T_TOK*256];
__device__ __half g_Xa  [(size_t)2*PAD_SP*128];   // zero-init padding stays zero
__device__ __half g_Xb  [(size_t)2*PAD_SP*128];
__device__ __half g_w2h [(size_t)4*W2SZ];         // 4 conv weights [tap][co][ci]
__device__ __half g_wqkvh[768*256];
__device__ __half g_gqkvh[768*256];
__device__ __half g_wprjh[256*256];
__device__ __half g_gprjh[256*256];
__device__ __half g_bmat[(size_t)2*4*128*112];    // bias matrices [attn][head][r][m], fp16

// ---------------- PTX helpers (sm_80-baseline only) ----------------
__device__ __forceinline__ uint32_t smem_u32(const void* p) {
    uint32_t a;
    asm("{ .reg .u64 t; cvta.to.shared.u64 t, %1; cvt.u32.u64 %0, t; }" : "=r"(a) : "l"(p));
    return a;
}
__device__ __forceinline__ void cp16(uint32_t s, const void* g) {
    asm volatile("cp.async.cg.shared.global [%0], [%1], 16;" :: "r"(s), "l"(g));
}
#define CP_COMMIT() asm volatile("cp.async.commit_group;" ::: "memory")
#define CP_WAIT1()  asm volatile("cp.async.wait_group 1;"  ::: "memory")

__device__ __forceinline__ void ldsm4(uint32_t* r, uint32_t a) {
    asm volatile("ldmatrix.sync.aligned.m8n8.x4.shared.b16 {%0,%1,%2,%3}, [%4];"
        : "=r"(r[0]), "=r"(r[1]), "=r"(r[2]), "=r"(r[3]) : "r"(a));
}
__device__ __forceinline__ void ldsm4t(uint32_t* r, uint32_t a) {
    asm volatile("ldmatrix.sync.aligned.m8n8.x4.trans.shared.b16 {%0,%1,%2,%3}, [%4];"
        : "=r"(r[0]), "=r"(r[1]), "=r"(r[2]), "=r"(r[3]) : "r"(a));
}
#define MMA_F16(c, a, b0, b1) \
    asm volatile("mma.sync.aligned.m16n8k16.row.col.f32.f16.f16.f32 " \
        "{%0,%1,%2,%3}, {%4,%5,%6,%7}, {%8,%9}, {%0,%1,%2,%3};" \
        : "+f"((c)[0]), "+f"((c)[1]), "+f"((c)[2]), "+f"((c)[3]) \
        : "r"((a)[0]), "r"((a)[1]), "r"((a)[2]), "r"((a)[3]), "r"(b0), "r"(b1))

// ---------------- all weight/bias prep in ONE kernel ----------------
__global__ __launch_bounds__(256) void prep_kernel(
    const float* __restrict__ wqkv, const float* __restrict__ gqkv,
    const float* __restrict__ wprj, const float* __restrict__ gprj,
    const float* __restrict__ c1w, const float* __restrict__ c2w,
    const float* __restrict__ c3w, const float* __restrict__ c4w,
    const float* __restrict__ wbias, const float* __restrict__ gbias,
    __half* __restrict__ wqkvh, __half* __restrict__ gqkvh,
    __half* __restrict__ wprjh, __half* __restrict__ gprjh,
    __half* __restrict__ w2h, __half* __restrict__ bmat)
{
    int bx = blockIdx.x, tid = threadIdx.x;
    if (bx < 1536) {                       // qkv weights f2h: 2 x 768 blocks
        int j = (bx >= 768) ? (bx - 768) : bx;
        const float* s = (bx < 768) ? wqkv : gqkv;
        __half* d = (bx < 768) ? wqkvh : gqkvh;
        int i = j*256 + tid;
        d[i] = __float2half_rn(s[i]);
    } else if (bx < 2048) {                // proj weights f2h: 2 x 256 blocks
        const float* s = (bx < 1792) ? wprj : gprj;
        __half* d = (bx < 1792) ? wprjh : gprjh;
        int j = bx - 1536; if (j >= 256) j -= 256;
        int i = j*256 + tid;
        d[i] = __float2half_rn(s[i]);
    } else if (bx < 8960) {                // conv weight transform: 4 x 1728 blocks
        int seg = (bx - 2048) / 1728;
        const float* w = (seg == 0) ? c1w : (seg == 1) ? c2w : (seg == 2) ? c3w : c4w;
        __half* o = w2h + (size_t)seg * W2SZ;
        int i = ((bx - 2048) % 1728)*256 + tid;
        int ci = i & 127; int r = i >> 7; int co = r & 127; int tap = r >> 7;
        o[i] = __float2half_rn(w[(co*128 + ci)*27 + tap]);
    } else {                               // bias matrices: 2 x 224 blocks
        int seg = (bx - 8960) / 224;
        const float* bt = seg ? gbias : wbias;
        __half* bm = bmat + (size_t)seg * 4*128*112;
        int i = ((bx - 8960) % 224)*256 + tid;
        int m = i % 112; int r = (i/112) & 127; int head = i / (112*128);
        float v = 0.f;
        if (r < 98) {
            if (m >= 98) v = -30000.f;     // mask (fits fp16; exp -> 0)
            else {
                int pd_r = r/49; int rr = r - pd_r*49; int ph_r = rr/7, pw_r = rr - ph_r*7;
                int pd_m = m/49; int mm = m - pd_m*49; int ph_m = mm/7, pw_m = mm - ph_m*7;
                int rpi = ((pd_r - pd_m + 1)*13 + (ph_r - ph_m + 6))*13 + (pw_r - pw_m + 6);
                v = bt[rpi*4 + head];
            }
        }
        bm[i] = __float2half_rn(v);
    }
}

// ---------------- LN kernels (output half) ----------------
__global__ __launch_bounds__(256) void ln_in_kernel(
    const float* __restrict__ in, const float* __restrict__ w,
    const float* __restrict__ b, __half* __restrict__ out)
{
    __shared__ float s[28][257];
    int bx = blockIdx.x;
    int wt = bx & 1; int tmp = bx >> 1;
    int h = tmp % 56; tmp /= 56;
    int d = tmp & 7; int bb = tmp >> 3;
    int w0 = wt * 28;
    size_t sp = ((size_t)d*56 + h)*56 + w0;
    const float* ib = in + (size_t)bb*256*SP + sp;
    for (int i = threadIdx.x; i < 28*256; i += 256) {
        int c = i / 28, ww_ = i - c*28;
        s[ww_][c] = ib[(size_t)c*SP + ww_];
    }
    __syncthreads();
    int warp = threadIdx.x >> 5, lane = threadIdx.x & 31;
    for (int tk = warp; tk < 28; tk += 8) {
        float s1 = 0.f, s2 = 0.f;
        #pragma unroll
        for (int j = 0; j < 8; j++) { float v = s[tk][lane + (j<<5)]; s1 += v; s2 += v*v; }
        #pragma unroll
        for (int o = 16; o; o >>= 1) {
            s1 += __shfl_xor_sync(0xffffffffu, s1, o);
            s2 += __shfl_xor_sync(0xffffffffu, s2, o);
        }
        float m = s1 * (1.f/256.f);
        float var = s2 * (1.f/256.f) - m*m;
        float iv = rsqrtf(var + 1e-5f);
        size_t t = (size_t)bb*SP + sp + tk;
        __half* orow = out + t*256;
        #pragma unroll
        for (int j = 0; j < 8; j++) {
            int c = lane + (j<<5);
            orow[c] = __float2half_rn((s[tk][c] - m) * iv * w[c] + b[c]);
        }
    }
}

__global__ __launch_bounds__(256) void ln_row_kernel(
    const float* __restrict__ in, const float* __restrict__ w,
    const float* __restrict__ b, __half* __restrict__ out)
{
    int t = blockIdx.x*8 + (threadIdx.x >> 5);
    int lane = threadIdx.x & 31;
    const float* row = in + (size_t)t*256;
    float v[8]; float s1 = 0.f, s2 = 0.f;
    #pragma unroll
    for (int j = 0; j < 8; j++) { v[j] = row[lane + (j<<5)]; s1 += v[j]; s2 += v[j]*v[j]; }
    #pragma unroll
    for (int o = 16; o; o >>= 1) {
        s1 += __shfl_xor_sync(0xffffffffu, s1, o);
        s2 += __shfl_xor_sync(0xffffffffu, s2, o);
    }
    float m = s1 * (1.f/256.f);
    float var = s2 * (1.f/256.f) - m*m;
    float iv = rsqrtf(var + 1e-5f);
    __half* orow = out + (size_t)t*256;
    #pragma unroll
    for (int j = 0; j < 8; j++) {
        int c = lane + (j<<5);
        orow[c] = __float2half_rn((v[j] - m) * iv * w[c] + b[c]);
    }
}

// ---------------- shared warp-MMA stage: 128x128 tile, BK=64 ----------------
struct FragCtx {
    uint32_t aoff;
    uint32_t boff;
    uint32_t axor[4];
    uint32_t bxor[4];
};
__device__ __forceinline__ FragCtx make_frag_ctx(int lane, int wm, int wn) {
    FragCtx f;
    int l7 = lane & 7;
    f.aoff = (uint32_t)((wm*32 + ((lane>>3)&1)*8 + l7) * 128);
    f.boff = (uint32_t)((wn*64 + ((lane>>4)&1)*8 + l7) * 128);
    #pragma unroll
    for (int kk = 0; kk < 4; kk++) {
        f.axor[kk] = (uint32_t)(((2*kk + (lane>>4)) ^ l7) << 4);
        f.bxor[kk] = (uint32_t)(((2*kk + ((lane>>3)&1)) ^ l7) << 4);
    }
    return f;
}
__device__ __forceinline__ void mma_stage(uint32_t Ab, uint32_t Bb,
                                          const FragCtx& f, float c[2][8][4])
{
    #pragma unroll
    for (int kk = 0; kk < 4; kk++) {
        uint32_t a0[4], a1[4];
        ldsm4(a0, Ab + f.aoff + f.axor[kk]);
        ldsm4(a1, Ab + f.aoff + 2048u + f.axor[kk]);
        #pragma unroll
        for (int g = 0; g < 4; g++) {
            uint32_t bb[4];
            ldsm4(bb, Bb + f.boff + (uint32_t)g*2048u + f.bxor[kk]);
            MMA_F16(c[0][2*g],   a0, bb[0], bb[1]);
            MMA_F16(c[1][2*g],   a1, bb[0], bb[1]);
            MMA_F16(c[0][2*g+1], a0, bb[2], bb[3]);
            MMA_F16(c[1][2*g+1], a1, bb[2], bb[3]);
        }
    }
}

// ---------------- shared mainloop body for 128x128 @ K=256 GEMM ----------------
__device__ __forceinline__ void hgemm_mainloop(
    const __half* asrc, const __half* bsrc, uint32_t sb, uint32_t dst,
    int q0, int mrow, const FragCtx& f, float c[2][8][4])
{
    auto load_st = [&](int s) {
        uint32_t base = (uint32_t)(s % 3) * 32768u;
        #pragma unroll
        for (int q = q0; q < q0 + 4; q++) {
            uint32_t sw = (uint32_t)((q ^ (mrow & 7)) << 4);
            cp16(dst + base + sw, asrc + s*64 + q*8);
            cp16(dst + base + 16384u + sw, bsrc + s*64 + q*8);
        }
    };
    load_st(0); CP_COMMIT();
    load_st(1); CP_COMMIT();
    #pragma unroll
    for (int k = 0; k < 4; k++) {
        CP_WAIT1();
        __syncthreads();
        if (k + 2 < 4) load_st(k + 2);
        CP_COMMIT();
        uint32_t Ab = sb + (uint32_t)(k % 3)*32768u;
        mma_stage(Ab, Ab + 16384u, f, c);
    }
    __syncthreads();
}

// ---------------- fp16 GEMM (plain): OUTHALF 1 -> C half, 0 -> C float (+res) --------
template<int OUTHALF>
__global__ __launch_bounds__(256, 2) void hgemm_kernel(
    const __half* __restrict__ A, const __half* __restrict__ B,
    const float* __restrict__ bias, const float* __restrict__ res,
    void* __restrict__ Cout, int N)
{
    extern __shared__ __align__(16) char dsm[];
    __shared__ float sbias[128];
    const int tid = threadIdx.x, lane = tid & 31, wid = tid >> 5;
    const int wm = wid & 3, wn = wid >> 2;
    const int bx = blockIdx.x, by = blockIdx.y;

    if (tid < 128) sbias[tid] = bias ? bias[bx*128 + tid] : 0.f;

    const int mrow = tid >> 1;
    const int q0 = (tid & 1) * 4;
    const uint32_t sb = smem_u32(dsm);
    FragCtx f = make_frag_ctx(lane, wm, wn);
    float c[2][8][4];
    #pragma unroll
    for (int t = 0; t < 2; t++)
        #pragma unroll
        for (int j = 0; j < 8; j++)
            #pragma unroll
            for (int q = 0; q < 4; q++) c[t][j][q] = 0.f;

    hgemm_mainloop(A + ((size_t)(by*128 + mrow))*256,
                   B + ((size_t)(bx*128 + mrow))*256,
                   sb, sb + (uint32_t)mrow*128u, q0, mrow, f, c);

    float* Cb = (float*)dsm;   // 128 x 132
    const int r0 = lane >> 2, c0 = lane & 3;
    #pragma unroll
    for (int t = 0; t < 2; t++) {
        int row = wm*32 + t*16 + r0;
        #pragma unroll
        for (int t2 = 0; t2 < 8; t2++) {
            int col = wn*64 + t2*8 + (c0 << 1);
            Cb[row*132 + col]       = c[t][t2][0] + sbias[col];
            Cb[row*132 + col + 1]   = c[t][t2][1] + sbias[col+1];
            Cb[(row+8)*132 + col]   = c[t][t2][2] + sbias[col];
            Cb[(row+8)*132 + col+1] = c[t][t2][3] + sbias[col+1];
        }
    }
    __syncthreads();

    const int m = tid >> 1, ch = (tid & 1) << 6;
    size_t goff = ((size_t)(by*128 + m))*N + bx*128 + ch;
    if (OUTHALF) {
        __half* Ch = (__half*)Cout;
        #pragma unroll
        for (int j8 = 0; j8 < 8; j8++) {
            const float* p = &Cb[m*132 + ch + j8*8];
            __half2 h0 = __floats2half2_rn(p[0], p[1]);
            __half2 h1 = __floats2half2_rn(p[2], p[3]);
            __half2 h2 = __floats2half2_rn(p[4], p[5]);
            __half2 h3 = __floats2half2_rn(p[6], p[7]);
            uint4 u;
            u.x = *(uint32_t*)&h0; u.y = *(uint32_t*)&h1;
            u.z = *(uint32_t*)&h2; u.w = *(uint32_t*)&h3;
            *(uint4*)(Ch + goff + j8*8) = u;
        }
    } else {
        float* Cf = (float*)Cout;
        #pragma unroll
        for (int j4 = 0; j4 < 16; j4++) {
            float4 v = *(const float4*)&Cb[m*132 + ch + j4*4];
            if (res) {
                float4 r = *(const float4*)(res + goff + j4*4);
                v.x += r.x; v.y += r.y; v.z += r.z; v.w += r.w;
            }
            *(float4*)(Cf + goff + j4*4) = v;
        }
    }
}

// ---------------- fused grid-proj: y = A@B^T + bias + xw; s = input + y; Xa = half(s2)
__global__ __launch_bounds__(256, 2) void hgemm_fuse_kernel(
    const __half* __restrict__ A, const __half* __restrict__ B,
    const float* __restrict__ bias, const float* __restrict__ xw,
    const float* __restrict__ input, float* __restrict__ s,
    __half* __restrict__ Xa)
{
    extern __shared__ __align__(16) char dsm[];
    __shared__ float sbias[128];
    const int tid = threadIdx.x, lane = tid & 31, wid = tid >> 5;
    const int wm = wid & 3, wn = wid >> 2;
    const int bx = blockIdx.x, by = blockIdx.y;

    if (tid < 128) sbias[tid] = bias[bx*128 + tid];

    const int mrow = tid >> 1;
    const int q0 = (tid & 1) * 4;
    const uint32_t sb = smem_u32(dsm);
    FragCtx f = make_frag_ctx(lane, wm, wn);
    float c[2][8][4];
    #pragma unroll
    for (int t = 0; t < 2; t++)
        #pragma unroll
        for (int j = 0; j < 8; j++)
            #pragma unroll
            for (int q = 0; q < 4; q++) c[t][j][q] = 0.f;

    hgemm_mainloop(A + ((size_t)(by*128 + mrow))*256,
                   B + ((size_t)(bx*128 + mrow))*256,
                   sb, sb + (uint32_t)mrow*128u, q0, mrow, f, c);

    float* Cb = (float*)dsm;   // 128 x 132, rows = tokens, cols = local chan
    const int r0 = lane >> 2, c0 = lane & 3;
    #pragma unroll
    for (int t = 0; t < 2; t++) {
        int row = wm*32 + t*16 + r0;
        #pragma unroll
        for (int t2 = 0; t2 < 8; t2++) {
            int col = wn*64 + t2*8 + (c0 << 1);
            Cb[row*132 + col]       = c[t][t2][0] + sbias[col];
            Cb[row*132 + col + 1]   = c[t][t2][1] + sbias[col+1];
            Cb[(row+8)*132 + col]   = c[t][t2][2] + sbias[col];
            Cb[(row+8)*132 + col+1] = c[t][t2][3] + sbias[col+1];
        }
    }
    __syncthreads();

    // phase A (token-major): y = Cb + xw
    const int m = tid >> 1, ch = (tid & 1) << 6;
    {
        size_t goff = ((size_t)(by*128 + m))*256 + bx*128 + ch;
        #pragma unroll
        for (int j4 = 0; j4 < 16; j4++) {
            float4 r = *(const float4*)(xw + goff + j4*4);
            float* p = &Cb[m*132 + ch + j4*4];
            p[0] += r.x; p[1] += r.y; p[2] += r.z; p[3] += r.w;
        }
    }
    __syncthreads();

    // phase B (chan-major, coalesced NCDHW): s = input + y; Cb <- s
    {
        const int co = tid >> 1, mh = (tid & 1) << 6;
        const int tok0 = by*128;
        const int b = tok0 / SP, sp0 = tok0 % SP;
        size_t gbase = (size_t)b*256*SP + (size_t)(bx*128 + co)*SP + sp0 + mh;
        #pragma unroll
        for (int j4 = 0; j4 < 16; j4++) {
            float4 iv = *(const float4*)(input + gbase + j4*4);
            float* p0 = &Cb[(mh + j4*4 + 0)*132 + co];
            float* p1 = &Cb[(mh + j4*4 + 1)*132 + co];
            float* p2 = &Cb[(mh + j4*4 + 2)*132 + co];
            float* p3 = &Cb[(mh + j4*4 + 3)*132 + co];
            float v0 = iv.x + *p0, v1 = iv.y + *p1, v2 = iv.z + *p2, v3 = iv.w + *p3;
            *p0 = v0; *p1 = v1; *p2 = v2; *p3 = v3;
            float4 o = make_float4(v0, v1, v2, v3);
            *(float4*)(s + gbase + j4*4) = o;
        }
    }
    __syncthreads();

    // phase C (token-major): Xa = half(s2) for channels 128..255 (bx==1)
    if (bx == 1) {
        const int tok = by*128 + m;
        const int b = tok / SP;
        int sp = tok % SP;
        int d = sp / 3136; int r = sp - d*3136; int h = r / 56, w = r - h*56;
        size_t po = (size_t)(d+1)*PDH + (size_t)(h+1)*58 + (w+1);
        __half* xp = Xa + ((size_t)b*PAD_SP + po)*128 + ch;
        #pragma unroll
        for (int j8 = 0; j8 < 8; j8++) {
            const float* p = &Cb[m*132 + ch + j8*8];
            __half2 h0 = __floats2half2_rn(p[0], p[1]);
            __half2 h1 = __floats2half2_rn(p[2], p[3]);
            __half2 h2 = __floats2half2_rn(p[4], p[5]);
            __half2 h3 = __floats2half2_rn(p[6], p[7]);
            uint4 u;
            u.x = *(uint32_t*)&h0; u.y = *(uint32_t*)&h1;
            u.z = *(uint32_t*)&h2; u.w = *(uint32_t*)&h3;
            *(uint4*)(xp + j8*8) = u;
        }
    }
}

// ---------------- tensor-core attention (M pad 112, 7 compute warps, fp16 bias) ------
__global__ __launch_bounds__(256, 3) void attn_mma_kernel(
    const __half* __restrict__ qkv, const __half* __restrict__ bmat,
    __half* __restrict__ out, int grid_mode)
{
    __shared__ __align__(16) __half Qs[112*64];
    __shared__ __align__(16) __half Ks[112*64];
    __shared__ __align__(16) __half Vs[112*64];
    __shared__ int ts[NTOK];

    const int tid = threadIdx.x, lane = tid & 31, warp = tid >> 5;
    const int wi = blockIdx.x, head = blockIdx.y;
    const int b = wi >> 8, wd = (wi>>6)&3, wh = (wi>>3)&7, ww = wi & 7;
    const int hoff = head << 6;

    if (tid < NTOK) {
        int pd = tid / 49; int r7 = tid - pd*49; int ph = r7 / 7, pw = r7 - ph*7;
        int d, h, w;
        if (grid_mode) { d = pd*4 + wd; h = ph*8 + wh; w = pw*8 + ww; }
        else           { d = wd*2 + pd; h = wh*7 + ph; w = ww*7 + pw; }
        ts[tid] = ((b*8 + d)*56 + h)*56 + w;
    }
    __syncthreads();

    {
        const int row = tid >> 1;
        const int cb = (tid & 1) * 4;
        const __half2 sc2 = __floats2half2_rn(SCALE_Q, SCALE_Q);
        const uint4 z4 = make_uint4(0,0,0,0);
        if (row < 112) {
            size_t base = (row < 98) ? ((size_t)ts[row]*768 + hoff) : 0;
            #pragma unroll
            for (int cc = 0; cc < 4; cc++) {
                int c = cb + cc;
                int sw8 = (c ^ (row & 7)) * 8;
                uint4 vq = z4, vk = z4, vv = z4;
                if (row < 98) {
                    vq = *(const uint4*)(qkv + base + c*8);
                    vk = *(const uint4*)(qkv + base + 256 + c*8);
                    vv = *(const uint4*)(qkv + base + 512 + c*8);
                    __half2* hq = (__half2*)&vq;
                    hq[0] = __hmul2(hq[0], sc2); hq[1] = __hmul2(hq[1], sc2);
                    hq[2] = __hmul2(hq[2], sc2); hq[3] = __hmul2(hq[3], sc2);
                }
                *(uint4*)(Qs + row*64 + sw8) = vq;
                *(uint4*)(Ks + row*64 + sw8) = vk;
                *(uint4*)(Vs + row*64 + sw8) = vv;
            }
        }
    }
    __syncthreads();

    if (warp < 7) {
        const uint32_t qb = smem_u32(Qs), kb = smem_u32(Ks), vb = smem_u32(Vs);
        const int l7 = lane & 7;

        float c[14][4];
        #pragma unroll
        for (int t = 0; t < 14; t++)
            #pragma unroll
            for (int q = 0; q < 4; q++) c[t][q] = 0.f;

        const uint32_t a_base = qb + (uint32_t)((warp*16 + ((lane>>3)&1)*8 + l7) * 128);
        const uint32_t b_rowo = (uint32_t)((((lane>>4)&1)*8 + l7) * 128);
        #pragma unroll
        for (int kk = 0; kk < 4; kk++) {
            uint32_t a[4];
            ldsm4(a, a_base + (uint32_t)(((2*kk + (lane>>4)) ^ l7) << 4));
            uint32_t bx_ = (uint32_t)(((2*kk + ((lane>>3)&1)) ^ l7) << 4);
            #pragma unroll
            for (int g = 0; g < 7; g++) {
                uint32_t bb[4];
                ldsm4(bb, kb + (uint32_t)(g*2048) + b_rowo + bx_);
                MMA_F16(c[2*g],   a, bb[0], bb[1]);
                MMA_F16(c[2*g+1], a, bb[2], bb[3]);
            }
        }

        const int r_lo = warp*16 + (lane >> 2);
        const int r_hi = r_lo + 8;
        const int mcol = (lane & 3) * 2;
        const __half* bm_lo = bmat + ((size_t)head*128 + r_lo)*112 + mcol;
        const __half* bm_hi = bm_lo + 8*112;
        float mx_lo = -1e30f, mx_hi = -1e30f;
        #pragma unroll
        for (int t = 0; t < 14; t++) {
            float2 blo = __half22float2(*(const __half2*)(bm_lo + t*8));
            float2 bhi = __half22float2(*(const __half2*)(bm_hi + t*8));
            c[t][0] += blo.x;  c[t][1] += blo.y;
            c[t][2] += bhi.x;  c[t][3] += bhi.y;
            mx_lo = fmaxf(mx_lo, fmaxf(c[t][0], c[t][1]));
            mx_hi = fmaxf(mx_hi, fmaxf(c[t][2], c[t][3]));
        }
        #pragma unroll
        for (int o = 1; o <= 2; o <<= 1) {
            mx_lo = fmaxf(mx_lo, __shfl_xor_sync(0xffffffffu, mx_lo, o));
            mx_hi = fmaxf(mx_hi, __shfl_xor_sync(0xffffffffu, mx_hi, o));
        }
        float sum_lo = 0.f, sum_hi = 0.f;
        #pragma unroll
        for (int t = 0; t < 14; t++) {
            c[t][0] = __expf(c[t][0] - mx_lo); sum_lo += c[t][0];
            c[t][1] = __expf(c[t][1] - mx_lo); sum_lo += c[t][1];
            c[t][2] = __expf(c[t][2] - mx_hi); sum_hi += c[t][2];
            c[t][3] = __expf(c[t][3] - mx_hi); sum_hi += c[t][3];
        }
        #pragma unroll
        for (int o = 1; o <= 2; o <<= 1) {
            sum_lo += __shfl_xor_sync(0xffffffffu, sum_lo, o);
            sum_hi += __shfl_xor_sync(0xffffffffu, sum_hi, o);
        }
        const float inv_lo = 1.f / sum_lo, inv_hi = 1.f / sum_hi;

        uint32_t ap[7][4];
        #pragma unroll
        for (int j = 0; j < 7; j++) {
            __half2 h;
            h = __floats2half2_rn(c[2*j][0]*inv_lo,   c[2*j][1]*inv_lo);   ap[j][0] = *(uint32_t*)&h;
            h = __floats2half2_rn(c[2*j][2]*inv_hi,   c[2*j][3]*inv_hi);   ap[j][1] = *(uint32_t*)&h;
            h = __floats2half2_rn(c[2*j+1][0]*inv_lo, c[2*j+1][1]*inv_lo); ap[j][2] = *(uint32_t*)&h;
            h = __floats2half2_rn(c[2*j+1][2]*inv_hi, c[2*j+1][3]*inv_hi); ap[j][3] = *(uint32_t*)&h;
        }

        float c2[8][4];
        #pragma unroll
        for (int t = 0; t < 8; t++)
            #pragma unroll
            for (int q = 0; q < 4; q++) c2[t][q] = 0.f;

        #pragma unroll
        for (int j = 0; j < 7; j++) {
            int vrow = j*16 + l7 + 8*((lane>>3)&1);
            uint32_t vbase = vb + (uint32_t)(vrow * 128);
            #pragma unroll
            for (int g = 0; g < 4; g++) {
                uint32_t bb[4];
                ldsm4t(bb, vbase + (uint32_t)((((2*g) + (lane>>4)) ^ (vrow & 7)) << 4));
                MMA_F16(c2[2*g],   ap[j], bb[0], bb[1]);
                MMA_F16(c2[2*g+1], ap[j], bb[2], bb[3]);
            }
        }

        if (r_lo < 98) {
            __half* op = out + (size_t)ts[r_lo]*256 + hoff;
            #pragma unroll
            for (int t2 = 0; t2 < 8; t2++) {
                __half2 h = __floats2half2_rn(c2[t2][0], c2[t2][1]);
                *(__half2*)(op + t2*8 + mcol) = h;
            }
        }
        if (r_hi < 98) {
            __half* op = out + (size_t)ts[r_hi]*256 + hoff;
            #pragma unroll
            for (int t2 = 0; t2 < 8; t2++) {
                __half2 h = __floats2half2_rn(c2[t2][2], c2[t2][3]);
                *(__half2*)(op + t2*8 + mcol) = h;
            }
        }
    }
}

// ---------------- fp16 implicit-GEMM conv (R11-proven: M=128, 3-stage ring) ----------
__global__ __launch_bounds__(256, 2) void conv_mma_kernel(
    const __half* __restrict__ Xin, const __half* __restrict__ w2,
    const float* __restrict__ bias, const float* __restrict__ res,
    float* __restrict__ outN, __half* __restrict__ outX, int leaky)
{
    extern __shared__ __align__(16) char dsm[];
    __shared__ float sbias[128];

    const int tid = threadIdx.x, lane = tid & 31, wid = tid >> 5;
    const int wm = wid & 3, wn = wid >> 2;
    const int bx = blockIdx.x;
    const int b = bx / 196;
    const int spb = (bx % 196) * 128;

    if (tid < 128) sbias[tid] = bias[tid];

    const int mrow = tid >> 1;
    const int q0 = (tid & 1) * 4;
    int sp_c = spb + mrow;
    int d_c = sp_c / 3136; int r_c = sp_c - d_c*3136; int h_c = r_c / 56, w_c = r_c - h_c*56;
    const int padrow = d_c*PDH + h_c*58 + w_c;
    const __half* XinB = Xin + (size_t)b * PAD_SP * 128;
    const uint32_t sb = smem_u32(dsm);
    const uint32_t dst = sb + (uint32_t)mrow*128u;
    FragCtx f = make_frag_ctx(lane, wm, wn);

    float c[2][8][4];
    #pragma unroll
    for (int t = 0; t < 2; t++)
        #pragma unroll
        for (int j = 0; j < 8; j++)
            #pragma unroll
            for (int q = 0; q < 4; q++) c[t][j][q] = 0.f;

    const int NST = 54;
    auto load_st = [&](int s) {
        int tap = s >> 1, kh64 = (s & 1) * 64;
        int kd = tap / 9; int rem = tap - kd*9; int kh = rem / 3, kw = rem - kh*3;
        int toff = kd*PDH + kh*58 + kw;
        uint32_t base = (uint32_t)(s % 3) * 32768u;
        const __half* ga = XinB + (size_t)(padrow + toff)*128 + kh64;
        const __half* gb = w2 + ((size_t)tap*128 + mrow)*128 + kh64;
        #pragma unroll
        for (int q = q0; q < q0 + 4; q++) {
            uint32_t sw = (uint32_t)((q ^ (mrow & 7)) << 4);
            cp16(dst + base + sw, ga + q*8);
            cp16(dst + base + 16384u + sw, gb + q*8);
        }
    };
    load_st(0); CP_COMMIT();
    load_st(1); CP_COMMIT();
    for (int k = 0; k < NST; k++) {
        CP_WAIT1();
        __syncthreads();
        if (k + 2 < NST) load_st(k + 2);
        CP_COMMIT();
        uint32_t Ab = sb + (uint32_t)(k % 3)*32768u;
        mma_stage(Ab, Ab + 16384u, f, c);
    }
    __syncthreads();

    float* Cb = (float*)dsm;   // 128 x 132
    const int r0 = lane >> 2, c0 = lane & 3;
    #pragma unroll
    for (int t = 0; t < 2; t++) {
        int row = wm*32 + t*16 + r0;
        #pragma unroll
        for (int t2 = 0; t2 < 8; t2++) {
            int col = wn*64 + t2*8 + (c0 << 1);
            float b0s = sbias[col], b1s = sbias[col+1];
            float v0 = c[t][t2][0] + b0s;
            float v1 = c[t][t2][1] + b1s;
            float v2 = c[t][t2][2] + b0s;
            float v3 = c[t][t2][3] + b1s;
            if (leaky) {
                v0 = (v0 >= 0.f) ? v0 : 0.01f*v0;
                v1 = (v1 >= 0.f) ? v1 : 0.01f*v1;
                v2 = (v2 >= 0.f) ? v2 : 0.01f*v2;
                v3 = (v3 >= 0.f) ? v3 : 0.01f*v3;
            }
            Cb[row*132 + col]       = v0;
            Cb[row*132 + col + 1]   = v1;
            Cb[(row+8)*132 + col]   = v2;
            Cb[(row+8)*132 + col+1] = v3;
        }
    }
    __syncthreads();

    if (res) {
        int co = tid >> 1, mh = (tid & 1) << 6;
        const float* rp = res + (size_t)b*256*SP + (size_t)co*SP + spb + mh;
        #pragma unroll
        for (int j4 = 0; j4 < 16; j4++) {
            float4 r4 = *(const float4*)(rp + j4*4);
            Cb[(mh + j4*4 + 0)*132 + co] += r4.x;
            Cb[(mh + j4*4 + 1)*132 + co] += r4.y;
            Cb[(mh + j4*4 + 2)*132 + co] += r4.z;
            Cb[(mh + j4*4 + 3)*132 + co] += r4.w;
        }
        __syncthreads();
    }

    if (outX) {
        int m = tid >> 1, ch = (tid & 1) << 6;
        int sp = spb + m; int d = sp / 3136; int r = sp - d*3136; int h = r / 56, w = r - h*56;
        size_t po = (size_t)(d+1)*PDH + (size_t)(h+1)*58 + (w+1);
        __half* xp = outX + ((size_t)b*PAD_SP + po)*128 + ch;
        #pragma unroll
        for (int j8 = 0; j8 < 8; j8++) {
            const float* p = &Cb[m*132 + ch + j8*8];
            __half2 h0 = __floats2half2_rn(p[0], p[1]);
            __half2 h1 = __floats2half2_rn(p[2], p[3]);
            __half2 h2 = __floats2half2_rn(p[4], p[5]);
            __half2 h3 = __floats2half2_rn(p[6], p[7]);
            uint4 u;
            u.x = *(uint32_t*)&h0; u.y = *(uint32_t*)&h1;
            u.z = *(uint32_t*)&h2; u.w = *(uint32_t*)&h3;
            *(uint4*)(xp + j8*8) = u;
        }
    }
    if (outN) {
        int co = tid >> 1, mh = (tid & 1) << 6;
        float* op = outN + (size_t)b*256*SP + (size_t)co*SP + spb + mh;
        #pragma unroll
        for (int j4 = 0; j4 < 16; j4++) {
            float4 o;
            o.x = Cb[(mh + j4*4 + 0)*132 + co];
            o.y = Cb[(mh + j4*4 + 1)*132 + co];
            o.z = Cb[(mh + j4*4 + 2)*132 + co];
            o.w = Cb[(mh + j4*4 + 3)*132 + co];
            *(float4*)(op + j4*4) = o;
        }
    }
}

// ---------------- launcher ----------------
extern "C" void kernel_launch(void* const* d_in, const int* in_sizes, int n_in,
                              void* d_out, int out_size)
{
    (void)in_sizes; (void)n_in; (void)out_size;
    const float* input  = (const float*)d_in[0];
    const float* n1w    = (const float*)d_in[1];
    const float* n1b    = (const float*)d_in[2];
    const float* n2w    = (const float*)d_in[3];
    const float* n2b    = (const float*)d_in[4];
    const float* wqkv   = (const float*)d_in[5];
    const float* wprojw = (const float*)d_in[6];
    const float* wprojb = (const float*)d_in[7];
    const float* wbias  = (const float*)d_in[8];
    const float* gqkv   = (const float*)d_in[9];
    const float* gprojw = (const float*)d_in[10];
    const float* gprojb = (const float*)d_in[11];
    const float* gbias  = (const float*)d_in[12];
    const float* f1c1w  = (const float*)d_in[13];
    const float* f1c1b  = (const float*)d_in[14];
    const float* f1c2w  = (const float*)d_in[15];
    const float* f1c2b  = (const float*)d_in[16];
    const float* g1c1w  = (const float*)d_in[17];
    const float* g1c1b  = (const float*)d_in[18];
    const float* g1c2w  = (const float*)d_in[19];
    const float* g1c2b  = (const float*)d_in[20];
    float* out = (float*)d_out;

    __half *xh, *qkvh, *atnh, *Xa, *Xb, *w2h, *wqkvh, *gqkvh, *wprjh, *gprjh, *bmat;
    float *xw, *s;
    cudaGetSymbolAddress((void**)&xh,    g_xh);
    cudaGetSymbolAddress((void**)&qkvh,  g_qkvh);
    cudaGetSymbolAddress((void**)&atnh,  g_atnh);
    cudaGetSymbolAddress((void**)&xw,    g_xw);
    cudaGetSymbolAddress((void**)&s,     g_s);
    cudaGetSymbolAddress((void**)&Xa,    g_Xa);
    cudaGetSymbolAddress((void**)&Xb,    g_Xb);
    cudaGetSymbolAddress((void**)&w2h,   g_w2h);
    cudaGetSymbolAddress((void**)&wqkvh, g_wqkvh);
    cudaGetSymbolAddress((void**)&gqkvh, g_gqkvh);
    cudaGetSymbolAddress((void**)&wprjh, g_wprjh);
    cudaGetSymbolAddress((void**)&gprjh, g_gprjh);
    cudaGetSymbolAddress((void**)&bmat,  g_bmat);

    const int TSMEM = 3 * 32768;   // shared by hgemm + conv rings / Cbuf
    cudaFuncSetAttribute(hgemm_kernel<1>,   cudaFuncAttributeMaxDynamicSharedMemorySize, TSMEM);
    cudaFuncSetAttribute(hgemm_kernel<0>,   cudaFuncAttributeMaxDynamicSharedMemorySize, TSMEM);
    cudaFuncSetAttribute(hgemm_fuse_kernel, cudaFuncAttributeMaxDynamicSharedMemorySize, TSMEM);
    cudaFuncSetAttribute(conv_mma_kernel,   cudaFuncAttributeMaxDynamicSharedMemorySize, TSMEM);

    // all prep in one launch
    prep_kernel<<<9408, 256>>>(wqkv, gqkv, wprojw, gprojw,
                               f1c1w, f1c2w, g1c1w, g1c2w, wbias, gbias,
                               wqkvh, gqkvh, wprjh, gprjh, w2h, bmat);

    // window attention block
    ln_in_kernel<<<1792, 256>>>(input, n1w, n1b, xh);
    hgemm_kernel<1><<<dim3(6, 392), 256, TSMEM>>>(xh, wqkvh, nullptr, nullptr, qkvh, 768);
    attn_mma_kernel<<<dim3(512, 4), 256>>>(qkvh, bmat, atnh, 0);
    hgemm_kernel<0><<<dim3(2, 392), 256, TSMEM>>>(atnh, wprjh, wprojb, nullptr, xw, 256);
    // grid attention block (proj fused with residuals -> s, Xa)
    ln_row_kernel<<<6272, 256>>>(xw, n2w, n2b, xh);
    hgemm_kernel<1><<<dim3(6, 392), 256, TSMEM>>>(xh, gqkvh, nullptr, nullptr, qkvh, 768);
    attn_mma_kernel<<<dim3(512, 4), 256>>>(qkvh, bmat + (size_t)4*128*112, atnh, 1);
    hgemm_fuse_kernel<<<dim3(2, 392), 256, TSMEM>>>(atnh, gprjh, gprojb, xw, input, s, Xa);

    // conv chain (R11-proven config: 392 blocks, 3-stage ring, 2 CTAs/SM)
    conv_mma_kernel<<<392, 256, TSMEM>>>(Xa, w2h,            f1c1b, nullptr, nullptr, Xb, 1);
    conv_mma_kernel<<<392, 256, TSMEM>>>(Xb, w2h + W2SZ,     f1c2b, s, out, Xa, 0);
    conv_mma_kernel<<<392, 256, TSMEM>>>(Xa, w2h + 2*W2SZ,   g1c1b, nullptr, nullptr, Xb, 1);
    conv_mma_kernel<<<392, 256, TSMEM>>>(Xb, w2h + 3*W2SZ,   g1c2b, s + (size_t)128*SP,
                                         out + (size_t)128*SP, nullptr, 0);
}

// round 15
// speedup vs baseline: 1.4733x; 1.0059x over previous
#include <cuda_runtime.h>
#include <cuda_fp16.h>
#include <cstdint>
#include <cstddef>

// ---------------- problem constants ----------------
#define SP    25088          // 8*56*56
#define T_TOK 50176          // 2*SP
#define NTOK  98
#define SCALE_Q 0.125f
#define PAD_SP 33640         // 10*58*58
#define PDH    3364          // 58*58
#define W2SZ  (27*128*128)

// ---------------- scratch ----------------
__device__ __half g_xh  [(size_t)T_TOK*256];
__device__ __half g_qkvh[(size_t)T_TOK*768];
__device__ __half g_atnh[(size_t)T_TOK*256];
__device__ __half g_xwh [(size_t)T_TOK*256];      // window-attn output, fp16
__device__ float  g_s   [(size_t)T_TOK*256];
__device__ __half g_Xa  [(size_t)2*PAD_SP*128];   // zero-init padding stays zero
__device__ __half g_Xb  [(size_t)2*PAD_SP*128];
__device__ __half g_w2h [(size_t)4*W2SZ];         // 4 conv weights [tap][co][ci]
__device__ __half g_wqkvh[768*256];
__device__ __half g_gqkvh[768*256];
__device__ __half g_wprjh[256*256];
__device__ __half g_gprjh[256*256];
__device__ __half g_bmat[(size_t)2*4*128*112];    // bias matrices [attn][head][r][m], fp16

// ---------------- PTX helpers (sm_80-baseline only) ----------------
__device__ __forceinline__ uint32_t smem_u32(const void* p) {
    uint32_t a;
    asm("{ .reg .u64 t; cvta.to.shared.u64 t, %1; cvt.u32.u64 %0, t; }" : "=r"(a) : "l"(p));
    return a;
}
__device__ __forceinline__ void cp16(uint32_t s, const void* g) {
    asm volatile("cp.async.cg.shared.global [%0], [%1], 16;" :: "r"(s), "l"(g));
}
#define CP_COMMIT() asm volatile("cp.async.commit_group;" ::: "memory")
#define CP_WAIT1()  asm volatile("cp.async.wait_group 1;"  ::: "memory")

__device__ __forceinline__ void ldsm4(uint32_t* r, uint32_t a) {
    asm volatile("ldmatrix.sync.aligned.m8n8.x4.shared.b16 {%0,%1,%2,%3}, [%4];"
        : "=r"(r[0]), "=r"(r[1]), "=r"(r[2]), "=r"(r[3]) : "r"(a));
}
__device__ __forceinline__ void ldsm4t(uint32_t* r, uint32_t a) {
    asm volatile("ldmatrix.sync.aligned.m8n8.x4.trans.shared.b16 {%0,%1,%2,%3}, [%4];"
        : "=r"(r[0]), "=r"(r[1]), "=r"(r[2]), "=r"(r[3]) : "r"(a));
}
#define MMA_F16(c, a, b0, b1) \
    asm volatile("mma.sync.aligned.m16n8k16.row.col.f32.f16.f16.f32 " \
        "{%0,%1,%2,%3}, {%4,%5,%6,%7}, {%8,%9}, {%0,%1,%2,%3};" \
        : "+f"((c)[0]), "+f"((c)[1]), "+f"((c)[2]), "+f"((c)[3]) \
        : "r"((a)[0]), "r"((a)[1]), "r"((a)[2]), "r"((a)[3]), "r"(b0), "r"(b1))

// ---------------- weight/bias prep + LN1, ONE kernel ----------------
__global__ __launch_bounds__(256) void prep_kernel(
    const float* __restrict__ wqkv, const float* __restrict__ gqkv,
    const float* __restrict__ wprj, const float* __restrict__ gprj,
    const float* __restrict__ c1w, const float* __restrict__ c2w,
    const float* __restrict__ c3w, const float* __restrict__ c4w,
    const float* __restrict__ wbias, const float* __restrict__ gbias,
    __half* __restrict__ wqkvh, __half* __restrict__ gqkvh,
    __half* __restrict__ wprjh, __half* __restrict__ gprjh,
    __half* __restrict__ w2h, __half* __restrict__ bmat,
    const float* __restrict__ in, const float* __restrict__ n1w,
    const float* __restrict__ n1b, __half* __restrict__ xh)
{
    __shared__ float s[28][257];
    int bx = blockIdx.x, tid = threadIdx.x;
    if (bx < 1536) {                       // qkv weights f2h
        int j = (bx >= 768) ? (bx - 768) : bx;
        const float* sp = (bx < 768) ? wqkv : gqkv;
        __half* d = (bx < 768) ? wqkvh : gqkvh;
        int i = j*256 + tid;
        d[i] = __float2half_rn(sp[i]);
    } else if (bx < 2048) {                // proj weights f2h
        const float* sp = (bx < 1792) ? wprj : gprj;
        __half* d = (bx < 1792) ? wprjh : gprjh;
        int j = bx - 1536; if (j >= 256) j -= 256;
        int i = j*256 + tid;
        d[i] = __float2half_rn(sp[i]);
    } else if (bx < 8960) {                // conv weight transform
        int seg = (bx - 2048) / 1728;
        const float* w = (seg == 0) ? c1w : (seg == 1) ? c2w : (seg == 2) ? c3w : c4w;
        __half* o = w2h + (size_t)seg * W2SZ;
        int i = ((bx - 2048) % 1728)*256 + tid;
        int ci = i & 127; int r = i >> 7; int co = r & 127; int tap = r >> 7;
        o[i] = __float2half_rn(w[(co*128 + ci)*27 + tap]);
    } else if (bx < 9408) {                // bias matrices
        int seg = (bx - 8960) / 224;
        const float* bt = seg ? gbias : wbias;
        __half* bm = bmat + (size_t)seg * 4*128*112;
        int i = ((bx - 8960) % 224)*256 + tid;
        int m = i % 112; int r = (i/112) & 127; int head = i / (112*128);
        float v = 0.f;
        if (r < 98) {
            if (m >= 98) v = -30000.f;
            else {
                int pd_r = r/49; int rr = r - pd_r*49; int ph_r = rr/7, pw_r = rr - ph_r*7;
                int pd_m = m/49; int mm = m - pd_m*49; int ph_m = mm/7, pw_m = mm - ph_m*7;
                int rpi = ((pd_r - pd_m + 1)*13 + (ph_r - ph_m + 6))*13 + (pw_r - pw_m + 6);
                v = bt[rpi*4 + head];
            }
        }
        bm[i] = __float2half_rn(v);
    } else {                               // LN1 (NCDHW -> token-major half)
        int j = bx - 9408;
        int wt = j & 1; int tmp = j >> 1;
        int h = tmp % 56; tmp /= 56;
        int d = tmp & 7; int bb = tmp >> 3;
        int w0 = wt * 28;
        size_t sp0 = ((size_t)d*56 + h)*56 + w0;
        const float* ib = in + (size_t)bb*256*SP + sp0;
        for (int i = tid; i < 28*256; i += 256) {
            int c = i / 28, ww_ = i - c*28;
            s[ww_][c] = ib[(size_t)c*SP + ww_];
        }
        __syncthreads();
        int warp = tid >> 5, lane = tid & 31;
        for (int tk = warp; tk < 28; tk += 8) {
            float s1 = 0.f, s2 = 0.f;
            #pragma unroll
            for (int q = 0; q < 8; q++) { float v = s[tk][lane + (q<<5)]; s1 += v; s2 += v*v; }
            #pragma unroll
            for (int o = 16; o; o >>= 1) {
                s1 += __shfl_xor_sync(0xffffffffu, s1, o);
                s2 += __shfl_xor_sync(0xffffffffu, s2, o);
            }
            float m = s1 * (1.f/256.f);
            float var = s2 * (1.f/256.f) - m*m;
            float iv = rsqrtf(var + 1e-5f);
            size_t t = (size_t)bb*SP + sp0 + tk;
            __half* orow = xh + t*256;
            #pragma unroll
            for (int q = 0; q < 8; q++) {
                int c = lane + (q<<5);
                orow[c] = __float2half_rn((s[tk][c] - m) * iv * n1w[c] + n1b[c]);
            }
        }
    }
}

// ---------------- LN2: half in, half out, vectorized ----------------
__global__ __launch_bounds__(256) void ln_row_kernel(
    const __half* __restrict__ in, const float* __restrict__ w,
    const float* __restrict__ b, __half* __restrict__ out)
{
    int t = blockIdx.x*8 + (threadIdx.x >> 5);
    int lane = threadIdx.x & 31;
    const __half* row = in + (size_t)t*256 + lane*8;
    uint4 u = *(const uint4*)row;
    const __half2* hp = (const __half2*)&u;
    float v[8];
    float s1 = 0.f, s2 = 0.f;
    #pragma unroll
    for (int j = 0; j < 4; j++) {
        float2 f = __half22float2(hp[j]);
        v[2*j] = f.x; v[2*j+1] = f.y;
        s1 += f.x + f.y; s2 += f.x*f.x + f.y*f.y;
    }
    #pragma unroll
    for (int o = 16; o; o >>= 1) {
        s1 += __shfl_xor_sync(0xffffffffu, s1, o);
        s2 += __shfl_xor_sync(0xffffffffu, s2, o);
    }
    float m = s1 * (1.f/256.f);
    float var = s2 * (1.f/256.f) - m*m;
    float iv = rsqrtf(var + 1e-5f);
    int c0 = lane*8;
    float4 w0 = *(const float4*)(w + c0);
    float4 w1 = *(const float4*)(w + c0 + 4);
    float4 b0 = *(const float4*)(b + c0);
    float4 b1 = *(const float4*)(b + c0 + 4);
    __half2 h0 = __floats2half2_rn((v[0]-m)*iv*w0.x + b0.x, (v[1]-m)*iv*w0.y + b0.y);
    __half2 h1 = __floats2half2_rn((v[2]-m)*iv*w0.z + b0.z, (v[3]-m)*iv*w0.w + b0.w);
    __half2 h2 = __floats2half2_rn((v[4]-m)*iv*w1.x + b1.x, (v[5]-m)*iv*w1.y + b1.y);
    __half2 h3 = __floats2half2_rn((v[6]-m)*iv*w1.z + b1.z, (v[7]-m)*iv*w1.w + b1.w);
    uint4 o;
    o.x = *(uint32_t*)&h0; o.y = *(uint32_t*)&h1;
    o.z = *(uint32_t*)&h2; o.w = *(uint32_t*)&h3;
    *(uint4*)(out + (size_t)t*256 + c0) = o;
}

// ---------------- shared warp-MMA stage: 128x128 tile, BK=64 ----------------
struct FragCtx {
    uint32_t aoff;
    uint32_t boff;
    uint32_t axor[4];
    uint32_t bxor[4];
};
__device__ __forceinline__ FragCtx make_frag_ctx(int lane, int wm, int wn) {
    FragCtx f;
    int l7 = lane & 7;
    f.aoff = (uint32_t)((wm*32 + ((lane>>3)&1)*8 + l7) * 128);
    f.boff = (uint32_t)((wn*64 + ((lane>>4)&1)*8 + l7) * 128);
    #pragma unroll
    for (int kk = 0; kk < 4; kk++) {
        f.axor[kk] = (uint32_t)(((2*kk + (lane>>4)) ^ l7) << 4);
        f.bxor[kk] = (uint32_t)(((2*kk + ((lane>>3)&1)) ^ l7) << 4);
    }
    return f;
}
__device__ __forceinline__ void mma_stage(uint32_t Ab, uint32_t Bb,
                                          const FragCtx& f, float c[2][8][4])
{
    #pragma unroll
    for (int kk = 0; kk < 4; kk++) {
        uint32_t a0[4], a1[4];
        ldsm4(a0, Ab + f.aoff + f.axor[kk]);
        ldsm4(a1, Ab + f.aoff + 2048u + f.axor[kk]);
        #pragma unroll
        for (int g = 0; g < 4; g++) {
            uint32_t bb[4];
            ldsm4(bb, Bb + f.boff + (uint32_t)g*2048u + f.bxor[kk]);
            MMA_F16(c[0][2*g],   a0, bb[0], bb[1]);
            MMA_F16(c[1][2*g],   a1, bb[0], bb[1]);
            MMA_F16(c[0][2*g+1], a0, bb[2], bb[3]);
            MMA_F16(c[1][2*g+1], a1, bb[2], bb[3]);
        }
    }
}

// ---------------- shared mainloop body for 128x128 @ K=256 GEMM ----------------
__device__ __forceinline__ void hgemm_mainloop(
    const __half* asrc, const __half* bsrc, uint32_t sb, uint32_t dst,
    int q0, int mrow, const FragCtx& f, float c[2][8][4])
{
    auto load_st = [&](int s) {
        uint32_t base = (uint32_t)(s % 3) * 32768u;
        #pragma unroll
        for (int q = q0; q < q0 + 4; q++) {
            uint32_t sw = (uint32_t)((q ^ (mrow & 7)) << 4);
            cp16(dst + base + sw, asrc + s*64 + q*8);
            cp16(dst + base + 16384u + sw, bsrc + s*64 + q*8);
        }
    };
    load_st(0); CP_COMMIT();
    load_st(1); CP_COMMIT();
    #pragma unroll
    for (int k = 0; k < 4; k++) {
        CP_WAIT1();
        __syncthreads();
        if (k + 2 < 4) load_st(k + 2);
        CP_COMMIT();
        uint32_t Ab = sb + (uint32_t)(k % 3)*32768u;
        mma_stage(Ab, Ab + 16384u, f, c);
    }
    __syncthreads();
}

// ---------------- fp16 GEMM (plain): C half (+bias) ----------------
__global__ __launch_bounds__(256, 2) void hgemm_kernel(
    const __half* __restrict__ A, const __half* __restrict__ B,
    const float* __restrict__ bias, __half* __restrict__ Cout, int N)
{
    extern __shared__ __align__(16) char dsm[];
    __shared__ float sbias[128];
    const int tid = threadIdx.x, lane = tid & 31, wid = tid >> 5;
    const int wm = wid & 3, wn = wid >> 2;
    const int bx = blockIdx.x, by = blockIdx.y;

    if (tid < 128) sbias[tid] = bias ? bias[bx*128 + tid] : 0.f;

    const int mrow = tid >> 1;
    const int q0 = (tid & 1) * 4;
    const uint32_t sb = smem_u32(dsm);
    FragCtx f = make_frag_ctx(lane, wm, wn);
    float c[2][8][4];
    #pragma unroll
    for (int t = 0; t < 2; t++)
        #pragma unroll
        for (int j = 0; j < 8; j++)
            #pragma unroll
            for (int q = 0; q < 4; q++) c[t][j][q] = 0.f;

    hgemm_mainloop(A + ((size_t)(by*128 + mrow))*256,
                   B + ((size_t)(bx*128 + mrow))*256,
                   sb, sb + (uint32_t)mrow*128u, q0, mrow, f, c);

    float* Cb = (float*)dsm;   // 128 x 132
    const int r0 = lane >> 2, c0 = lane & 3;
    #pragma unroll
    for (int t = 0; t < 2; t++) {
        int row = wm*32 + t*16 + r0;
        #pragma unroll
        for (int t2 = 0; t2 < 8; t2++) {
            int col = wn*64 + t2*8 + (c0 << 1);
            Cb[row*132 + col]       = c[t][t2][0] + sbias[col];
            Cb[row*132 + col + 1]   = c[t][t2][1] + sbias[col+1];
            Cb[(row+8)*132 + col]   = c[t][t2][2] + sbias[col];
            Cb[(row+8)*132 + col+1] = c[t][t2][3] + sbias[col+1];
        }
    }
    __syncthreads();

    const int m = tid >> 1, ch = (tid & 1) << 6;
    size_t goff = ((size_t)(by*128 + m))*N + bx*128 + ch;
    #pragma unroll
    for (int j8 = 0; j8 < 8; j8++) {
        const float* p = &Cb[m*132 + ch + j8*8];
        __half2 h0 = __floats2half2_rn(p[0], p[1]);
        __half2 h1 = __floats2half2_rn(p[2], p[3]);
        __half2 h2 = __floats2half2_rn(p[4], p[5]);
        __half2 h3 = __floats2half2_rn(p[6], p[7]);
        uint4 u;
        u.x = *(uint32_t*)&h0; u.y = *(uint32_t*)&h1;
        u.z = *(uint32_t*)&h2; u.w = *(uint32_t*)&h3;
        *(uint4*)(Cout + goff + j8*8) = u;
    }
}

// ---------------- fused grid-proj: y = A@B^T + bias + xw; s = input + y; Xa = half(s2)
__global__ __launch_bounds__(256, 2) void hgemm_fuse_kernel(
    const __half* __restrict__ A, const __half* __restrict__ B,
    const float* __restrict__ bias, const __half* __restrict__ xw,
    const float* __restrict__ input, float* __restrict__ s,
    __half* __restrict__ Xa)
{
    extern __shared__ __align__(16) char dsm[];
    __shared__ float sbias[128];
    const int tid = threadIdx.x, lane = tid & 31, wid = tid >> 5;
    const int wm = wid & 3, wn = wid >> 2;
    const int bx = blockIdx.x, by = blockIdx.y;

    if (tid < 128) sbias[tid] = bias[bx*128 + tid];

    const int mrow = tid >> 1;
    const int q0 = (tid & 1) * 4;
    const uint32_t sb = smem_u32(dsm);
    FragCtx f = make_frag_ctx(lane, wm, wn);
    float c[2][8][4];
    #pragma unroll
    for (int t = 0; t < 2; t++)
        #pragma unroll
        for (int j = 0; j < 8; j++)
            #pragma unroll
            for (int q = 0; q < 4; q++) c[t][j][q] = 0.f;

    hgemm_mainloop(A + ((size_t)(by*128 + mrow))*256,
                   B + ((size_t)(bx*128 + mrow))*256,
                   sb, sb + (uint32_t)mrow*128u, q0, mrow, f, c);

    float* Cb = (float*)dsm;   // 128 x 132, rows = tokens, cols = local chan
    const int r0 = lane >> 2, c0 = lane & 3;
    #pragma unroll
    for (int t = 0; t < 2; t++) {
        int row = wm*32 + t*16 + r0;
        #pragma unroll
        for (int t2 = 0; t2 < 8; t2++) {
            int col = wn*64 + t2*8 + (c0 << 1);
            Cb[row*132 + col]       = c[t][t2][0] + sbias[col];
            Cb[row*132 + col + 1]   = c[t][t2][1] + sbias[col+1];
            Cb[(row+8)*132 + col]   = c[t][t2][2] + sbias[col];
            Cb[(row+8)*132 + col+1] = c[t][t2][3] + sbias[col+1];
        }
    }
    __syncthreads();

    // phase A (token-major): y = Cb + xw  (xw fp16)
    const int m = tid >> 1, ch = (tid & 1) << 6;
    {
        size_t goff = ((size_t)(by*128 + m))*256 + bx*128 + ch;
        #pragma unroll
        for (int j8 = 0; j8 < 8; j8++) {
            uint4 u = *(const uint4*)(xw + goff + j8*8);
            const __half2* hp = (const __half2*)&u;
            float* p = &Cb[m*132 + ch + j8*8];
            #pragma unroll
            for (int q = 0; q < 4; q++) {
                float2 fv = __half22float2(hp[q]);
                p[2*q]   += fv.x;
                p[2*q+1] += fv.y;
            }
        }
    }
    __syncthreads();

    // phase B (chan-major, coalesced NCDHW): s = input + y; Cb <- s
    {
        const int co = tid >> 1, mh = (tid & 1) << 6;
        const int tok0 = by*128;
        const int b = tok0 / SP, sp0 = tok0 % SP;
        size_t gbase = (size_t)b*256*SP + (size_t)(bx*128 + co)*SP + sp0 + mh;
        #pragma unroll
        for (int j4 = 0; j4 < 16; j4++) {
            float4 iv = *(const float4*)(input + gbase + j4*4);
            float* p0 = &Cb[(mh + j4*4 + 0)*132 + co];
            float* p1 = &Cb[(mh + j4*4 + 1)*132 + co];
            float* p2 = &Cb[(mh + j4*4 + 2)*132 + co];
            float* p3 = &Cb[(mh + j4*4 + 3)*132 + co];
            float v0 = iv.x + *p0, v1 = iv.y + *p1, v2 = iv.z + *p2, v3 = iv.w + *p3;
            *p0 = v0; *p1 = v1; *p2 = v2; *p3 = v3;
            float4 o = make_float4(v0, v1, v2, v3);
            *(float4*)(s + gbase + j4*4) = o;
        }
    }
    __syncthreads();

    // phase C (token-major): Xa = half(s2) for channels 128..255 (bx==1)
    if (bx == 1) {
        const int tok = by*128 + m;
        const int b = tok / SP;
        int sp = tok % SP;
        int d = sp / 3136; int r = sp - d*3136; int h = r / 56, w = r - h*56;
        size_t po = (size_t)(d+1)*PDH + (size_t)(h+1)*58 + (w+1);
        __half* xp = Xa + ((size_t)b*PAD_SP + po)*128 + ch;
        #pragma unroll
        for (int j8 = 0; j8 < 8; j8++) {
            const float* p = &Cb[m*132 + ch + j8*8];
            __half2 h0 = __floats2half2_rn(p[0], p[1]);
            __half2 h1 = __floats2half2_rn(p[2], p[3]);
            __half2 h2 = __floats2half2_rn(p[4], p[5]);
            __half2 h3 = __floats2half2_rn(p[6], p[7]);
            uint4 u;
            u.x = *(uint32_t*)&h0; u.y = *(uint32_t*)&h1;
            u.z = *(uint32_t*)&h2; u.w = *(uint32_t*)&h3;
            *(uint4*)(xp + j8*8) = u;
        }
    }
}

// ---------------- tensor-core attention (M pad 112, 7 compute warps, fp16 bias) ------
// SCALE_Q folded into post-MMA bias FMA.
__global__ __launch_bounds__(256, 3) void attn_mma_kernel(
    const __half* __restrict__ qkv, const __half* __restrict__ bmat,
    __half* __restrict__ out, int grid_mode)
{
    __shared__ __align__(16) __half Qs[112*64];
    __shared__ __align__(16) __half Ks[112*64];
    __shared__ __align__(16) __half Vs[112*64];
    __shared__ int ts[NTOK];

    const int tid = threadIdx.x, lane = tid & 31, warp = tid >> 5;
    const int wi = blockIdx.x, head = blockIdx.y;
    const int b = wi >> 8, wd = (wi>>6)&3, wh = (wi>>3)&7, ww = wi & 7;
    const int hoff = head << 6;

    if (tid < NTOK) {
        int pd = tid / 49; int r7 = tid - pd*49; int ph = r7 / 7, pw = r7 - ph*7;
        int d, h, w;
        if (grid_mode) { d = pd*4 + wd; h = ph*8 + wh; w = pw*8 + ww; }
        else           { d = wd*2 + pd; h = wh*7 + ph; w = ww*7 + pw; }
        ts[tid] = ((b*8 + d)*56 + h)*56 + w;
    }
    __syncthreads();

    {
        const int row = tid >> 1;
        const int cb = (tid & 1) * 4;
        const uint4 z4 = make_uint4(0,0,0,0);
        if (row < 112) {
            size_t base = (row < 98) ? ((size_t)ts[row]*768 + hoff) : 0;
            #pragma unroll
            for (int cc = 0; cc < 4; cc++) {
                int c = cb + cc;
                int sw8 = (c ^ (row & 7)) * 8;
                uint4 vq = z4, vk = z4, vv = z4;
                if (row < 98) {
                    vq = *(const uint4*)(qkv + base + c*8);
                    vk = *(const uint4*)(qkv + base + 256 + c*8);
                    vv = *(const uint4*)(qkv + base + 512 + c*8);
                }
                *(uint4*)(Qs + row*64 + sw8) = vq;
                *(uint4*)(Ks + row*64 + sw8) = vk;
                *(uint4*)(Vs + row*64 + sw8) = vv;
            }
        }
    }
    __syncthreads();

    if (warp < 7) {
        const uint32_t qb = smem_u32(Qs), kb = smem_u32(Ks), vb = smem_u32(Vs);
        const int l7 = lane & 7;

        float c[14][4];
        #pragma unroll
        for (int t = 0; t < 14; t++)
            #pragma unroll
            for (int q = 0; q < 4; q++) c[t][q] = 0.f;

        const uint32_t a_base = qb + (uint32_t)((warp*16 + ((lane>>3)&1)*8 + l7) * 128);
        const uint32_t b_rowo = (uint32_t)((((lane>>4)&1)*8 + l7) * 128);
        #pragma unroll
        for (int kk = 0; kk < 4; kk++) {
            uint32_t a[4];
            ldsm4(a, a_base + (uint32_t)(((2*kk + (lane>>4)) ^ l7) << 4));
            uint32_t bx_ = (uint32_t)(((2*kk + ((lane>>3)&1)) ^ l7) << 4);
            #pragma unroll
            for (int g = 0; g < 7; g++) {
                uint32_t bb[4];
                ldsm4(bb, kb + (uint32_t)(g*2048) + b_rowo + bx_);
                MMA_F16(c[2*g],   a, bb[0], bb[1]);
                MMA_F16(c[2*g+1], a, bb[2], bb[3]);
            }
        }

        const int r_lo = warp*16 + (lane >> 2);
        const int r_hi = r_lo + 8;
        const int mcol = (lane & 3) * 2;
        const __half* bm_lo = bmat + ((size_t)head*128 + r_lo)*112 + mcol;
        const __half* bm_hi = bm_lo + 8*112;
        float mx_lo = -1e30f, mx_hi = -1e30f;
        #pragma unroll
        for (int t = 0; t < 14; t++) {
            float2 blo = __half22float2(*(const __half2*)(bm_lo + t*8));
            float2 bhi = __half22float2(*(const __half2*)(bm_hi + t*8));
            c[t][0] = fmaf(c[t][0], SCALE_Q, blo.x);
            c[t][1] = fmaf(c[t][1], SCALE_Q, blo.y);
            c[t][2] = fmaf(c[t][2], SCALE_Q, bhi.x);
            c[t][3] = fmaf(c[t][3], SCALE_Q, bhi.y);
            mx_lo = fmaxf(mx_lo, fmaxf(c[t][0], c[t][1]));
            mx_hi = fmaxf(mx_hi, fmaxf(c[t][2], c[t][3]));
        }
        #pragma unroll
        for (int o = 1; o <= 2; o <<= 1) {
            mx_lo = fmaxf(mx_lo, __shfl_xor_sync(0xffffffffu, mx_lo, o));
            mx_hi = fmaxf(mx_hi, __shfl_xor_sync(0xffffffffu, mx_hi, o));
        }
        float sum_lo = 0.f, sum_hi = 0.f;
        #pragma unroll
        for (int t = 0; t < 14; t++) {
            c[t][0] = __expf(c[t][0] - mx_lo); sum_lo += c[t][0];
            c[t][1] = __expf(c[t][1] - mx_lo); sum_lo += c[t][1];
            c[t][2] = __expf(c[t][2] - mx_hi); sum_hi += c[t][2];
            c[t][3] = __expf(c[t][3] - mx_hi); sum_hi += c[t][3];
        }
        #pragma unroll
        for (int o = 1; o <= 2; o <<= 1) {
            sum_lo += __shfl_xor_sync(0xffffffffu, sum_lo, o);
            sum_hi += __shfl_xor_sync(0xffffffffu, sum_hi, o);
        }
        const float inv_lo = 1.f / sum_lo, inv_hi = 1.f / sum_hi;

        uint32_t ap[7][4];
        #pragma unroll
        for (int j = 0; j < 7; j++) {
            __half2 h;
            h = __floats2half2_rn(c[2*j][0]*inv_lo,   c[2*j][1]*inv_lo);   ap[j][0] = *(uint32_t*)&h;
            h = __floats2half2_rn(c[2*j][2]*inv_hi,   c[2*j][3]*inv_hi);   ap[j][1] = *(uint32_t*)&h;
            h = __floats2half2_rn(c[2*j+1][0]*inv_lo, c[2*j+1][1]*inv_lo); ap[j][2] = *(uint32_t*)&h;
            h = __floats2half2_rn(c[2*j+1][2]*inv_hi, c[2*j+1][3]*inv_hi); ap[j][3] = *(uint32_t*)&h;
        }

        float c2[8][4];
        #pragma unroll
        for (int t = 0; t < 8; t++)
            #pragma unroll
            for (int q = 0; q < 4; q++) c2[t][q] = 0.f;

        #pragma unroll
        for (int j = 0; j < 7; j++) {
            int vrow = j*16 + l7 + 8*((lane>>3)&1);
            uint32_t vbase = vb + (uint32_t)(vrow * 128);
            #pragma unroll
            for (int g = 0; g < 4; g++) {
                uint32_t bb[4];
                ldsm4t(bb, vbase + (uint32_t)((((2*g) + (lane>>4)) ^ (vrow & 7)) << 4));
                MMA_F16(c2[2*g],   ap[j], bb[0], bb[1]);
                MMA_F16(c2[2*g+1], ap[j], bb[2], bb[3]);
            }
        }

        if (r_lo < 98) {
            __half* op = out + (size_t)ts[r_lo]*256 + hoff;
            #pragma unroll
            for (int t2 = 0; t2 < 8; t2++) {
                __half2 h = __floats2half2_rn(c2[t2][0], c2[t2][1]);
                *(__half2*)(op + t2*8 + mcol) = h;
            }
        }
        if (r_hi < 98) {
            __half* op = out + (size_t)ts[r_hi]*256 + hoff;
            #pragma unroll
            for (int t2 = 0; t2 < 8; t2++) {
                __half2 h = __floats2half2_rn(c2[t2][2], c2[t2][3]);
                *(__half2*)(op + t2*8 + mcol) = h;
            }
        }
    }
}

// ---------------- fp16 implicit-GEMM conv (R11-proven: M=128, 3-stage ring) ----------
__global__ __launch_bounds__(256, 2) void conv_mma_kernel(
    const __half* __restrict__ Xin, const __half* __restrict__ w2,
    const float* __restrict__ bias, const float* __restrict__ res,
    float* __restrict__ outN, __half* __restrict__ outX, int leaky)
{
    extern __shared__ __align__(16) char dsm[];
    __shared__ float sbias[128];

    const int tid = threadIdx.x, lane = tid & 31, wid = tid >> 5;
    const int wm = wid & 3, wn = wid >> 2;
    const int bx = blockIdx.x;
    const int b = bx / 196;
    const int spb = (bx % 196) * 128;

    if (tid < 128) sbias[tid] = bias[tid];

    const int mrow = tid >> 1;
    const int q0 = (tid & 1) * 4;
    int sp_c = spb + mrow;
    int d_c = sp_c / 3136; int r_c = sp_c - d_c*3136; int h_c = r_c / 56, w_c = r_c - h_c*56;
    const int padrow = d_c*PDH + h_c*58 + w_c;
    const __half* XinB = Xin + (size_t)b * PAD_SP * 128;
    const uint32_t sb = smem_u32(dsm);
    const uint32_t dst = sb + (uint32_t)mrow*128u;
    FragCtx f = make_frag_ctx(lane, wm, wn);

    float c[2][8][4];
    #pragma unroll
    for (int t = 0; t < 2; t++)
        #pragma unroll
        for (int j = 0; j < 8; j++)
            #pragma unroll
            for (int q = 0; q < 4; q++) c[t][j][q] = 0.f;

    const int NST = 54;
    auto load_st = [&](int s) {
        int tap = s >> 1, kh64 = (s & 1) * 64;
        int kd = tap / 9; int rem = tap - kd*9; int kh = rem / 3, kw = rem - kh*3;
        int toff = kd*PDH + kh*58 + kw;
        uint32_t base = (uint32_t)(s % 3) * 32768u;
        const __half* ga = XinB + (size_t)(padrow + toff)*128 + kh64;
        const __half* gb = w2 + ((size_t)tap*128 + mrow)*128 + kh64;
        #pragma unroll
        for (int q = q0; q < q0 + 4; q++) {
            uint32_t sw = (uint32_t)((q ^ (mrow & 7)) << 4);
            cp16(dst + base + sw, ga + q*8);
            cp16(dst + base + 16384u + sw, gb + q*8);
        }
    };
    load_st(0); CP_COMMIT();
    load_st(1); CP_COMMIT();
    for (int k = 0; k < NST; k++) {
        CP_WAIT1();
        __syncthreads();
        if (k + 2 < NST) load_st(k + 2);
        CP_COMMIT();
        uint32_t Ab = sb + (uint32_t)(k % 3)*32768u;
        mma_stage(Ab, Ab + 16384u, f, c);
    }
    __syncthreads();

    float* Cb = (float*)dsm;   // 128 x 132
    const int r0 = lane >> 2, c0 = lane & 3;
    #pragma unroll
    for (int t = 0; t < 2; t++) {
        int row = wm*32 + t*16 + r0;
        #pragma unroll
        for (int t2 = 0; t2 < 8; t2++) {
            int col = wn*64 + t2*8 + (c0 << 1);
            float b0s = sbias[col], b1s = sbias[col+1];
            float v0 = c[t][t2][0] + b0s;
            float v1 = c[t][t2][1] + b1s;
            float v2 = c[t][t2][2] + b0s;
            float v3 = c[t][t2][3] + b1s;
            if (leaky) {
                v0 = (v0 >= 0.f) ? v0 : 0.01f*v0;
                v1 = (v1 >= 0.f) ? v1 : 0.01f*v1;
                v2 = (v2 >= 0.f) ? v2 : 0.01f*v2;
                v3 = (v3 >= 0.f) ? v3 : 0.01f*v3;
            }
            Cb[row*132 + col]       = v0;
            Cb[row*132 + col + 1]   = v1;
            Cb[(row+8)*132 + col]   = v2;
            Cb[(row+8)*132 + col+1] = v3;
        }
    }
    __syncthreads();

    if (res) {
        int co = tid >> 1, mh = (tid & 1) << 6;
        const float* rp = res + (size_t)b*256*SP + (size_t)co*SP + spb + mh;
        #pragma unroll
        for (int j4 = 0; j4 < 16; j4++) {
            float4 r4 = *(const float4*)(rp + j4*4);
            Cb[(mh + j4*4 + 0)*132 + co] += r4.x;
            Cb[(mh + j4*4 + 1)*132 + co] += r4.y;
            Cb[(mh + j4*4 + 2)*132 + co] += r4.z;
            Cb[(mh + j4*4 + 3)*132 + co] += r4.w;
        }
        __syncthreads();
    }

    if (outX) {
        int m = tid >> 1, ch = (tid & 1) << 6;
        int sp = spb + m; int d = sp / 3136; int r = sp - d*3136; int h = r / 56, w = r - h*56;
        size_t po = (size_t)(d+1)*PDH + (size_t)(h+1)*58 + (w+1);
        __half* xp = outX + ((size_t)b*PAD_SP + po)*128 + ch;
        #pragma unroll
        for (int j8 = 0; j8 < 8; j8++) {
            const float* p = &Cb[m*132 + ch + j8*8];
            __half2 h0 = __floats2half2_rn(p[0], p[1]);
            __half2 h1 = __floats2half2_rn(p[2], p[3]);
            __half2 h2 = __floats2half2_rn(p[4], p[5]);
            __half2 h3 = __floats2half2_rn(p[6], p[7]);
            uint4 u;
            u.x = *(uint32_t*)&h0; u.y = *(uint32_t*)&h1;
            u.z = *(uint32_t*)&h2; u.w = *(uint32_t*)&h3;
            *(uint4*)(xp + j8*8) = u;
        }
    }
    if (outN) {
        int co = tid >> 1, mh = (tid & 1) << 6;
        float* op = outN + (size_t)b*256*SP + (size_t)co*SP + spb + mh;
        #pragma unroll
        for (int j4 = 0; j4 < 16; j4++) {
            float4 o;
            o.x = Cb[(mh + j4*4 + 0)*132 + co];
            o.y = Cb[(mh + j4*4 + 1)*132 + co];
            o.z = Cb[(mh + j4*4 + 2)*132 + co];
            o.w = Cb[(mh + j4*4 + 3)*132 + co];
            *(float4*)(op + j4*4) = o;
        }
    }
}

// ---------------- launcher ----------------
extern "C" void kernel_launch(void* const* d_in, const int* in_sizes, int n_in,
                              void* d_out, int out_size)
{
    (void)in_sizes; (void)n_in; (void)out_size;
    const float* input  = (const float*)d_in[0];
    const float* n1w    = (const float*)d_in[1];
    const float* n1b    = (const float*)d_in[2];
    const float* n2w    = (const float*)d_in[3];
    const float* n2b    = (const float*)d_in[4];
    const float* wqkv   = (const float*)d_in[5];
    const float* wprojw = (const float*)d_in[6];
    const float* wprojb = (const float*)d_in[7];
    const float* wbias  = (const float*)d_in[8];
    const float* gqkv   = (const float*)d_in[9];
    const float* gprojw = (const float*)d_in[10];
    const float* gprojb = (const float*)d_in[11];
    const float* gbias  = (const float*)d_in[12];
    const float* f1c1w  = (const float*)d_in[13];
    const float* f1c1b  = (const float*)d_in[14];
    const float* f1c2w  = (const float*)d_in[15];
    const float* f1c2b  = (const float*)d_in[16];
    const float* g1c1w  = (const float*)d_in[17];
    const float* g1c1b  = (const float*)d_in[18];
    const float* g1c2w  = (const float*)d_in[19];
    const float* g1c2b  = (const float*)d_in[20];
    float* out = (float*)d_out;

    __half *xh, *qkvh, *atnh, *xwh, *Xa, *Xb, *w2h, *wqkvh, *gqkvh, *wprjh, *gprjh, *bmat;
    float *s;
    cudaGetSymbolAddress((void**)&xh,    g_xh);
    cudaGetSymbolAddress((void**)&qkvh,  g_qkvh);
    cudaGetSymbolAddress((void**)&atnh,  g_atnh);
    cudaGetSymbolAddress((void**)&xwh,   g_xwh);
    cudaGetSymbolAddress((void**)&s,     g_s);
    cudaGetSymbolAddress((void**)&Xa,    g_Xa);
    cudaGetSymbolAddress((void**)&Xb,    g_Xb);
    cudaGetSymbolAddress((void**)&w2h,   g_w2h);
    cudaGetSymbolAddress((void**)&wqkvh, g_wqkvh);
    cudaGetSymbolAddress((void**)&gqkvh, g_gqkvh);
    cudaGetSymbolAddress((void**)&wprjh, g_wprjh);
    cudaGetSymbolAddress((void**)&gprjh, g_gprjh);
    cudaGetSymbolAddress((void**)&bmat,  g_bmat);

    const int TSMEM = 3 * 32768;
    cudaFuncSetAttribute(hgemm_kernel,      cudaFuncAttributeMaxDynamicSharedMemorySize, TSMEM);
    cudaFuncSetAttribute(hgemm_fuse_kernel, cudaFuncAttributeMaxDynamicSharedMemorySize, TSMEM);
    cudaFuncSetAttribute(conv_mma_kernel,   cudaFuncAttributeMaxDynamicSharedMemorySize, TSMEM);

    // prep + LN1 in one launch
    prep_kernel<<<11200, 256>>>(wqkv, gqkv, wprojw, gprojw,
                                f1c1w, f1c2w, g1c1w, g1c2w, wbias, gbias,
                                wqkvh, gqkvh, wprjh, gprjh, w2h, bmat,
                                input, n1w, n1b, xh);

    // window attention block
    hgemm_kernel<<<dim3(6, 392), 256, TSMEM>>>(xh, wqkvh, nullptr, qkvh, 768);
    attn_mma_kernel<<<dim3(512, 4), 256>>>(qkvh, bmat, atnh, 0);
    hgemm_kernel<<<dim3(2, 392), 256, TSMEM>>>(atnh, wprjh, wprojb, xwh, 256);
    // grid attention block
    ln_row_kernel<<<6272, 256>>>(xwh, n2w, n2b, xh);
    hgemm_kernel<<<dim3(6, 392), 256, TSMEM>>>(xh, gqkvh, nullptr, qkvh, 768);
    attn_mma_kernel<<<dim3(512, 4), 256>>>(qkvh, bmat + (size_t)4*128*112, atnh, 1);
    hgemm_fuse_kernel<<<dim3(2, 392), 256, TSMEM>>>(atnh, gprjh, gprojb, xwh, input, s, Xa);

    // conv chain (R11-proven config)
    conv_mma_kernel<<<392, 256, TSMEM>>>(Xa, w2h,            f1c1b, nullptr, nullptr, Xb, 1);
    conv_mma_kernel<<<392, 256, TSMEM>>>(Xb, w2h + W2SZ,     f1c2b, s, out, Xa, 0);
    conv_mma_kernel<<<392, 256, TSMEM>>>(Xa, w2h + 2*W2SZ,   g1c1b, nullptr, nullptr, Xb, 1);
    conv_mma_kernel<<<392, 256, TSMEM>>>(Xb, w2h + 3*W2SZ,   g1c2b, s + (size_t)128*SP,
                                         out + (size_t)128*SP, nullptr, 0);
}

// round 16
// speedup vs baseline: 1.4735x; 1.0002x over previous
#include <cuda_runtime.h>
#include <cuda_fp16.h>
#include <cstdint>
#include <cstddef>

// ---------------- problem constants ----------------
#define SP    25088          // 8*56*56
#define T_TOK 50176          // 2*SP
#define NTOK  98
#define SCALE_Q 0.125f
#define PAD_SP 33640         // 10*58*58
#define PDH    3364          // 58*58
#define W2SZ  (27*128*128)
#define BMSZ  65536          // per-attn bias matrix halves: 4*128*4*16*2

// ---------------- scratch ----------------
__device__ __half g_xh  [(size_t)T_TOK*256];
__device__ __half g_qkvh[(size_t)T_TOK*768];
__device__ __half g_atnh[(size_t)T_TOK*256];
__device__ __half g_xwh [(size_t)T_TOK*256];      // window-attn output, fp16
__device__ float  g_s   [(size_t)T_TOK*256];
__device__ __half g_Xa  [(size_t)2*PAD_SP*128];   // zero-init padding stays zero
__device__ __half g_Xb  [(size_t)2*PAD_SP*128];
__device__ __half g_w2h [(size_t)4*W2SZ];         // 4 conv weights [tap][co][ci]
__device__ __half g_wqkvh[768*256];
__device__ __half g_gqkvh[768*256];
__device__ __half g_wprjh[256*256];
__device__ __half g_gprjh[256*256];
__device__ __half g_bmat[(size_t)2*BMSZ];         // frag-major bias [attn][head][r][c0][t16][2]

// ---------------- PTX helpers (sm_80-baseline only) ----------------
__device__ __forceinline__ uint32_t smem_u32(const void* p) {
    uint32_t a;
    asm("{ .reg .u64 t; cvta.to.shared.u64 t, %1; cvt.u32.u64 %0, t; }" : "=r"(a) : "l"(p));
    return a;
}
__device__ __forceinline__ void cp16(uint32_t s, const void* g) {
    asm volatile("cp.async.cg.shared.global [%0], [%1], 16;" :: "r"(s), "l"(g));
}
#define CP_COMMIT() asm volatile("cp.async.commit_group;" ::: "memory")
#define CP_WAIT1()  asm volatile("cp.async.wait_group 1;"  ::: "memory")

__device__ __forceinline__ void ldsm4(uint32_t* r, uint32_t a) {
    asm volatile("ldmatrix.sync.aligned.m8n8.x4.shared.b16 {%0,%1,%2,%3}, [%4];"
        : "=r"(r[0]), "=r"(r[1]), "=r"(r[2]), "=r"(r[3]) : "r"(a));
}
__device__ __forceinline__ void ldsm4t(uint32_t* r, uint32_t a) {
    asm volatile("ldmatrix.sync.aligned.m8n8.x4.trans.shared.b16 {%0,%1,%2,%3}, [%4];"
        : "=r"(r[0]), "=r"(r[1]), "=r"(r[2]), "=r"(r[3]) : "r"(a));
}
#define MMA_F16(c, a, b0, b1) \
    asm volatile("mma.sync.aligned.m16n8k16.row.col.f32.f16.f16.f32 " \
        "{%0,%1,%2,%3}, {%4,%5,%6,%7}, {%8,%9}, {%0,%1,%2,%3};" \
        : "+f"((c)[0]), "+f"((c)[1]), "+f"((c)[2]), "+f"((c)[3]) \
        : "r"((a)[0]), "r"((a)[1]), "r"((a)[2]), "r"((a)[3]), "r"(b0), "r"(b1))

// ---------------- weight/bias prep + LN1, ONE kernel ----------------
__global__ __launch_bounds__(256) void prep_kernel(
    const float* __restrict__ wqkv, const float* __restrict__ gqkv,
    const float* __restrict__ wprj, const float* __restrict__ gprj,
    const float* __restrict__ c1w, const float* __restrict__ c2w,
    const float* __restrict__ c3w, const float* __restrict__ c4w,
    const float* __restrict__ wbias, const float* __restrict__ gbias,
    __half* __restrict__ wqkvh, __half* __restrict__ gqkvh,
    __half* __restrict__ wprjh, __half* __restrict__ gprjh,
    __half* __restrict__ w2h, __half* __restrict__ bmat,
    const float* __restrict__ in, const float* __restrict__ n1w,
    const float* __restrict__ n1b, __half* __restrict__ xh)
{
    __shared__ float s[28][257];
    int bx = blockIdx.x, tid = threadIdx.x;
    if (bx < 1536) {                       // qkv weights f2h
        int j = (bx >= 768) ? (bx - 768) : bx;
        const float* sp = (bx < 768) ? wqkv : gqkv;
        __half* d = (bx < 768) ? wqkvh : gqkvh;
        int i = j*256 + tid;
        d[i] = __float2half_rn(sp[i]);
    } else if (bx < 2048) {                // proj weights f2h
        const float* sp = (bx < 1792) ? wprj : gprj;
        __half* d = (bx < 1792) ? wprjh : gprjh;
        int j = bx - 1536; if (j >= 256) j -= 256;
        int i = j*256 + tid;
        d[i] = __float2half_rn(sp[i]);
    } else if (bx < 8960) {                // conv weight transform
        int seg = (bx - 2048) / 1728;
        const float* w = (seg == 0) ? c1w : (seg == 1) ? c2w : (seg == 2) ? c3w : c4w;
        __half* o = w2h + (size_t)seg * W2SZ;
        int i = ((bx - 2048) % 1728)*256 + tid;
        int ci = i & 127; int r = i >> 7; int co = r & 127; int tap = r >> 7;
        o[i] = __float2half_rn(w[(co*128 + ci)*27 + tap]);
    } else if (bx < 9472) {                // bias matrices, frag-major: 2 x 256 blocks
        int seg = (bx - 8960) >> 8;
        const float* bt = seg ? gbias : wbias;
        __half* bm = bmat + (size_t)seg * BMSZ;
        int i = ((bx - 8960) & 255)*256 + tid;     // i in [0, 65536)
        // i = (((head*128 + r)*4 + c0)*16 + t)*2 + j
        int j = i & 1; int t = (i >> 1) & 15; int c0 = (i >> 5) & 3;
        int r = (i >> 7) & 127; int head = i >> 14;
        int m = t*8 + c0*2 + j;
        float v = 0.f;
        if (r < 98 && t < 14) {
            if (m >= 98) v = -30000.f;
            else {
                int pd_r = r/49; int rr = r - pd_r*49; int ph_r = rr/7, pw_r = rr - ph_r*7;
                int pd_m = m/49; int mm = m - pd_m*49; int ph_m = mm/7, pw_m = mm - ph_m*7;
                int rpi = ((pd_r - pd_m + 1)*13 + (ph_r - ph_m + 6))*13 + (pw_r - pw_m + 6);
                v = bt[rpi*4 + head];
            }
        }
        bm[i] = __float2half_rn(v);
    } else {                               // LN1 (NCDHW -> token-major half)
        int j = bx - 9472;
        int wt = j & 1; int tmp = j >> 1;
        int h = tmp % 56; tmp /= 56;
        int d = tmp & 7; int bb = tmp >> 3;
        int w0 = wt * 28;
        size_t sp0 = ((size_t)d*56 + h)*56 + w0;
        const float* ib = in + (size_t)bb*256*SP + sp0;
        for (int i = tid; i < 28*256; i += 256) {
            int c = i / 28, ww_ = i - c*28;
            s[ww_][c] = ib[(size_t)c*SP + ww_];
        }
        __syncthreads();
        int warp = tid >> 5, lane = tid & 31;
        for (int tk = warp; tk < 28; tk += 8) {
            float s1 = 0.f, s2 = 0.f;
            #pragma unroll
            for (int q = 0; q < 8; q++) { float v = s[tk][lane + (q<<5)]; s1 += v; s2 += v*v; }
            #pragma unroll
            for (int o = 16; o; o >>= 1) {
                s1 += __shfl_xor_sync(0xffffffffu, s1, o);
                s2 += __shfl_xor_sync(0xffffffffu, s2, o);
            }
            float m = s1 * (1.f/256.f);
            float var = s2 * (1.f/256.f) - m*m;
            float iv = rsqrtf(var + 1e-5f);
            size_t t = (size_t)bb*SP + sp0 + tk;
            __half* orow = xh + t*256;
            #pragma unroll
            for (int q = 0; q < 8; q++) {
                int c = lane + (q<<5);
                orow[c] = __float2half_rn((s[tk][c] - m) * iv * n1w[c] + n1b[c]);
            }
        }
    }
}

// ---------------- LN2: half in, half out, vectorized ----------------
__global__ __launch_bounds__(256) void ln_row_kernel(
    const __half* __restrict__ in, const float* __restrict__ w,
    const float* __restrict__ b, __half* __restrict__ out)
{
    int t = blockIdx.x*8 + (threadIdx.x >> 5);
    int lane = threadIdx.x & 31;
    const __half* row = in + (size_t)t*256 + lane*8;
    uint4 u = *(const uint4*)row;
    const __half2* hp = (const __half2*)&u;
    float v[8];
    float s1 = 0.f, s2 = 0.f;
    #pragma unroll
    for (int j = 0; j < 4; j++) {
        float2 f = __half22float2(hp[j]);
        v[2*j] = f.x; v[2*j+1] = f.y;
        s1 += f.x + f.y; s2 += f.x*f.x + f.y*f.y;
    }
    #pragma unroll
    for (int o = 16; o; o >>= 1) {
        s1 += __shfl_xor_sync(0xffffffffu, s1, o);
        s2 += __shfl_xor_sync(0xffffffffu, s2, o);
    }
    float m = s1 * (1.f/256.f);
    float var = s2 * (1.f/256.f) - m*m;
    float iv = rsqrtf(var + 1e-5f);
    int c0 = lane*8;
    float4 w0 = *(const float4*)(w + c0);
    float4 w1 = *(const float4*)(w + c0 + 4);
    float4 b0 = *(const float4*)(b + c0);
    float4 b1 = *(const float4*)(b + c0 + 4);
    __half2 h0 = __floats2half2_rn((v[0]-m)*iv*w0.x + b0.x, (v[1]-m)*iv*w0.y + b0.y);
    __half2 h1 = __floats2half2_rn((v[2]-m)*iv*w0.z + b0.z, (v[3]-m)*iv*w0.w + b0.w);
    __half2 h2 = __floats2half2_rn((v[4]-m)*iv*w1.x + b1.x, (v[5]-m)*iv*w1.y + b1.y);
    __half2 h3 = __floats2half2_rn((v[6]-m)*iv*w1.z + b1.z, (v[7]-m)*iv*w1.w + b1.w);
    uint4 o;
    o.x = *(uint32_t*)&h0; o.y = *(uint32_t*)&h1;
    o.z = *(uint32_t*)&h2; o.w = *(uint32_t*)&h3;
    *(uint4*)(out + (size_t)t*256 + c0) = o;
}

// ---------------- shared warp-MMA stage: 128x128 tile, BK=64 ----------------
struct FragCtx {
    uint32_t aoff;
    uint32_t boff;
    uint32_t axor[4];
    uint32_t bxor[4];
};
__device__ __forceinline__ FragCtx make_frag_ctx(int lane, int wm, int wn) {
    FragCtx f;
    int l7 = lane & 7;
    f.aoff = (uint32_t)((wm*32 + ((lane>>3)&1)*8 + l7) * 128);
    f.boff = (uint32_t)((wn*64 + ((lane>>4)&1)*8 + l7) * 128);
    #pragma unroll
    for (int kk = 0; kk < 4; kk++) {
        f.axor[kk] = (uint32_t)(((2*kk + (lane>>4)) ^ l7) << 4);
        f.bxor[kk] = (uint32_t)(((2*kk + ((lane>>3)&1)) ^ l7) << 4);
    }
    return f;
}
__device__ __forceinline__ void mma_stage(uint32_t Ab, uint32_t Bb,
                                          const FragCtx& f, float c[2][8][4])
{
    #pragma unroll
    for (int kk = 0; kk < 4; kk++) {
        uint32_t a0[4], a1[4];
        ldsm4(a0, Ab + f.aoff + f.axor[kk]);
        ldsm4(a1, Ab + f.aoff + 2048u + f.axor[kk]);
        #pragma unroll
        for (int g = 0; g < 4; g++) {
            uint32_t bb[4];
            ldsm4(bb, Bb + f.boff + (uint32_t)g*2048u + f.bxor[kk]);
            MMA_F16(c[0][2*g],   a0, bb[0], bb[1]);
            MMA_F16(c[1][2*g],   a1, bb[0], bb[1]);
            MMA_F16(c[0][2*g+1], a0, bb[2], bb[3]);
            MMA_F16(c[1][2*g+1], a1, bb[2], bb[3]);
        }
    }
}

// ---------------- shared mainloop body for 128x128 @ K=256 GEMM ----------------
__device__ __forceinline__ void hgemm_mainloop(
    const __half* asrc, const __half* bsrc, uint32_t sb, uint32_t dst,
    int q0, int mrow, const FragCtx& f, float c[2][8][4])
{
    auto load_st = [&](int s) {
        uint32_t base = (uint32_t)(s % 3) * 32768u;
        #pragma unroll
        for (int q = q0; q < q0 + 4; q++) {
            uint32_t sw = (uint32_t)((q ^ (mrow & 7)) << 4);
            cp16(dst + base + sw, asrc + s*64 + q*8);
            cp16(dst + base + 16384u + sw, bsrc + s*64 + q*8);
        }
    };
    load_st(0); CP_COMMIT();
    load_st(1); CP_COMMIT();
    #pragma unroll
    for (int k = 0; k < 4; k++) {
        CP_WAIT1();
        __syncthreads();
        if (k + 2 < 4) load_st(k + 2);
        CP_COMMIT();
        uint32_t Ab = sb + (uint32_t)(k % 3)*32768u;
        mma_stage(Ab, Ab + 16384u, f, c);
    }
    __syncthreads();
}

// ---------------- fp16 GEMM (plain): C half (+bias) ----------------
__global__ __launch_bounds__(256, 2) void hgemm_kernel(
    const __half* __restrict__ A, const __half* __restrict__ B,
    const float* __restrict__ bias, __half* __restrict__ Cout, int N)
{
    extern __shared__ __align__(16) char dsm[];
    __shared__ float sbias[128];
    const int tid = threadIdx.x, lane = tid & 31, wid = tid >> 5;
    const int wm = wid & 3, wn = wid >> 2;
    const int bx = blockIdx.x, by = blockIdx.y;

    if (tid < 128) sbias[tid] = bias ? bias[bx*128 + tid] : 0.f;

    const int mrow = tid >> 1;
    const int q0 = (tid & 1) * 4;
    const uint32_t sb = smem_u32(dsm);
    FragCtx f = make_frag_ctx(lane, wm, wn);
    float c[2][8][4];
    #pragma unroll
    for (int t = 0; t < 2; t++)
        #pragma unroll
        for (int j = 0; j < 8; j++)
            #pragma unroll
            for (int q = 0; q < 4; q++) c[t][j][q] = 0.f;

    hgemm_mainloop(A + ((size_t)(by*128 + mrow))*256,
                   B + ((size_t)(bx*128 + mrow))*256,
                   sb, sb + (uint32_t)mrow*128u, q0, mrow, f, c);

    float* Cb = (float*)dsm;   // 128 x 132
    const int r0 = lane >> 2, c0 = lane & 3;
    #pragma unroll
    for (int t = 0; t < 2; t++) {
        int row = wm*32 + t*16 + r0;
        #pragma unroll
        for (int t2 = 0; t2 < 8; t2++) {
            int col = wn*64 + t2*8 + (c0 << 1);
            Cb[row*132 + col]       = c[t][t2][0] + sbias[col];
            Cb[row*132 + col + 1]   = c[t][t2][1] + sbias[col+1];
            Cb[(row+8)*132 + col]   = c[t][t2][2] + sbias[col];
            Cb[(row+8)*132 + col+1] = c[t][t2][3] + sbias[col+1];
        }
    }
    __syncthreads();

    const int m = tid >> 1, ch = (tid & 1) << 6;
    size_t goff = ((size_t)(by*128 + m))*N + bx*128 + ch;
    #pragma unroll
    for (int j8 = 0; j8 < 8; j8++) {
        const float* p = &Cb[m*132 + ch + j8*8];
        __half2 h0 = __floats2half2_rn(p[0], p[1]);
        __half2 h1 = __floats2half2_rn(p[2], p[3]);
        __half2 h2 = __floats2half2_rn(p[4], p[5]);
        __half2 h3 = __floats2half2_rn(p[6], p[7]);
        uint4 u;
        u.x = *(uint32_t*)&h0; u.y = *(uint32_t*)&h1;
        u.z = *(uint32_t*)&h2; u.w = *(uint32_t*)&h3;
        *(uint4*)(Cout + goff + j8*8) = u;
    }
}

// ---------------- fused grid-proj: y = A@B^T + bias + xw; s = input + y; Xa = half(s2)
__global__ __launch_bounds__(256, 2) void hgemm_fuse_kernel(
    const __half* __restrict__ A, const __half* __restrict__ B,
    const float* __restrict__ bias, const __half* __restrict__ xw,
    const float* __restrict__ input, float* __restrict__ s,
    __half* __restrict__ Xa)
{
    extern __shared__ __align__(16) char dsm[];
    __shared__ float sbias[128];
    const int tid = threadIdx.x, lane = tid & 31, wid = tid >> 5;
    const int wm = wid & 3, wn = wid >> 2;
    const int bx = blockIdx.x, by = blockIdx.y;

    if (tid < 128) sbias[tid] = bias[bx*128 + tid];

    const int mrow = tid >> 1;
    const int q0 = (tid & 1) * 4;
    const uint32_t sb = smem_u32(dsm);
    FragCtx f = make_frag_ctx(lane, wm, wn);
    float c[2][8][4];
    #pragma unroll
    for (int t = 0; t < 2; t++)
        #pragma unroll
        for (int j = 0; j < 8; j++)
            #pragma unroll
            for (int q = 0; q < 4; q++) c[t][j][q] = 0.f;

    hgemm_mainloop(A + ((size_t)(by*128 + mrow))*256,
                   B + ((size_t)(bx*128 + mrow))*256,
                   sb, sb + (uint32_t)mrow*128u, q0, mrow, f, c);

    float* Cb = (float*)dsm;   // 128 x 132, rows = tokens, cols = local chan
    const int r0 = lane >> 2, c0 = lane & 3;
    #pragma unroll
    for (int t = 0; t < 2; t++) {
        int row = wm*32 + t*16 + r0;
        #pragma unroll
        for (int t2 = 0; t2 < 8; t2++) {
            int col = wn*64 + t2*8 + (c0 << 1);
            Cb[row*132 + col]       = c[t][t2][0] + sbias[col];
            Cb[row*132 + col + 1]   = c[t][t2][1] + sbias[col+1];
            Cb[(row+8)*132 + col]   = c[t][t2][2] + sbias[col];
            Cb[(row+8)*132 + col+1] = c[t][t2][3] + sbias[col+1];
        }
    }
    __syncthreads();

    // phase A (token-major): y = Cb + xw  (xw fp16)
    const int m = tid >> 1, ch = (tid & 1) << 6;
    {
        size_t goff = ((size_t)(by*128 + m))*256 + bx*128 + ch;
        #pragma unroll
        for (int j8 = 0; j8 < 8; j8++) {
            uint4 u = *(const uint4*)(xw + goff + j8*8);
            const __half2* hp = (const __half2*)&u;
            float* p = &Cb[m*132 + ch + j8*8];
            #pragma unroll
            for (int q = 0; q < 4; q++) {
                float2 fv = __half22float2(hp[q]);
                p[2*q]   += fv.x;
                p[2*q+1] += fv.y;
            }
        }
    }
    __syncthreads();

    // phase B (chan-major, coalesced NCDHW): s = input + y; Cb <- s
    {
        const int co = tid >> 1, mh = (tid & 1) << 6;
        const int tok0 = by*128;
        const int b = tok0 / SP, sp0 = tok0 % SP;
        size_t gbase = (size_t)b*256*SP + (size_t)(bx*128 + co)*SP + sp0 + mh;
        #pragma unroll
        for (int j4 = 0; j4 < 16; j4++) {
            float4 iv = *(const float4*)(input + gbase + j4*4);
            float* p0 = &Cb[(mh + j4*4 + 0)*132 + co];
            float* p1 = &Cb[(mh + j4*4 + 1)*132 + co];
            float* p2 = &Cb[(mh + j4*4 + 2)*132 + co];
            float* p3 = &Cb[(mh + j4*4 + 3)*132 + co];
            float v0 = iv.x + *p0, v1 = iv.y + *p1, v2 = iv.z + *p2, v3 = iv.w + *p3;
            *p0 = v0; *p1 = v1; *p2 = v2; *p3 = v3;
            float4 o = make_float4(v0, v1, v2, v3);
            *(float4*)(s + gbase + j4*4) = o;
        }
    }
    __syncthreads();

    // phase C (token-major): Xa = half(s2) for channels 128..255 (bx==1)
    if (bx == 1) {
        const int tok = by*128 + m;
        const int b = tok / SP;
        int sp = tok % SP;
        int d = sp / 3136; int r = sp - d*3136; int h = r / 56, w = r - h*56;
        size_t po = (size_t)(d+1)*PDH + (size_t)(h+1)*58 + (w+1);
        __half* xp = Xa + ((size_t)b*PAD_SP + po)*128 + ch;
        #pragma unroll
        for (int j8 = 0; j8 < 8; j8++) {
            const float* p = &Cb[m*132 + ch + j8*8];
            __half2 h0 = __floats2half2_rn(p[0], p[1]);
            __half2 h1 = __floats2half2_rn(p[2], p[3]);
            __half2 h2 = __floats2half2_rn(p[4], p[5]);
            __half2 h3 = __floats2half2_rn(p[6], p[7]);
            uint4 u;
            u.x = *(uint32_t*)&h0; u.y = *(uint32_t*)&h1;
            u.z = *(uint32_t*)&h2; u.w = *(uint32_t*)&h3;
            *(uint4*)(xp + j8*8) = u;
        }
    }
}

// ---------------- tensor-core attention (frag-major fp16 bias, coalesced) ------------
__global__ __launch_bounds__(256, 3) void attn_mma_kernel(
    const __half* __restrict__ qkv, const __half* __restrict__ bmat,
    __half* __restrict__ out, int grid_mode)
{
    __shared__ __align__(16) __half Qs[112*64];
    __shared__ __align__(16) __half Ks[112*64];
    __shared__ __align__(16) __half Vs[112*64];
    __shared__ int ts[NTOK];

    const int tid = threadIdx.x, lane = tid & 31, warp = tid >> 5;
    const int wi = blockIdx.x, head = blockIdx.y;
    const int b = wi >> 8, wd = (wi>>6)&3, wh = (wi>>3)&7, ww = wi & 7;
    const int hoff = head << 6;

    if (tid < NTOK) {
        int pd = tid / 49; int r7 = tid - pd*49; int ph = r7 / 7, pw = r7 - ph*7;
        int d, h, w;
        if (grid_mode) { d = pd*4 + wd; h = ph*8 + wh; w = pw*8 + ww; }
        else           { d = wd*2 + pd; h = wh*7 + ph; w = ww*7 + pw; }
        ts[tid] = ((b*8 + d)*56 + h)*56 + w;
    }
    __syncthreads();

    {
        const int row = tid >> 1;
        const int cb = (tid & 1) * 4;
        const uint4 z4 = make_uint4(0,0,0,0);
        if (row < 112) {
            size_t base = (row < 98) ? ((size_t)ts[row]*768 + hoff) : 0;
            #pragma unroll
            for (int cc = 0; cc < 4; cc++) {
                int c = cb + cc;
                int sw8 = (c ^ (row & 7)) * 8;
                uint4 vq = z4, vk = z4, vv = z4;
                if (row < 98) {
                    vq = *(const uint4*)(qkv + base + c*8);
                    vk = *(const uint4*)(qkv + base + 256 + c*8);
                    vv = *(const uint4*)(qkv + base + 512 + c*8);
                }
                *(uint4*)(Qs + row*64 + sw8) = vq;
                *(uint4*)(Ks + row*64 + sw8) = vk;
                *(uint4*)(Vs + row*64 + sw8) = vv;
            }
        }
    }
    __syncthreads();

    if (warp < 7) {
        const uint32_t qb = smem_u32(Qs), kb = smem_u32(Ks), vb = smem_u32(Vs);
        const int l7 = lane & 7;

        float c[14][4];
        #pragma unroll
        for (int t = 0; t < 14; t++)
            #pragma unroll
            for (int q = 0; q < 4; q++) c[t][q] = 0.f;

        const uint32_t a_base = qb + (uint32_t)((warp*16 + ((lane>>3)&1)*8 + l7) * 128);
        const uint32_t b_rowo = (uint32_t)((((lane>>4)&1)*8 + l7) * 128);
        #pragma unroll
        for (int kk = 0; kk < 4; kk++) {
            uint32_t a[4];
            ldsm4(a, a_base + (uint32_t)(((2*kk + (lane>>4)) ^ l7) << 4));
            uint32_t bx_ = (uint32_t)(((2*kk + ((lane>>3)&1)) ^ l7) << 4);
            #pragma unroll
            for (int g = 0; g < 7; g++) {
                uint32_t bb[4];
                ldsm4(bb, kb + (uint32_t)(g*2048) + b_rowo + bx_);
                MMA_F16(c[2*g],   a, bb[0], bb[1]);
                MMA_F16(c[2*g+1], a, bb[2], bb[3]);
            }
        }

        const int r_lo = warp*16 + (lane >> 2);
        const int r_hi = r_lo + 8;
        const int mcol = (lane & 3) * 2;
        // frag-major bias: [head][r][c0][t16] half2, fully contiguous per thread
        const __half2* bm_lo = (const __half2*)(bmat
            + ((((size_t)head*128 + r_lo)*4 + (lane & 3))*16)*2);
        const __half2* bm_hi = bm_lo + 8*4*16;     // +8 rows
        float mx_lo = -1e30f, mx_hi = -1e30f;
        #pragma unroll
        for (int tc = 0; tc < 4; tc++) {
            uint4 ulo = *(const uint4*)(bm_lo + tc*4);
            uint4 uhi = *(const uint4*)(bm_hi + tc*4);
            const __half2* plo = (const __half2*)&ulo;
            const __half2* phi = (const __half2*)&uhi;
            const int tmax = (tc == 3) ? 2 : 4;
            #pragma unroll
            for (int tt = 0; tt < tmax; tt++) {
                int t = tc*4 + tt;
                float2 blo = __half22float2(plo[tt]);
                float2 bhi = __half22float2(phi[tt]);
                c[t][0] = fmaf(c[t][0], SCALE_Q, blo.x);
                c[t][1] = fmaf(c[t][1], SCALE_Q, blo.y);
                c[t][2] = fmaf(c[t][2], SCALE_Q, bhi.x);
                c[t][3] = fmaf(c[t][3], SCALE_Q, bhi.y);
                mx_lo = fmaxf(mx_lo, fmaxf(c[t][0], c[t][1]));
                mx_hi = fmaxf(mx_hi, fmaxf(c[t][2], c[t][3]));
            }
        }
        #pragma unroll
        for (int o = 1; o <= 2; o <<= 1) {
            mx_lo = fmaxf(mx_lo, __shfl_xor_sync(0xffffffffu, mx_lo, o));
            mx_hi = fmaxf(mx_hi, __shfl_xor_sync(0xffffffffu, mx_hi, o));
        }
        float sum_lo = 0.f, sum_hi = 0.f;
        #pragma unroll
        for (int t = 0; t < 14; t++) {
            c[t][0] = __expf(c[t][0] - mx_lo); sum_lo += c[t][0];
            c[t][1] = __expf(c[t][1] - mx_lo); sum_lo += c[t][1];
            c[t][2] = __expf(c[t][2] - mx_hi); sum_hi += c[t][2];
            c[t][3] = __expf(c[t][3] - mx_hi); sum_hi += c[t][3];
        }
        #pragma unroll
        for (int o = 1; o <= 2; o <<= 1) {
            sum_lo += __shfl_xor_sync(0xffffffffu, sum_lo, o);
            sum_hi += __shfl_xor_sync(0xffffffffu, sum_hi, o);
        }
        const float inv_lo = 1.f / sum_lo, inv_hi = 1.f / sum_hi;

        uint32_t ap[7][4];
        #pragma unroll
        for (int j = 0; j < 7; j++) {
            __half2 h;
            h = __floats2half2_rn(c[2*j][0]*inv_lo,   c[2*j][1]*inv_lo);   ap[j][0] = *(uint32_t*)&h;
            h = __floats2half2_rn(c[2*j][2]*inv_hi,   c[2*j][3]*inv_hi);   ap[j][1] = *(uint32_t*)&h;
            h = __floats2half2_rn(c[2*j+1][0]*inv_lo, c[2*j+1][1]*inv_lo); ap[j][2] = *(uint32_t*)&h;
            h = __floats2half2_rn(c[2*j+1][2]*inv_hi, c[2*j+1][3]*inv_hi); ap[j][3] = *(uint32_t*)&h;
        }

        float c2[8][4];
        #pragma unroll
        for (int t = 0; t < 8; t++)
            #pragma unroll
            for (int q = 0; q < 4; q++) c2[t][q] = 0.f;

        #pragma unroll
        for (int j = 0; j < 7; j++) {
            int vrow = j*16 + l7 + 8*((lane>>3)&1);
            uint32_t vbase = vb + (uint32_t)(vrow * 128);
            #pragma unroll
            for (int g = 0; g < 4; g++) {
                uint32_t bb[4];
                ldsm4t(bb, vbase + (uint32_t)((((2*g) + (lane>>4)) ^ (vrow & 7)) << 4));
                MMA_F16(c2[2*g],   ap[j], bb[0], bb[1]);
                MMA_F16(c2[2*g+1], ap[j], bb[2], bb[3]);
            }
        }

        if (r_lo < 98) {
            __half* op = out + (size_t)ts[r_lo]*256 + hoff;
            #pragma unroll
            for (int t2 = 0; t2 < 8; t2++) {
                __half2 h = __floats2half2_rn(c2[t2][0], c2[t2][1]);
                *(__half2*)(op + t2*8 + mcol) = h;
            }
        }
        if (r_hi < 98) {
            __half* op = out + (size_t)ts[r_hi]*256 + hoff;
            #pragma unroll
            for (int t2 = 0; t2 < 8; t2++) {
                __half2 h = __floats2half2_rn(c2[t2][2], c2[t2][3]);
                *(__half2*)(op + t2*8 + mcol) = h;
            }
        }
    }
}

// ---------------- fp16 implicit-GEMM conv (R11-proven: M=128, 3-stage ring) ----------
__global__ __launch_bounds__(256, 2) void conv_mma_kernel(
    const __half* __restrict__ Xin, const __half* __restrict__ w2,
    const float* __restrict__ bias, const float* __restrict__ res,
    float* __restrict__ outN, __half* __restrict__ outX, int leaky)
{
    extern __shared__ __align__(16) char dsm[];
    __shared__ float sbias[128];

    const int tid = threadIdx.x, lane = tid & 31, wid = tid >> 5;
    const int wm = wid & 3, wn = wid >> 2;
    const int bx = blockIdx.x;
    const int b = bx / 196;
    const int spb = (bx % 196) * 128;

    if (tid < 128) sbias[tid] = bias[tid];

    const int mrow = tid >> 1;
    const int q0 = (tid & 1) * 4;
    int sp_c = spb + mrow;
    int d_c = sp_c / 3136; int r_c = sp_c - d_c*3136; int h_c = r_c / 56, w_c = r_c - h_c*56;
    const int padrow = d_c*PDH + h_c*58 + w_c;
    const __half* XinB = Xin + (size_t)b * PAD_SP * 128;
    const uint32_t sb = smem_u32(dsm);
    const uint32_t dst = sb + (uint32_t)mrow*128u;
    FragCtx f = make_frag_ctx(lane, wm, wn);

    float c[2][8][4];
    #pragma unroll
    for (int t = 0; t < 2; t++)
        #pragma unroll
        for (int j = 0; j < 8; j++)
            #pragma unroll
            for (int q = 0; q < 4; q++) c[t][j][q] = 0.f;

    const int NST = 54;
    auto load_st = [&](int s) {
        int tap = s >> 1, kh64 = (s & 1) * 64;
        int kd = tap / 9; int rem = tap - kd*9; int kh = rem / 3, kw = rem - kh*3;
        int toff = kd*PDH + kh*58 + kw;
        uint32_t base = (uint32_t)(s % 3) * 32768u;
        const __half* ga = XinB + (size_t)(padrow + toff)*128 + kh64;
        const __half* gb = w2 + ((size_t)tap*128 + mrow)*128 + kh64;
        #pragma unroll
        for (int q = q0; q < q0 + 4; q++) {
            uint32_t sw = (uint32_t)((q ^ (mrow & 7)) << 4);
            cp16(dst + base + sw, ga + q*8);
            cp16(dst + base + 16384u + sw, gb + q*8);
        }
    };
    load_st(0); CP_COMMIT();
    load_st(1); CP_COMMIT();
    for (int k = 0; k < NST; k++) {
        CP_WAIT1();
        __syncthreads();
        if (k + 2 < NST) load_st(k + 2);
        CP_COMMIT();
        uint32_t Ab = sb + (uint32_t)(k % 3)*32768u;
        mma_stage(Ab, Ab + 16384u, f, c);
    }
    __syncthreads();

    float* Cb = (float*)dsm;   // 128 x 132
    const int r0 = lane >> 2, c0 = lane & 3;
    #pragma unroll
    for (int t = 0; t < 2; t++) {
        int row = wm*32 + t*16 + r0;
        #pragma unroll
        for (int t2 = 0; t2 < 8; t2++) {
            int col = wn*64 + t2*8 + (c0 << 1);
            float b0s = sbias[col], b1s = sbias[col+1];
            float v0 = c[t][t2][0] + b0s;
            float v1 = c[t][t2][1] + b1s;
            float v2 = c[t][t2][2] + b0s;
            float v3 = c[t][t2][3] + b1s;
            if (leaky) {
                v0 = (v0 >= 0.f) ? v0 : 0.01f*v0;
                v1 = (v1 >= 0.f) ? v1 : 0.01f*v1;
                v2 = (v2 >= 0.f) ? v2 : 0.01f*v2;
                v3 = (v3 >= 0.f) ? v3 : 0.01f*v3;
            }
            Cb[row*132 + col]       = v0;
            Cb[row*132 + col + 1]   = v1;
            Cb[(row+8)*132 + col]   = v2;
            Cb[(row+8)*132 + col+1] = v3;
        }
    }
    __syncthreads();

    if (res) {
        int co = tid >> 1, mh = (tid & 1) << 6;
        const float* rp = res + (size_t)b*256*SP + (size_t)co*SP + spb + mh;
        #pragma unroll
        for (int j4 = 0; j4 < 16; j4++) {
            float4 r4 = *(const float4*)(rp + j4*4);
            Cb[(mh + j4*4 + 0)*132 + co] += r4.x;
            Cb[(mh + j4*4 + 1)*132 + co] += r4.y;
            Cb[(mh + j4*4 + 2)*132 + co] += r4.z;
            Cb[(mh + j4*4 + 3)*132 + co] += r4.w;
        }
        __syncthreads();
    }

    if (outX) {
        int m = tid >> 1, ch = (tid & 1) << 6;
        int sp = spb + m; int d = sp / 3136; int r = sp - d*3136; int h = r / 56, w = r - h*56;
        size_t po = (size_t)(d+1)*PDH + (size_t)(h+1)*58 + (w+1);
        __half* xp = outX + ((size_t)b*PAD_SP + po)*128 + ch;
        #pragma unroll
        for (int j8 = 0; j8 < 8; j8++) {
            const float* p = &Cb[m*132 + ch + j8*8];
            __half2 h0 = __floats2half2_rn(p[0], p[1]);
            __half2 h1 = __floats2half2_rn(p[2], p[3]);
            __half2 h2 = __floats2half2_rn(p[4], p[5]);
            __half2 h3 = __floats2half2_rn(p[6], p[7]);
            uint4 u;
            u.x = *(uint32_t*)&h0; u.y = *(uint32_t*)&h1;
            u.z = *(uint32_t*)&h2; u.w = *(uint32_t*)&h3;
            *(uint4*)(xp + j8*8) = u;
        }
    }
    if (outN) {
        int co = tid >> 1, mh = (tid & 1) << 6;
        float* op = outN + (size_t)b*256*SP + (size_t)co*SP + spb + mh;
        #pragma unroll
        for (int j4 = 0; j4 < 16; j4++) {
            float4 o;
            o.x = Cb[(mh + j4*4 + 0)*132 + co];
            o.y = Cb[(mh + j4*4 + 1)*132 + co];
            o.z = Cb[(mh + j4*4 + 2)*132 + co];
            o.w = Cb[(mh + j4*4 + 3)*132 + co];
            *(float4*)(op + j4*4) = o;
        }
    }
}

// ---------------- launcher ----------------
extern "C" void kernel_launch(void* const* d_in, const int* in_sizes, int n_in,
                              void* d_out, int out_size)
{
    (void)in_sizes; (void)n_in; (void)out_size;
    const float* input  = (const float*)d_in[0];
    const float* n1w    = (const float*)d_in[1];
    const float* n1b    = (const float*)d_in[2];
    const float* n2w    = (const float*)d_in[3];
    const float* n2b    = (const float*)d_in[4];
    const float* wqkv   = (const float*)d_in[5];
    const float* wprojw = (const float*)d_in[6];
    const float* wprojb = (const float*)d_in[7];
    const float* wbias  = (const float*)d_in[8];
    const float* gqkv   = (const float*)d_in[9];
    const float* gprojw = (const float*)d_in[10];
    const float* gprojb = (const float*)d_in[11];
    const float* gbias  = (const float*)d_in[12];
    const float* f1c1w  = (const float*)d_in[13];
    const float* f1c1b  = (const float*)d_in[14];
    const float* f1c2w  = (const float*)d_in[15];
    const float* f1c2b  = (const float*)d_in[16];
    const float* g1c1w  = (const float*)d_in[17];
    const float* g1c1b  = (const float*)d_in[18];
    const float* g1c2w  = (const float*)d_in[19];
    const float* g1c2b  = (const float*)d_in[20];
    float* out = (float*)d_out;

    __half *xh, *qkvh, *atnh, *xwh, *Xa, *Xb, *w2h, *wqkvh, *gqkvh, *wprjh, *gprjh, *bmat;
    float *s;
    cudaGetSymbolAddress((void**)&xh,    g_xh);
    cudaGetSymbolAddress((void**)&qkvh,  g_qkvh);
    cudaGetSymbolAddress((void**)&atnh,  g_atnh);
    cudaGetSymbolAddress((void**)&xwh,   g_xwh);
    cudaGetSymbolAddress((void**)&s,     g_s);
    cudaGetSymbolAddress((void**)&Xa,    g_Xa);
    cudaGetSymbolAddress((void**)&Xb,    g_Xb);
    cudaGetSymbolAddress((void**)&w2h,   g_w2h);
    cudaGetSymbolAddress((void**)&wqkvh, g_wqkvh);
    cudaGetSymbolAddress((void**)&gqkvh, g_gqkvh);
    cudaGetSymbolAddress((void**)&wprjh, g_wprjh);
    cudaGetSymbolAddress((void**)&gprjh, g_gprjh);
    cudaGetSymbolAddress((void**)&bmat,  g_bmat);

    const int TSMEM = 3 * 32768;
    cudaFuncSetAttribute(hgemm_kernel,      cudaFuncAttributeMaxDynamicSharedMemorySize, TSMEM);
    cudaFuncSetAttribute(hgemm_fuse_kernel, cudaFuncAttributeMaxDynamicSharedMemorySize, TSMEM);
    cudaFuncSetAttribute(conv_mma_kernel,   cudaFuncAttributeMaxDynamicSharedMemorySize, TSMEM);

    // prep (weights + frag-major bias) + LN1 in one launch
    prep_kernel<<<11264, 256>>>(wqkv, gqkv, wprojw, gprojw,
                                f1c1w, f1c2w, g1c1w, g1c2w, wbias, gbias,
                                wqkvh, gqkvh, wprjh, gprjh, w2h, bmat,
                                input, n1w, n1b, xh);

    // window attention block
    hgemm_kernel<<<dim3(6, 392), 256, TSMEM>>>(xh, wqkvh, nullptr, qkvh, 768);
    attn_mma_kernel<<<dim3(512, 4), 256>>>(qkvh, bmat, atnh, 0);
    hgemm_kernel<<<dim3(2, 392), 256, TSMEM>>>(atnh, wprjh, wprojb, xwh, 256);
    // grid attention block
    ln_row_kernel<<<6272, 256>>>(xwh, n2w, n2b, xh);
    hgemm_kernel<<<dim3(6, 392), 256, TSMEM>>>(xh, gqkvh, nullptr, qkvh, 768);
    attn_mma_kernel<<<dim3(512, 4), 256>>>(qkvh, bmat + BMSZ, atnh, 1);
    hgemm_fuse_kernel<<<dim3(2, 392), 256, TSMEM>>>(atnh, gprjh, gprojb, xwh, input, s, Xa);

    // conv chain (R11-proven config)
    conv_mma_kernel<<<392, 256, TSMEM>>>(Xa, w2h,            f1c1b, nullptr, nullptr, Xb, 1);
    conv_mma_kernel<<<392, 256, TSMEM>>>(Xb, w2h + W2SZ,     f1c2b, s, out, Xa, 0);
    conv_mma_kernel<<<392, 256, TSMEM>>>(Xa, w2h + 2*W2SZ,   g1c1b, nullptr, nullptr, Xb, 1);
    conv_mma_kernel<<<392, 256, TSMEM>>>(Xb, w2h + 3*W2SZ,   g1c2b, s + (size_t)128*SP,
                                         out + (size_t)128*SP, nullptr, 0);
}

// round 17
// speedup vs baseline: 1.4977x; 1.0164x over previous
#include <cuda_runtime.h>
#include <cuda_fp16.h>
#include <cstdint>
#include <cstddef>

// ---------------- problem constants ----------------
#define SP    25088          // 8*56*56
#define T_TOK 50176          // 2*SP
#define NTOK  98
#define SCALE_Q 0.125f
#define PAD_SP 33640         // 10*58*58
#define PDH    3364          // 58*58
#define W2SZ  (27*128*128)
#define BMSZ  65536          // per-attn bias matrix halves: 4*128*4*16*2

// ---------------- scratch ----------------
__device__ __half g_xh  [(size_t)T_TOK*256];
__device__ __half g_qkvh[(size_t)T_TOK*768];
__device__ __half g_atnh[(size_t)T_TOK*256];
__device__ __half g_xwh [(size_t)T_TOK*256];      // window-attn output, fp16
__device__ __half g_s   [(size_t)T_TOK*256];      // s residual, fp16 (NCDHW)
__device__ __half g_Xa  [(size_t)2*PAD_SP*128];   // zero-init padding stays zero
__device__ __half g_Xb  [(size_t)2*PAD_SP*128];
__device__ __half g_w2h [(size_t)4*W2SZ];         // 4 conv weights [tap][co][ci]
__device__ __half g_wqkvh[768*256];
__device__ __half g_gqkvh[768*256];
__device__ __half g_wprjh[256*256];
__device__ __half g_gprjh[256*256];
__device__ __half g_bmat[(size_t)2*BMSZ];         // frag-major bias [attn][head][r][c0][t16][2]

// ---------------- PTX helpers (sm_80-baseline only) ----------------
__device__ __forceinline__ uint32_t smem_u32(const void* p) {
    uint32_t a;
    asm("{ .reg .u64 t; cvta.to.shared.u64 t, %1; cvt.u32.u64 %0, t; }" : "=r"(a) : "l"(p));
    return a;
}
__device__ __forceinline__ void cp16(uint32_t s, const void* g) {
    asm volatile("cp.async.cg.shared.global [%0], [%1], 16;" :: "r"(s), "l"(g));
}
#define CP_COMMIT() asm volatile("cp.async.commit_group;" ::: "memory")
#define CP_WAIT1()  asm volatile("cp.async.wait_group 1;"  ::: "memory")

__device__ __forceinline__ void ldsm4(uint32_t* r, uint32_t a) {
    asm volatile("ldmatrix.sync.aligned.m8n8.x4.shared.b16 {%0,%1,%2,%3}, [%4];"
        : "=r"(r[0]), "=r"(r[1]), "=r"(r[2]), "=r"(r[3]) : "r"(a));
}
__device__ __forceinline__ void ldsm4t(uint32_t* r, uint32_t a) {
    asm volatile("ldmatrix.sync.aligned.m8n8.x4.trans.shared.b16 {%0,%1,%2,%3}, [%4];"
        : "=r"(r[0]), "=r"(r[1]), "=r"(r[2]), "=r"(r[3]) : "r"(a));
}
#define MMA_F16(c, a, b0, b1) \
    asm volatile("mma.sync.aligned.m16n8k16.row.col.f32.f16.f16.f32 " \
        "{%0,%1,%2,%3}, {%4,%5,%6,%7}, {%8,%9}, {%0,%1,%2,%3};" \
        : "+f"((c)[0]), "+f"((c)[1]), "+f"((c)[2]), "+f"((c)[3]) \
        : "r"((a)[0]), "r"((a)[1]), "r"((a)[2]), "r"((a)[3]), "r"(b0), "r"(b1))

// ---------------- weight/bias prep + LN1, ONE kernel ----------------
// segments: [0,1536) qkv f2h | [1536,2048) proj f2h | [2048,2304) conv wT (smem transpose)
//           [2304,2816) bias matrices | [2816,4608) LN1
__global__ __launch_bounds__(256) void prep_kernel(
    const float* __restrict__ wqkv, const float* __restrict__ gqkv,
    const float* __restrict__ wprj, const float* __restrict__ gprj,
    const float* __restrict__ c1w, const float* __restrict__ c2w,
    const float* __restrict__ c3w, const float* __restrict__ c4w,
    const float* __restrict__ wbias, const float* __restrict__ gbias,
    __half* __restrict__ wqkvh, __half* __restrict__ gqkvh,
    __half* __restrict__ wprjh, __half* __restrict__ gprjh,
    __half* __restrict__ w2h, __half* __restrict__ bmat,
    const float* __restrict__ in, const float* __restrict__ n1w,
    const float* __restrict__ n1b, __half* __restrict__ xh)
{
    __shared__ float s[28][257];           // 28.8KB; also stages 6912 floats for conv wT
    int bx = blockIdx.x, tid = threadIdx.x;
    if (bx < 1536) {                       // qkv weights f2h
        int j = (bx >= 768) ? (bx - 768) : bx;
        const float* sp = (bx < 768) ? wqkv : gqkv;
        __half* d = (bx < 768) ? wqkvh : gqkvh;
        int i = j*256 + tid;
        d[i] = __float2half_rn(sp[i]);
    } else if (bx < 2048) {                // proj weights f2h
        const float* sp = (bx < 1792) ? wprj : gprj;
        __half* d = (bx < 1792) ? wprjh : gprjh;
        int j = bx - 1536; if (j >= 256) j -= 256;
        int i = j*256 + tid;
        d[i] = __float2half_rn(sp[i]);
    } else if (bx < 2304) {                // conv weight transform, coalesced (2 co per block)
        int seg = (bx - 2048) >> 6;
        int p = (bx - 2048) & 63;
        const float* w = (seg == 0) ? c1w : (seg == 1) ? c2w : (seg == 2) ? c3w : c4w;
        float* raw = &s[0][0];
        const float* src = w + (size_t)(2*p)*3456;
        for (int i = tid; i < 6912; i += 256) raw[i] = src[i];
        __syncthreads();
        __half* o = w2h + (size_t)seg * W2SZ + 2*p*128;
        for (int j = tid; j < 6912; j += 256) {
            int tap = j >> 8; int rem = j & 255; int col = rem >> 7; int ci = rem & 127;
            o[(size_t)tap*16384 + col*128 + ci] =
                __float2half_rn(raw[col*3456 + ci*27 + tap]);
        }
    } else if (bx < 2816) {                // bias matrices, frag-major: 2 x 256 blocks
        int seg = (bx - 2304) >> 8;
        const float* bt = seg ? gbias : wbias;
        __half* bm = bmat + (size_t)seg * BMSZ;
        int i = ((bx - 2304) & 255)*256 + tid;     // i in [0, 65536)
        int j = i & 1; int t = (i >> 1) & 15; int c0 = (i >> 5) & 3;
        int r = (i >> 7) & 127; int head = i >> 14;
        int m = t*8 + c0*2 + j;
        float v = 0.f;
        if (r < 98 && t < 14) {
            if (m >= 98) v = -30000.f;
            else {
                int pd_r = r/49; int rr = r - pd_r*49; int ph_r = rr/7, pw_r = rr - ph_r*7;
                int pd_m = m/49; int mm = m - pd_m*49; int ph_m = mm/7, pw_m = mm - ph_m*7;
                int rpi = ((pd_r - pd_m + 1)*13 + (ph_r - ph_m + 6))*13 + (pw_r - pw_m + 6);
                v = bt[rpi*4 + head];
            }
        }
        bm[i] = __float2half_rn(v);
    } else {                               // LN1 (NCDHW -> token-major half)
        int j = bx - 2816;
        int wt = j & 1; int tmp = j >> 1;
        int h = tmp % 56; tmp /= 56;
        int d = tmp & 7; int bb = tmp >> 3;
        int w0 = wt * 28;
        size_t sp0 = ((size_t)d*56 + h)*56 + w0;
        const float* ib = in + (size_t)bb*256*SP + sp0;
        for (int i = tid; i < 28*256; i += 256) {
            int c = i / 28, ww_ = i - c*28;
            s[ww_][c] = ib[(size_t)c*SP + ww_];
        }
        __syncthreads();
        int warp = tid >> 5, lane = tid & 31;
        for (int tk = warp; tk < 28; tk += 8) {
            float s1 = 0.f, s2 = 0.f;
            #pragma unroll
            for (int q = 0; q < 8; q++) { float v = s[tk][lane + (q<<5)]; s1 += v; s2 += v*v; }
            #pragma unroll
            for (int o = 16; o; o >>= 1) {
                s1 += __shfl_xor_sync(0xffffffffu, s1, o);
                s2 += __shfl_xor_sync(0xffffffffu, s2, o);
            }
            float m = s1 * (1.f/256.f);
            float var = s2 * (1.f/256.f) - m*m;
            float iv = rsqrtf(var + 1e-5f);
            size_t t = (size_t)bb*SP + sp0 + tk;
            __half* orow = xh + t*256;
            #pragma unroll
            for (int q = 0; q < 8; q++) {
                int c = lane + (q<<5);
                orow[c] = __float2half_rn((s[tk][c] - m) * iv * n1w[c] + n1b[c]);
            }
        }
    }
}

// ---------------- LN2: half in, half out, vectorized ----------------
__global__ __launch_bounds__(256) void ln_row_kernel(
    const __half* __restrict__ in, const float* __restrict__ w,
    const float* __restrict__ b, __half* __restrict__ out)
{
    int t = blockIdx.x*8 + (threadIdx.x >> 5);
    int lane = threadIdx.x & 31;
    const __half* row = in + (size_t)t*256 + lane*8;
    uint4 u = *(const uint4*)row;
    const __half2* hp = (const __half2*)&u;
    float v[8];
    float s1 = 0.f, s2 = 0.f;
    #pragma unroll
    for (int j = 0; j < 4; j++) {
        float2 f = __half22float2(hp[j]);
        v[2*j] = f.x; v[2*j+1] = f.y;
        s1 += f.x + f.y; s2 += f.x*f.x + f.y*f.y;
    }
    #pragma unroll
    for (int o = 16; o; o >>= 1) {
        s1 += __shfl_xor_sync(0xffffffffu, s1, o);
        s2 += __shfl_xor_sync(0xffffffffu, s2, o);
    }
    float m = s1 * (1.f/256.f);
    float var = s2 * (1.f/256.f) - m*m;
    float iv = rsqrtf(var + 1e-5f);
    int c0 = lane*8;
    float4 w0 = *(const float4*)(w + c0);
    float4 w1 = *(const float4*)(w + c0 + 4);
    float4 b0 = *(const float4*)(b + c0);
    float4 b1 = *(const float4*)(b + c0 + 4);
    __half2 h0 = __floats2half2_rn((v[0]-m)*iv*w0.x + b0.x, (v[1]-m)*iv*w0.y + b0.y);
    __half2 h1 = __floats2half2_rn((v[2]-m)*iv*w0.z + b0.z, (v[3]-m)*iv*w0.w + b0.w);
    __half2 h2 = __floats2half2_rn((v[4]-m)*iv*w1.x + b1.x, (v[5]-m)*iv*w1.y + b1.y);
    __half2 h3 = __floats2half2_rn((v[6]-m)*iv*w1.z + b1.z, (v[7]-m)*iv*w1.w + b1.w);
    uint4 o;
    o.x = *(uint32_t*)&h0; o.y = *(uint32_t*)&h1;
    o.z = *(uint32_t*)&h2; o.w = *(uint32_t*)&h3;
    *(uint4*)(out + (size_t)t*256 + c0) = o;
}

// ---------------- shared warp-MMA stage: 128x128 tile, BK=64 ----------------
struct FragCtx {
    uint32_t aoff;
    uint32_t boff;
    uint32_t axor[4];
    uint32_t bxor[4];
};
__device__ __forceinline__ FragCtx make_frag_ctx(int lane, int wm, int wn) {
    FragCtx f;
    int l7 = lane & 7;
    f.aoff = (uint32_t)((wm*32 + ((lane>>3)&1)*8 + l7) * 128);
    f.boff = (uint32_t)((wn*64 + ((lane>>4)&1)*8 + l7) * 128);
    #pragma unroll
    for (int kk = 0; kk < 4; kk++) {
        f.axor[kk] = (uint32_t)(((2*kk + (lane>>4)) ^ l7) << 4);
        f.bxor[kk] = (uint32_t)(((2*kk + ((lane>>3)&1)) ^ l7) << 4);
    }
    return f;
}
__device__ __forceinline__ void mma_stage(uint32_t Ab, uint32_t Bb,
                                          const FragCtx& f, float c[2][8][4])
{
    #pragma unroll
    for (int kk = 0; kk < 4; kk++) {
        uint32_t a0[4], a1[4];
        ldsm4(a0, Ab + f.aoff + f.axor[kk]);
        ldsm4(a1, Ab + f.aoff + 2048u + f.axor[kk]);
        #pragma unroll
        for (int g = 0; g < 4; g++) {
            uint32_t bb[4];
            ldsm4(bb, Bb + f.boff + (uint32_t)g*2048u + f.bxor[kk]);
            MMA_F16(c[0][2*g],   a0, bb[0], bb[1]);
            MMA_F16(c[1][2*g],   a1, bb[0], bb[1]);
            MMA_F16(c[0][2*g+1], a0, bb[2], bb[3]);
            MMA_F16(c[1][2*g+1], a1, bb[2], bb[3]);
        }
    }
}

// ---------------- shared mainloop body for 128x128 @ K=256 GEMM ----------------
__device__ __forceinline__ void hgemm_mainloop(
    const __half* asrc, const __half* bsrc, uint32_t sb, uint32_t dst,
    int q0, int mrow, const FragCtx& f, float c[2][8][4])
{
    auto load_st = [&](int s) {
        uint32_t base = (uint32_t)(s % 3) * 32768u;
        #pragma unroll
        for (int q = q0; q < q0 + 4; q++) {
            uint32_t sw = (uint32_t)((q ^ (mrow & 7)) << 4);
            cp16(dst + base + sw, asrc + s*64 + q*8);
            cp16(dst + base + 16384u + sw, bsrc + s*64 + q*8);
        }
    };
    load_st(0); CP_COMMIT();
    load_st(1); CP_COMMIT();
    #pragma unroll
    for (int k = 0; k < 4; k++) {
        CP_WAIT1();
        __syncthreads();
        if (k + 2 < 4) load_st(k + 2);
        CP_COMMIT();
        uint32_t Ab = sb + (uint32_t)(k % 3)*32768u;
        mma_stage(Ab, Ab + 16384u, f, c);
    }
    __syncthreads();
}

// ---------------- fp16 GEMM (plain): C half (+bias) ----------------
__global__ __launch_bounds__(256, 2) void hgemm_kernel(
    const __half* __restrict__ A, const __half* __restrict__ B,
    const float* __restrict__ bias, __half* __restrict__ Cout, int N)
{
    extern __shared__ __align__(16) char dsm[];
    __shared__ float sbias[128];
    const int tid = threadIdx.x, lane = tid & 31, wid = tid >> 5;
    const int wm = wid & 3, wn = wid >> 2;
    const int bx = blockIdx.x, by = blockIdx.y;

    if (tid < 128) sbias[tid] = bias ? bias[bx*128 + tid] : 0.f;

    const int mrow = tid >> 1;
    const int q0 = (tid & 1) * 4;
    const uint32_t sb = smem_u32(dsm);
    FragCtx f = make_frag_ctx(lane, wm, wn);
    float c[2][8][4];
    #pragma unroll
    for (int t = 0; t < 2; t++)
        #pragma unroll
        for (int j = 0; j < 8; j++)
            #pragma unroll
            for (int q = 0; q < 4; q++) c[t][j][q] = 0.f;

    hgemm_mainloop(A + ((size_t)(by*128 + mrow))*256,
                   B + ((size_t)(bx*128 + mrow))*256,
                   sb, sb + (uint32_t)mrow*128u, q0, mrow, f, c);

    float* Cb = (float*)dsm;   // 128 x 132
    const int r0 = lane >> 2, c0 = lane & 3;
    #pragma unroll
    for (int t = 0; t < 2; t++) {
        int row = wm*32 + t*16 + r0;
        #pragma unroll
        for (int t2 = 0; t2 < 8; t2++) {
            int col = wn*64 + t2*8 + (c0 << 1);
            Cb[row*132 + col]       = c[t][t2][0] + sbias[col];
            Cb[row*132 + col + 1]   = c[t][t2][1] + sbias[col+1];
            Cb[(row+8)*132 + col]   = c[t][t2][2] + sbias[col];
            Cb[(row+8)*132 + col+1] = c[t][t2][3] + sbias[col+1];
        }
    }
    __syncthreads();

    const int m = tid >> 1, ch = (tid & 1) << 6;
    size_t goff = ((size_t)(by*128 + m))*N + bx*128 + ch;
    #pragma unroll
    for (int j8 = 0; j8 < 8; j8++) {
        const float* p = &Cb[m*132 + ch + j8*8];
        __half2 h0 = __floats2half2_rn(p[0], p[1]);
        __half2 h1 = __floats2half2_rn(p[2], p[3]);
        __half2 h2 = __floats2half2_rn(p[4], p[5]);
        __half2 h3 = __floats2half2_rn(p[6], p[7]);
        uint4 u;
        u.x = *(uint32_t*)&h0; u.y = *(uint32_t*)&h1;
        u.z = *(uint32_t*)&h2; u.w = *(uint32_t*)&h3;
        *(uint4*)(Cout + goff + j8*8) = u;
    }
}

// ---------------- fused grid-proj: y = A@B^T + bias + xw; s = half(input + y); Xa ----
__global__ __launch_bounds__(256, 2) void hgemm_fuse_kernel(
    const __half* __restrict__ A, const __half* __restrict__ B,
    const float* __restrict__ bias, const __half* __restrict__ xw,
    const float* __restrict__ input, __half* __restrict__ s,
    __half* __restrict__ Xa)
{
    extern __shared__ __align__(16) char dsm[];
    __shared__ float sbias[128];
    const int tid = threadIdx.x, lane = tid & 31, wid = tid >> 5;
    const int wm = wid & 3, wn = wid >> 2;
    const int bx = blockIdx.x, by = blockIdx.y;

    if (tid < 128) sbias[tid] = bias[bx*128 + tid];

    const int mrow = tid >> 1;
    const int q0 = (tid & 1) * 4;
    const uint32_t sb = smem_u32(dsm);
    FragCtx f = make_frag_ctx(lane, wm, wn);
    float c[2][8][4];
    #pragma unroll
    for (int t = 0; t < 2; t++)
        #pragma unroll
        for (int j = 0; j < 8; j++)
            #pragma unroll
            for (int q = 0; q < 4; q++) c[t][j][q] = 0.f;

    hgemm_mainloop(A + ((size_t)(by*128 + mrow))*256,
                   B + ((size_t)(bx*128 + mrow))*256,
                   sb, sb + (uint32_t)mrow*128u, q0, mrow, f, c);

    float* Cb = (float*)dsm;   // 128 x 132, rows = tokens, cols = local chan
    const int r0 = lane >> 2, c0 = lane & 3;
    #pragma unroll
    for (int t = 0; t < 2; t++) {
        int row = wm*32 + t*16 + r0;
        #pragma unroll
        for (int t2 = 0; t2 < 8; t2++) {
            int col = wn*64 + t2*8 + (c0 << 1);
            Cb[row*132 + col]       = c[t][t2][0] + sbias[col];
            Cb[row*132 + col + 1]   = c[t][t2][1] + sbias[col+1];
            Cb[(row+8)*132 + col]   = c[t][t2][2] + sbias[col];
            Cb[(row+8)*132 + col+1] = c[t][t2][3] + sbias[col+1];
        }
    }
    __syncthreads();

    // phase A (token-major): y = Cb + xw  (xw fp16)
    const int m = tid >> 1, ch = (tid & 1) << 6;
    {
        size_t goff = ((size_t)(by*128 + m))*256 + bx*128 + ch;
        #pragma unroll
        for (int j8 = 0; j8 < 8; j8++) {
            uint4 u = *(const uint4*)(xw + goff + j8*8);
            const __half2* hp = (const __half2*)&u;
            float* p = &Cb[m*132 + ch + j8*8];
            #pragma unroll
            for (int q = 0; q < 4; q++) {
                float2 fv = __half22float2(hp[q]);
                p[2*q]   += fv.x;
                p[2*q+1] += fv.y;
            }
        }
    }
    __syncthreads();

    // phase B (chan-major, coalesced NCDHW): s = half(input + y); Cb <- s (fp32)
    {
        const int co = tid >> 1, mh = (tid & 1) << 6;
        const int tok0 = by*128;
        const int b = tok0 / SP, sp0 = tok0 % SP;
        size_t gbase = (size_t)b*256*SP + (size_t)(bx*128 + co)*SP + sp0 + mh;
        #pragma unroll
        for (int j8 = 0; j8 < 8; j8++) {
            float4 iv0 = *(const float4*)(input + gbase + j8*8);
            float4 iv1 = *(const float4*)(input + gbase + j8*8 + 4);
            float v[8];
            const float ivs[8] = {iv0.x, iv0.y, iv0.z, iv0.w, iv1.x, iv1.y, iv1.z, iv1.w};
            #pragma unroll
            for (int q = 0; q < 8; q++) {
                float* p = &Cb[(mh + j8*8 + q)*132 + co];
                v[q] = ivs[q] + *p;
                *p = v[q];
            }
            __half2 h0 = __floats2half2_rn(v[0], v[1]);
            __half2 h1 = __floats2half2_rn(v[2], v[3]);
            __half2 h2 = __floats2half2_rn(v[4], v[5]);
            __half2 h3 = __floats2half2_rn(v[6], v[7]);
            uint4 u;
            u.x = *(uint32_t*)&h0; u.y = *(uint32_t*)&h1;
            u.z = *(uint32_t*)&h2; u.w = *(uint32_t*)&h3;
            *(uint4*)(s + gbase + j8*8) = u;
        }
    }
    __syncthreads();

    // phase C (token-major): Xa = half(s2) for channels 128..255 (bx==1)
    if (bx == 1) {
        const int tok = by*128 + m;
        const int b = tok / SP;
        int sp = tok % SP;
        int d = sp / 3136; int r = sp - d*3136; int h = r / 56, w = r - h*56;
        size_t po = (size_t)(d+1)*PDH + (size_t)(h+1)*58 + (w+1);
        __half* xp = Xa + ((size_t)b*PAD_SP + po)*128 + ch;
        #pragma unroll
        for (int j8 = 0; j8 < 8; j8++) {
            const float* p = &Cb[m*132 + ch + j8*8];
            __half2 h0 = __floats2half2_rn(p[0], p[1]);
            __half2 h1 = __floats2half2_rn(p[2], p[3]);
            __half2 h2 = __floats2half2_rn(p[4], p[5]);
            __half2 h3 = __floats2half2_rn(p[6], p[7]);
            uint4 u;
            u.x = *(uint32_t*)&h0; u.y = *(uint32_t*)&h1;
            u.z = *(uint32_t*)&h2; u.w = *(uint32_t*)&h3;
            *(uint4*)(xp + j8*8) = u;
        }
    }
}

// ---------------- tensor-core attention (frag-major fp16 bias, coalesced) ------------
__global__ __launch_bounds__(256, 3) void attn_mma_kernel(
    const __half* __restrict__ qkv, const __half* __restrict__ bmat,
    __half* __restrict__ out, int grid_mode)
{
    __shared__ __align__(16) __half Qs[112*64];
    __shared__ __align__(16) __half Ks[112*64];
    __shared__ __align__(16) __half Vs[112*64];
    __shared__ int ts[NTOK];

    const int tid = threadIdx.x, lane = tid & 31, warp = tid >> 5;
    const int wi = blockIdx.x, head = blockIdx.y;
    const int b = wi >> 8, wd = (wi>>6)&3, wh = (wi>>3)&7, ww = wi & 7;
    const int hoff = head << 6;

    if (tid < NTOK) {
        int pd = tid / 49; int r7 = tid - pd*49; int ph = r7 / 7, pw = r7 - ph*7;
        int d, h, w;
        if (grid_mode) { d = pd*4 + wd; h = ph*8 + wh; w = pw*8 + ww; }
        else           { d = wd*2 + pd; h = wh*7 + ph; w = ww*7 + pw; }
        ts[tid] = ((b*8 + d)*56 + h)*56 + w;
    }
    __syncthreads();

    {
        const int row = tid >> 1;
        const int cb = (tid & 1) * 4;
        const uint4 z4 = make_uint4(0,0,0,0);
        if (row < 112) {
            size_t base = (row < 98) ? ((size_t)ts[row]*768 + hoff) : 0;
            #pragma unroll
            for (int cc = 0; cc < 4; cc++) {
                int c = cb + cc;
                int sw8 = (c ^ (row & 7)) * 8;
                uint4 vq = z4, vk = z4, vv = z4;
                if (row < 98) {
                    vq = *(const uint4*)(qkv + base + c*8);
                    vk = *(const uint4*)(qkv + base + 256 + c*8);
                    vv = *(const uint4*)(qkv + base + 512 + c*8);
                }
                *(uint4*)(Qs + row*64 + sw8) = vq;
                *(uint4*)(Ks + row*64 + sw8) = vk;
                *(uint4*)(Vs + row*64 + sw8) = vv;
            }
        }
    }
    __syncthreads();

    if (warp < 7) {
        const uint32_t qb = smem_u32(Qs), kb = smem_u32(Ks), vb = smem_u32(Vs);
        const int l7 = lane & 7;

        float c[14][4];
        #pragma unroll
        for (int t = 0; t < 14; t++)
            #pragma unroll
            for (int q = 0; q < 4; q++) c[t][q] = 0.f;

        const uint32_t a_base = qb + (uint32_t)((warp*16 + ((lane>>3)&1)*8 + l7) * 128);
        const uint32_t b_rowo = (uint32_t)((((lane>>4)&1)*8 + l7) * 128);
        #pragma unroll
        for (int kk = 0; kk < 4; kk++) {
            uint32_t a[4];
            ldsm4(a, a_base + (uint32_t)(((2*kk + (lane>>4)) ^ l7) << 4));
            uint32_t bx_ = (uint32_t)(((2*kk + ((lane>>3)&1)) ^ l7) << 4);
            #pragma unroll
            for (int g = 0; g < 7; g++) {
                uint32_t bb[4];
                ldsm4(bb, kb + (uint32_t)(g*2048) + b_rowo + bx_);
                MMA_F16(c[2*g],   a, bb[0], bb[1]);
                MMA_F16(c[2*g+1], a, bb[2], bb[3]);
            }
        }

        const int r_lo = warp*16 + (lane >> 2);
        const int r_hi = r_lo + 8;
        const int mcol = (lane & 3) * 2;
        const __half2* bm_lo = (const __half2*)(bmat
            + ((((size_t)head*128 + r_lo)*4 + (lane & 3))*16)*2);
        const __half2* bm_hi = bm_lo + 8*4*16;
        float mx_lo = -1e30f, mx_hi = -1e30f;
        #pragma unroll
        for (int tc = 0; tc < 4; tc++) {
            uint4 ulo = *(const uint4*)(bm_lo + tc*4);
            uint4 uhi = *(const uint4*)(bm_hi + tc*4);
            const __half2* plo = (const __half2*)&ulo;
            const __half2* phi = (const __half2*)&uhi;
            const int tmax = (tc == 3) ? 2 : 4;
            #pragma unroll
            for (int tt = 0; tt < tmax; tt++) {
                int t = tc*4 + tt;
                float2 blo = __half22float2(plo[tt]);
                float2 bhi = __half22float2(phi[tt]);
                c[t][0] = fmaf(c[t][0], SCALE_Q, blo.x);
                c[t][1] = fmaf(c[t][1], SCALE_Q, blo.y);
                c[t][2] = fmaf(c[t][2], SCALE_Q, bhi.x);
                c[t][3] = fmaf(c[t][3], SCALE_Q, bhi.y);
                mx_lo = fmaxf(mx_lo, fmaxf(c[t][0], c[t][1]));
                mx_hi = fmaxf(mx_hi, fmaxf(c[t][2], c[t][3]));
            }
        }
        #pragma unroll
        for (int o = 1; o <= 2; o <<= 1) {
            mx_lo = fmaxf(mx_lo, __shfl_xor_sync(0xffffffffu, mx_lo, o));
            mx_hi = fmaxf(mx_hi, __shfl_xor_sync(0xffffffffu, mx_hi, o));
        }
        float sum_lo = 0.f, sum_hi = 0.f;
        #pragma unroll
        for (int t = 0; t < 14; t++) {
            c[t][0] = __expf(c[t][0] - mx_lo); sum_lo += c[t][0];
            c[t][1] = __expf(c[t][1] - mx_lo); sum_lo += c[t][1];
            c[t][2] = __expf(c[t][2] - mx_hi); sum_hi += c[t][2];
            c[t][3] = __expf(c[t][3] - mx_hi); sum_hi += c[t][3];
        }
        #pragma unroll
        for (int o = 1; o <= 2; o <<= 1) {
            sum_lo += __shfl_xor_sync(0xffffffffu, sum_lo, o);
            sum_hi += __shfl_xor_sync(0xffffffffu, sum_hi, o);
        }
        const float inv_lo = 1.f / sum_lo, inv_hi = 1.f / sum_hi;

        uint32_t ap[7][4];
        #pragma unroll
        for (int j = 0; j < 7; j++) {
            __half2 h;
            h = __floats2half2_rn(c[2*j][0]*inv_lo,   c[2*j][1]*inv_lo);   ap[j][0] = *(uint32_t*)&h;
            h = __floats2half2_rn(c[2*j][2]*inv_hi,   c[2*j][3]*inv_hi);   ap[j][1] = *(uint32_t*)&h;
            h = __floats2half2_rn(c[2*j+1][0]*inv_lo, c[2*j+1][1]*inv_lo); ap[j][2] = *(uint32_t*)&h;
            h = __floats2half2_rn(c[2*j+1][2]*inv_hi, c[2*j+1][3]*inv_hi); ap[j][3] = *(uint32_t*)&h;
        }

        float c2[8][4];
        #pragma unroll
        for (int t = 0; t < 8; t++)
            #pragma unroll
            for (int q = 0; q < 4; q++) c2[t][q] = 0.f;

        #pragma unroll
        for (int j = 0; j < 7; j++) {
            int vrow = j*16 + l7 + 8*((lane>>3)&1);
            uint32_t vbase = vb + (uint32_t)(vrow * 128);
            #pragma unroll
            for (int g = 0; g < 4; g++) {
                uint32_t bb[4];
                ldsm4t(bb, vbase + (uint32_t)((((2*g) + (lane>>4)) ^ (vrow & 7)) << 4));
                MMA_F16(c2[2*g],   ap[j], bb[0], bb[1]);
                MMA_F16(c2[2*g+1], ap[j], bb[2], bb[3]);
            }
        }

        if (r_lo < 98) {
            __half* op = out + (size_t)ts[r_lo]*256 + hoff;
            #pragma unroll
            for (int t2 = 0; t2 < 8; t2++) {
                __half2 h = __floats2half2_rn(c2[t2][0], c2[t2][1]);
                *(__half2*)(op + t2*8 + mcol) = h;
            }
        }
        if (r_hi < 98) {
            __half* op = out + (size_t)ts[r_hi]*256 + hoff;
            #pragma unroll
            for (int t2 = 0; t2 < 8; t2++) {
                __half2 h = __floats2half2_rn(c2[t2][2], c2[t2][3]);
                *(__half2*)(op + t2*8 + mcol) = h;
            }
        }
    }
}

// ---------------- fp16 implicit-GEMM conv (R11-proven: M=128, 3-stage ring) ----------
__global__ __launch_bounds__(256, 2) void conv_mma_kernel(
    const __half* __restrict__ Xin, const __half* __restrict__ w2,
    const float* __restrict__ bias, const __half* __restrict__ res,
    float* __restrict__ outN, __half* __restrict__ outX, int leaky)
{
    extern __shared__ __align__(16) char dsm[];
    __shared__ float sbias[128];

    const int tid = threadIdx.x, lane = tid & 31, wid = tid >> 5;
    const int wm = wid & 3, wn = wid >> 2;
    const int bx = blockIdx.x;
    const int b = bx / 196;
    const int spb = (bx % 196) * 128;

    if (tid < 128) sbias[tid] = bias[tid];

    const int mrow = tid >> 1;
    const int q0 = (tid & 1) * 4;
    int sp_c = spb + mrow;
    int d_c = sp_c / 3136; int r_c = sp_c - d_c*3136; int h_c = r_c / 56, w_c = r_c - h_c*56;
    const int padrow = d_c*PDH + h_c*58 + w_c;
    const __half* XinB = Xin + (size_t)b * PAD_SP * 128;
    const uint32_t sb = smem_u32(dsm);
    const uint32_t dst = sb + (uint32_t)mrow*128u;
    FragCtx f = make_frag_ctx(lane, wm, wn);

    float c[2][8][4];
    #pragma unroll
    for (int t = 0; t < 2; t++)
        #pragma unroll
        for (int j = 0; j < 8; j++)
            #pragma unroll
            for (int q = 0; q < 4; q++) c[t][j][q] = 0.f;

    const int NST = 54;
    auto load_st = [&](int s) {
        int tap = s >> 1, kh64 = (s & 1) * 64;
        int kd = tap / 9; int rem = tap - kd*9; int kh = rem / 3, kw = rem - kh*3;
        int toff = kd*PDH + kh*58 + kw;
        uint32_t base = (uint32_t)(s % 3) * 32768u;
        const __half* ga = XinB + (size_t)(padrow + toff)*128 + kh64;
        const __half* gb = w2 + ((size_t)tap*128 + mrow)*128 + kh64;
        #pragma unroll
        for (int q = q0; q < q0 + 4; q++) {
            uint32_t sw = (uint32_t)((q ^ (mrow & 7)) << 4);
            cp16(dst + base + sw, ga + q*8);
            cp16(dst + base + 16384u + sw, gb + q*8);
        }
    };
    load_st(0); CP_COMMIT();
    load_st(1); CP_COMMIT();
    for (int k = 0; k < NST; k++) {
        CP_WAIT1();
        __syncthreads();
        if (k + 2 < NST) load_st(k + 2);
        CP_COMMIT();
        uint32_t Ab = sb + (uint32_t)(k % 3)*32768u;
        mma_stage(Ab, Ab + 16384u, f, c);
    }
    __syncthreads();

    float* Cb = (float*)dsm;   // 128 x 132
    const int r0 = lane >> 2, c0 = lane & 3;
    #pragma unroll
    for (int t = 0; t < 2; t++) {
        int row = wm*32 + t*16 + r0;
        #pragma unroll
        for (int t2 = 0; t2 < 8; t2++) {
            int col = wn*64 + t2*8 + (c0 << 1);
            float b0s = sbias[col], b1s = sbias[col+1];
            float v0 = c[t][t2][0] + b0s;
            float v1 = c[t][t2][1] + b1s;
            float v2 = c[t][t2][2] + b0s;
            float v3 = c[t][t2][3] + b1s;
            if (leaky) {
                v0 = (v0 >= 0.f) ? v0 : 0.01f*v0;
                v1 = (v1 >= 0.f) ? v1 : 0.01f*v1;
                v2 = (v2 >= 0.f) ? v2 : 0.01f*v2;
                v3 = (v3 >= 0.f) ? v3 : 0.01f*v3;
            }
            Cb[row*132 + col]       = v0;
            Cb[row*132 + col + 1]   = v1;
            Cb[(row+8)*132 + col]   = v2;
            Cb[(row+8)*132 + col+1] = v3;
        }
    }
    __syncthreads();

    if (res) {
        int co = tid >> 1, mh = (tid & 1) << 6;
        const __half* rp = res + (size_t)b*256*SP + (size_t)co*SP + spb + mh;
        #pragma unroll
        for (int j8 = 0; j8 < 8; j8++) {
            uint4 u = *(const uint4*)(rp + j8*8);
            const __half2* hp = (const __half2*)&u;
            #pragma unroll
            for (int q = 0; q < 4; q++) {
                float2 fv = __half22float2(hp[q]);
                Cb[(mh + j8*8 + 2*q + 0)*132 + co] += fv.x;
                Cb[(mh + j8*8 + 2*q + 1)*132 + co] += fv.y;
            }
        }
        __syncthreads();
    }

    if (outX) {
        int m = tid >> 1, ch = (tid & 1) << 6;
        int sp = spb + m; int d = sp / 3136; int r = sp - d*3136; int h = r / 56, w = r - h*56;
        size_t po = (size_t)(d+1)*PDH + (size_t)(h+1)*58 + (w+1);
        __half* xp = outX + ((size_t)b*PAD_SP + po)*128 + ch;
        #pragma unroll
        for (int j8 = 0; j8 < 8; j8++) {
            const float* p = &Cb[m*132 + ch + j8*8];
            __half2 h0 = __floats2half2_rn(p[0], p[1]);
            __half2 h1 = __floats2half2_rn(p[2], p[3]);
            __half2 h2 = __floats2half2_rn(p[4], p[5]);
            __half2 h3 = __floats2half2_rn(p[6], p[7]);
            uint4 u;
            u.x = *(uint32_t*)&h0; u.y = *(uint32_t*)&h1;
            u.z = *(uint32_t*)&h2; u.w = *(uint32_t*)&h3;
            *(uint4*)(xp + j8*8) = u;
        }
    }
    if (outN) {
        int co = tid >> 1, mh = (tid & 1) << 6;
        float* op = outN + (size_t)b*256*SP + (size_t)co*SP + spb + mh;
        #pragma unroll
        for (int j4 = 0; j4 < 16; j4++) {
            float4 o;
            o.x = Cb[(mh + j4*4 + 0)*132 + co];
            o.y = Cb[(mh + j4*4 + 1)*132 + co];
            o.z = Cb[(mh + j4*4 + 2)*132 + co];
            o.w = Cb[(mh + j4*4 + 3)*132 + co];
            *(float4*)(op + j4*4) = o;
        }
    }
}

// ---------------- launcher ----------------
extern "C" void kernel_launch(void* const* d_in, const int* in_sizes, int n_in,
                              void* d_out, int out_size)
{
    (void)in_sizes; (void)n_in; (void)out_size;
    const float* input  = (const float*)d_in[0];
    const float* n1w    = (const float*)d_in[1];
    const float* n1b    = (const float*)d_in[2];
    const float* n2w    = (const float*)d_in[3];
    const float* n2b    = (const float*)d_in[4];
    const float* wqkv   = (const float*)d_in[5];
    const float* wprojw = (const float*)d_in[6];
    const float* wprojb = (const float*)d_in[7];
    const float* wbias  = (const float*)d_in[8];
    const float* gqkv   = (const float*)d_in[9];
    const float* gprojw = (const float*)d_in[10];
    const float* gprojb = (const float*)d_in[11];
    const float* gbias  = (const float*)d_in[12];
    const float* f1c1w  = (const float*)d_in[13];
    const float* f1c1b  = (const float*)d_in[14];
    const float* f1c2w  = (const float*)d_in[15];
    const float* f1c2b  = (const float*)d_in[16];
    const float* g1c1w  = (const float*)d_in[17];
    const float* g1c1b  = (const float*)d_in[18];
    const float* g1c2w  = (const float*)d_in[19];
    const float* g1c2b  = (const float*)d_in[20];
    float* out = (float*)d_out;

    __half *xh, *qkvh, *atnh, *xwh, *sh, *Xa, *Xb, *w2h, *wqkvh, *gqkvh, *wprjh, *gprjh, *bmat;
    cudaGetSymbolAddress((void**)&xh,    g_xh);
    cudaGetSymbolAddress((void**)&qkvh,  g_qkvh);
    cudaGetSymbolAddress((void**)&atnh,  g_atnh);
    cudaGetSymbolAddress((void**)&xwh,   g_xwh);
    cudaGetSymbolAddress((void**)&sh,    g_s);
    cudaGetSymbolAddress((void**)&Xa,    g_Xa);
    cudaGetSymbolAddress((void**)&Xb,    g_Xb);
    cudaGetSymbolAddress((void**)&w2h,   g_w2h);
    cudaGetSymbolAddress((void**)&wqkvh, g_wqkvh);
    cudaGetSymbolAddress((void**)&gqkvh, g_gqkvh);
    cudaGetSymbolAddress((void**)&wprjh, g_wprjh);
    cudaGetSymbolAddress((void**)&gprjh, g_gprjh);
    cudaGetSymbolAddress((void**)&bmat,  g_bmat);

    const int TSMEM = 3 * 32768;
    cudaFuncSetAttribute(hgemm_kernel,      cudaFuncAttributeMaxDynamicSharedMemorySize, TSMEM);
    cudaFuncSetAttribute(hgemm_fuse_kernel, cudaFuncAttributeMaxDynamicSharedMemorySize, TSMEM);
    cudaFuncSetAttribute(conv_mma_kernel,   cudaFuncAttributeMaxDynamicSharedMemorySize, TSMEM);

    // prep (weights coalesced + frag-major bias) + LN1 in one launch
    prep_kernel<<<4608, 256>>>(wqkv, gqkv, wprojw, gprojw,
                               f1c1w, f1c2w, g1c1w, g1c2w, wbias, gbias,
                               wqkvh, gqkvh, wprjh, gprjh, w2h, bmat,
                               input, n1w, n1b, xh);

    // window attention block
    hgemm_kernel<<<dim3(6, 392), 256, TSMEM>>>(xh, wqkvh, nullptr, qkvh, 768);
    attn_mma_kernel<<<dim3(512, 4), 256>>>(qkvh, bmat, atnh, 0);
    hgemm_kernel<<<dim3(2, 392), 256, TSMEM>>>(atnh, wprjh, wprojb, xwh, 256);
    // grid attention block
    ln_row_kernel<<<6272, 256>>>(xwh, n2w, n2b, xh);
    hgemm_kernel<<<dim3(6, 392), 256, TSMEM>>>(xh, gqkvh, nullptr, qkvh, 768);
    attn_mma_kernel<<<dim3(512, 4), 256>>>(qkvh, bmat + BMSZ, atnh, 1);
    hgemm_fuse_kernel<<<dim3(2, 392), 256, TSMEM>>>(atnh, gprjh, gprojb, xwh, input, sh, Xa);

    // conv chain (R11-proven config)
    conv_mma_kernel<<<392, 256, TSMEM>>>(Xa, w2h,            f1c1b, nullptr, nullptr, Xb, 1);
    conv_mma_kernel<<<392, 256, TSMEM>>>(Xb, w2h + W2SZ,     f1c2b, sh, out, Xa, 0);
    conv_mma_kernel<<<392, 256, TSMEM>>>(Xa, w2h + 2*W2SZ,   g1c1b, nullptr, nullptr, Xb, 1);
    conv_mma_kernel<<<392, 256, TSMEM>>>(Xb, w2h + 3*W2SZ,   g1c2b, sh + (size_t)128*SP,
                                         out + (size_t)128*SP, nullptr, 0);
}